// round 10
// baseline (speedup 1.0000x reference)
#include <cuda_runtime.h>
#include <cuda_bf16.h>
#include <math.h>

// Problem constants
#define EG 1024      // embed dim
#define MG 2048      // B*S rows
#define SG 1024      // seq len
#define HG 16        // heads
#define DH 64        // head dim

// ---------------- scratch (device globals: no runtime allocation allowed) ----
__device__ float g_qa[MG * EG];
__device__ float g_qb[MG * EG];
__device__ float g_ka[MG * EG];
__device__ float g_kb[MG * EG];
__device__ float g_va[MG * EG];
__device__ float g_vb[MG * EG];

// pre-split bf16 hi/lo buffers
// weights: 0 q_wa, 1 q_wb, 2 q_ws, 3 k_wa, 4 k_wb, 5 k_ws,
//          6 v_wa, 7 v_wb, 8 v_ws, 9 o_wa, 10 o_wb, 11 o_ws   (ws = wa+wb)
__device__ __nv_bfloat16 g_wH[12][EG * EG];
__device__ __nv_bfloat16 g_wL[12][EG * EG];
// activations: 0 xq_a, 1 xq_b, 2 xq_s, 3 xkv_a, 4 xkv_b, 5 xkv_s,
//              6 oa, 7 ob, 8 os                               (s = a+b)
__device__ __nv_bfloat16 g_xH[9][MG * EG];
__device__ __nv_bfloat16 g_xL[9][MG * EG];

// ---------------------------------------------------------------------------
// helpers
// ---------------------------------------------------------------------------
__device__ __forceinline__ void mma_bf16(float* c, const unsigned* a, const unsigned* b)
{
    asm volatile(
        "mma.sync.aligned.m16n8k16.row.col.f32.bf16.bf16.f32 "
        "{%0,%1,%2,%3}, {%4,%5,%6,%7}, {%8,%9}, {%0,%1,%2,%3};"
        : "+f"(c[0]), "+f"(c[1]), "+f"(c[2]), "+f"(c[3])
        : "r"(a[0]), "r"(a[1]), "r"(a[2]), "r"(a[3]),
          "r"(b[0]), "r"(b[1]));
}

__device__ __forceinline__ void ldsm_x4(unsigned* r, const __nv_bfloat16* p)
{
    unsigned addr = (unsigned)__cvta_generic_to_shared(p);
    asm volatile("ldmatrix.sync.aligned.m8n8.x4.shared.b16 {%0,%1,%2,%3}, [%4];"
                 : "=r"(r[0]), "=r"(r[1]), "=r"(r[2]), "=r"(r[3]) : "r"(addr));
}

__device__ __forceinline__ unsigned pack_hi2(float x, float y)
{
    __nv_bfloat162 h(__float2bfloat16(x), __float2bfloat16(y));
    return *reinterpret_cast<unsigned*>(&h);
}
__device__ __forceinline__ unsigned pack_lo2(float x, float y)
{
    float hx = __bfloat162float(__float2bfloat16(x));
    float hy = __bfloat162float(__float2bfloat16(y));
    __nv_bfloat162 l(__float2bfloat16(x - hx), __float2bfloat16(y - hy));
    return *reinterpret_cast<unsigned*>(&l);
}

__device__ __forceinline__ void cp_async16(unsigned daddr, const void* src)
{
    asm volatile("cp.async.cg.shared.global [%0], [%1], 16;" :: "r"(daddr), "l"(src));
}
__device__ __forceinline__ void cp_commit()
{
    asm volatile("cp.async.commit_group;");
}
template<int N>
__device__ __forceinline__ void cp_wait()
{
    asm volatile("cp.async.wait_group %0;" :: "n"(N));
}

// GEMM smem geometry: BK=16, stride 24 (48B rows: 16B aligned, LDSM conflict-free)
#define KSTRIDE 24
#define KTILE   (64 * KSTRIDE)     // 1536 elems
#define KSTAGE  (12 * KTILE)       // 18432 elems
#define NSTAGES 3

// split fp32 -> bf16 hi/lo, write pairs into smem tiles (used in attention)
__device__ __forceinline__ void split_store4(
    __nv_bfloat16* shi, __nv_bfloat16* slo, int idx, float4 v)
{
    __nv_bfloat16 hx = __float2bfloat16(v.x);
    __nv_bfloat16 hy = __float2bfloat16(v.y);
    __nv_bfloat16 hz = __float2bfloat16(v.z);
    __nv_bfloat16 hw = __float2bfloat16(v.w);
    __nv_bfloat16 lx = __float2bfloat16(v.x - __bfloat162float(hx));
    __nv_bfloat16 ly = __float2bfloat16(v.y - __bfloat162float(hy));
    __nv_bfloat16 lz = __float2bfloat16(v.z - __bfloat162float(hz));
    __nv_bfloat16 lw = __float2bfloat16(v.w - __bfloat162float(hw));
    *reinterpret_cast<__nv_bfloat162*>(&shi[idx])     = __nv_bfloat162(hx, hy);
    *reinterpret_cast<__nv_bfloat162*>(&shi[idx + 2]) = __nv_bfloat162(hz, hw);
    *reinterpret_cast<__nv_bfloat162*>(&slo[idx])     = __nv_bfloat162(lx, ly);
    *reinterpret_cast<__nv_bfloat162*>(&slo[idx + 2]) = __nv_bfloat162(lz, lw);
}

// ---------------------------------------------------------------------------
// Batched fp32 -> bf16 hi/lo split; optional second source (summed in fp32).
// ---------------------------------------------------------------------------
struct SplitBatch {
    const float* s1[12];
    const float* s2[12];
    __nv_bfloat16* hi[12];
    __nv_bfloat16* lo[12];
};

__global__ __launch_bounds__(256) void split_kernel(SplitBatch sb, int nvec)
{
    const int t = blockIdx.x * 256 + threadIdx.x;
    if (t >= nvec) return;
    const int w = blockIdx.y;
    float4 v = reinterpret_cast<const float4*>(sb.s1[w])[t];
    const float* p2 = sb.s2[w];
    if (p2) {
        float4 u = reinterpret_cast<const float4*>(p2)[t];
        v.x += u.x; v.y += u.y; v.z += u.z; v.w += u.w;
    }
    unsigned h0 = pack_hi2(v.x, v.y);
    unsigned h1 = pack_hi2(v.z, v.w);
    unsigned l0 = pack_lo2(v.x, v.y);
    unsigned l1 = pack_lo2(v.z, v.w);
    reinterpret_cast<uint2*>(sb.hi[w])[t] = make_uint2(h0, h1);
    reinterpret_cast<uint2*>(sb.lo[w])[t] = make_uint2(l0, l1);
}

// ---------------------------------------------------------------------------
// Karatsuba quaternion-complex dense on tensor cores.
//   P1 = Xa.Wa^T, P2 = Xb.Wb^T, P3 = (Xa+Xb).(Wa+Wb)^T  (each 3-term bf16 split)
//   outA = P1 + j2*P2 + ba ;  outB = P3 - P1 - P2 + bb
// 64x64 CTA tile, BK=16, 3-stage cp.async, ldmatrix frags, 8 warps (4x2).
// smem: 3 stages x 12 tiles [64][24] bf16 = 110592 B -> 2 CTAs/SM.
// Loader: threads 0..191, 16 threads per tile, 8 x 16B chunks each.
// ---------------------------------------------------------------------------
__global__ __launch_bounds__(256, 2) void qc_gemm_bf16_kernel(
    const __nv_bfloat16* __restrict__ xaH, const __nv_bfloat16* __restrict__ xaL,
    const __nv_bfloat16* __restrict__ xbH, const __nv_bfloat16* __restrict__ xbL,
    const __nv_bfloat16* __restrict__ xsH, const __nv_bfloat16* __restrict__ xsL,
    const __nv_bfloat16* __restrict__ waH, const __nv_bfloat16* __restrict__ waL,
    const __nv_bfloat16* __restrict__ wbH, const __nv_bfloat16* __restrict__ wbL,
    const __nv_bfloat16* __restrict__ wsH, const __nv_bfloat16* __restrict__ wsL,
    const float* __restrict__ ba, const float* __restrict__ bb,
    const float* __restrict__ theta_ptr,
    float* __restrict__ outA, float* __restrict__ outB)
{
    extern __shared__ __nv_bfloat16 sbuf[];

    const int tid = threadIdx.x;
    const int lane = tid & 31;
    const int wid = tid >> 5;
    const int warp_m = wid >> 1;
    const int warp_n = wid & 1;
    const int g = lane >> 2;
    const int t = lane & 3;

    const int m0 = blockIdx.y * 64;
    const int n0 = blockIdx.x * 64;

    const float j2 = sinf(2.0f * theta_ptr[0]) - 1.0f;

    // ldmatrix per-lane offsets
    const int aoff = (warp_m * 16 + (lane & 15)) * KSTRIDE + ((lane >> 4) << 3);
    const int boff = ((lane & 7) + ((lane & 16) >> 1)) * KSTRIDE + (((lane >> 3) & 1) << 3);

    // ---- loader setup: 12 tiles x 16 threads, 8 chunks of 16B each ----
    const bool loader = tid < 192;
    const __nv_bfloat16* gsrc = nullptr;
    unsigned sdst = 0;   // element offset within a stage
    if (loader) {
        const int tg = tid >> 4;                 // tile 0..11
        const __nv_bfloat16* srcs[12] =
            { xaH, xaL, xbH, xbL, xsH, xsL, waH, waL, wbH, wbL, wsH, wsL };
        const __nv_bfloat16* gp = srcs[tg];
        const int row0 = (tg < 6) ? m0 : n0;
        const int t16 = tid & 15;
        const int r0l = t16 >> 1;                // 0..7
        const int coll = (t16 & 1) << 3;         // 0 or 8
        gsrc = gp + (size_t)(row0 + r0l) * EG + coll;
        sdst = tg * KTILE + r0l * KSTRIDE + coll;
    }
    const unsigned sbase = (unsigned)__cvta_generic_to_shared(sbuf);

    auto fill = [&](int s, int k) {
        if (loader) {
            const unsigned d0 = sbase + 2u * (s * KSTAGE + sdst);
            const __nv_bfloat16* src = gsrc + k;
            #pragma unroll
            for (int j = 0; j < 8; j++)
                cp_async16(d0 + j * (8 * KSTRIDE * 2), src + (size_t)j * 8 * EG);
        }
        cp_commit();
    };

    float P1[4][4] = {};
    float P2[4][4] = {};
    float P3[4][4] = {};

    fill(0, 0);
    fill(1, 16);

    const int NIT = EG / 16;   // 64
    for (int it = 0; it < NIT; it++) {
        const int cur = it % 3;
        cp_wait<1>();
        __syncthreads();
        if (it + 2 < NIT) fill((it + 2) % 3, (it + 2) * 16);

        const __nv_bfloat16* cb = sbuf + cur * KSTAGE;

        unsigned aAH[4], aAL[4], aBH[4], aBL[4], aSH[4], aSL[4];
        ldsm_x4(aAH, cb + 0 * KTILE + aoff);
        ldsm_x4(aAL, cb + 1 * KTILE + aoff);
        ldsm_x4(aBH, cb + 2 * KTILE + aoff);
        ldsm_x4(aBL, cb + 3 * KTILE + aoff);
        ldsm_x4(aSH, cb + 4 * KTILE + aoff);
        ldsm_x4(aSL, cb + 5 * KTILE + aoff);

        #pragma unroll
        for (int fp = 0; fp < 2; fp++) {
            const int bo = (warp_n * 32 + fp * 16) * KSTRIDE + boff;
            unsigned bAH[4], bAL[4], bBH[4], bBL[4], bSH[4], bSL[4];
            ldsm_x4(bAH, cb + 6  * KTILE + bo);
            ldsm_x4(bAL, cb + 7  * KTILE + bo);
            ldsm_x4(bBH, cb + 8  * KTILE + bo);
            ldsm_x4(bBL, cb + 9  * KTILE + bo);
            ldsm_x4(bSH, cb + 10 * KTILE + bo);
            ldsm_x4(bSL, cb + 11 * KTILE + bo);

            #pragma unroll
            for (int half = 0; half < 2; half++) {
                const int f = fp * 2 + half;
                const int o = half * 2;
                mma_bf16(P1[f], aAH, bAH + o);
                mma_bf16(P1[f], aAH, bAL + o);
                mma_bf16(P1[f], aAL, bAH + o);
                mma_bf16(P2[f], aBH, bBH + o);
                mma_bf16(P2[f], aBH, bBL + o);
                mma_bf16(P2[f], aBL, bBH + o);
                mma_bf16(P3[f], aSH, bSH + o);
                mma_bf16(P3[f], aSH, bSL + o);
                mma_bf16(P3[f], aSL, bSH + o);
            }
        }
    }

    #pragma unroll
    for (int f = 0; f < 4; f++) {
        const int n = n0 + warp_n * 32 + f * 8 + 2 * t;
        const int r0 = m0 + warp_m * 16 + g;
        const int r1 = r0 + 8;
        const float ba0 = ba[n], ba1 = ba[n + 1];
        const float bb0 = bb[n], bb1 = bb[n + 1];

        float2 oa0 = { P1[f][0] + j2 * P2[f][0] + ba0,
                       P1[f][1] + j2 * P2[f][1] + ba1 };
        float2 oa1 = { P1[f][2] + j2 * P2[f][2] + ba0,
                       P1[f][3] + j2 * P2[f][3] + ba1 };
        float2 ob0 = { P3[f][0] - P1[f][0] - P2[f][0] + bb0,
                       P3[f][1] - P1[f][1] - P2[f][1] + bb1 };
        float2 ob1 = { P3[f][2] - P1[f][2] - P2[f][2] + bb0,
                       P3[f][3] - P1[f][3] - P2[f][3] + bb1 };

        *(float2*)&outA[r0 * EG + n] = oa0;
        *(float2*)&outA[r1 * EG + n] = oa1;
        *(float2*)&outB[r0 * EG + n] = ob0;
        *(float2*)&outB[r1 * EG + n] = ob1;
    }
}

// ---------------------------------------------------------------------------
// RoPE applied in place to g_qa, g_qb, g_ka, g_kb (fp32 throughout).
// ---------------------------------------------------------------------------
__global__ __launch_bounds__(256) void rope_kernel()
{
    const int PAIRS = MG * (EG / 2);
    int tt = blockIdx.x * blockDim.x + threadIdx.x;
    if (tt >= 4 * PAIRS) return;

    const int w = tt / PAIRS;
    const int p = tt % PAIRS;
    float* X = (w == 0) ? g_qa : (w == 1) ? g_qb : (w == 2) ? g_ka : g_kb;

    const int row = p >> 9;
    const int pp  = p & 511;
    const int h   = pp >> 5;
    const int i   = pp & 31;
    const int s   = row & (SG - 1);

    const float freq = exp2f(-(float)i * (13.287712379549449f / 32.0f));
    float sn, cs;
    sincosf((float)s * freq, &sn, &cs);

    const int base = row * EG + h * DH + i;
    const float x1 = X[base];
    const float x2 = X[base + 32];
    X[base]      = x1 * cs - x2 * sn;
    X[base + 32] = x2 * cs + x1 * sn;
}

// ---------------------------------------------------------------------------
// Tensor-core flash attention, complex-magnitude scores, bf16 hi/lo split,
// ldmatrix fragment loads; epilogue writes pre-split bf16 hi/lo for oa, ob
// AND their sum os (for the Karatsuba O projection).
// ---------------------------------------------------------------------------
#define KSTR 72
#define VSTR 40

__global__ __launch_bounds__(256) void attn_mma_kernel(const float* __restrict__ thetas_head)
{
    __shared__ __nv_bfloat16 sKaH[32 * KSTR], sKaL[32 * KSTR];
    __shared__ __nv_bfloat16 sKbH[32 * KSTR], sKbL[32 * KSTR];
    __shared__ __nv_bfloat16 sKjH[32 * KSTR], sKjL[32 * KSTR];
    __shared__ __nv_bfloat16 sVaH[64 * VSTR], sVaL[64 * VSTR];
    __shared__ __nv_bfloat16 sVbH[64 * VSTR], sVbL[64 * VSTR];

    const int b   = blockIdx.z;
    const int h   = blockIdx.y;
    const int r0  = blockIdx.x * 128;
    const int tid = threadIdx.x;
    const int lane = tid & 31;
    const int wid  = tid >> 5;
    const int g = lane >> 2;
    const int t = lane & 3;

    const float j2h = sinf(2.0f * thetas_head[h]) - 1.0f;

    const int koff = ((lane & 7) + ((lane & 16) >> 1)) * KSTR + (((lane >> 3) & 1) << 3);
    const int voff = ((lane & 7) + ((lane & 16) >> 1)) * VSTR + (((lane >> 3) & 1) << 3);

    unsigned qaH[4][4], qaL[4][4], qbH[4][4], qbL[4][4];
    {
        const int row0 = r0 + wid * 16 + g;
        const int base0 = (b * SG + row0) * EG + h * DH;
        const int base1 = base0 + 8 * EG;
        #pragma unroll
        for (int ks = 0; ks < 4; ks++) {
            const int col = ks * 16 + 2 * t;
            float2 a0 = *(const float2*)&g_qa[base0 + col];
            float2 a1 = *(const float2*)&g_qa[base1 + col];
            float2 a2 = *(const float2*)&g_qa[base0 + col + 8];
            float2 a3 = *(const float2*)&g_qa[base1 + col + 8];
            qaH[ks][0] = pack_hi2(a0.x, a0.y); qaL[ks][0] = pack_lo2(a0.x, a0.y);
            qaH[ks][1] = pack_hi2(a1.x, a1.y); qaL[ks][1] = pack_lo2(a1.x, a1.y);
            qaH[ks][2] = pack_hi2(a2.x, a2.y); qaL[ks][2] = pack_lo2(a2.x, a2.y);
            qaH[ks][3] = pack_hi2(a3.x, a3.y); qaL[ks][3] = pack_lo2(a3.x, a3.y);
            float2 b0 = *(const float2*)&g_qb[base0 + col];
            float2 b1 = *(const float2*)&g_qb[base1 + col];
            float2 b2 = *(const float2*)&g_qb[base0 + col + 8];
            float2 b3 = *(const float2*)&g_qb[base1 + col + 8];
            qbH[ks][0] = pack_hi2(b0.x, b0.y); qbL[ks][0] = pack_lo2(b0.x, b0.y);
            qbH[ks][1] = pack_hi2(b1.x, b1.y); qbL[ks][1] = pack_lo2(b1.x, b1.y);
            qbH[ks][2] = pack_hi2(b2.x, b2.y); qbL[ks][2] = pack_lo2(b2.x, b2.y);
            qbH[ks][3] = pack_hi2(b3.x, b3.y); qbL[ks][3] = pack_lo2(b3.x, b3.y);
        }
    }

    float oa[8][4] = {};
    float ob[8][4] = {};
    float mrow0 = -1e30f, mrow1 = -1e30f;
    float lrow0 = 0.0f,   lrow1 = 0.0f;

    const int ntiles = (r0 >> 5) + 4;
    for (int tile = 0; tile < ntiles; tile++) {
        const int k0 = tile * 32;

        __syncthreads();

        #pragma unroll
        for (int it = 0; it < 2; it++) {
            const int idx = tid + it * 256;
            const int n  = idx >> 4;
            const int d4 = (idx & 15) << 2;
            const int ga = (b * SG + k0 + n) * EG + h * DH + d4;
            float4 vka = *(const float4*)&g_ka[ga];
            float4 vkb = *(const float4*)&g_kb[ga];
            const int si = n * KSTR + d4;
            split_store4(sKaH, sKaL, si, vka);
            split_store4(sKbH, sKbL, si, vkb);
            float4 vkj = { j2h * vkb.x, j2h * vkb.y, j2h * vkb.z, j2h * vkb.w };
            split_store4(sKjH, sKjL, si, vkj);
        }
        #pragma unroll
        for (int it = 0; it < 2; it++) {
            const int idx = tid + it * 256;
            const int n  = idx >> 4;
            const int d4 = (idx & 15) << 2;
            const int ga = (b * SG + k0 + n) * EG + h * DH + d4;
            float4 vva = *(const float4*)&g_va[ga];
            float4 vvb = *(const float4*)&g_vb[ga];
            const float va4[4] = { vva.x, vva.y, vva.z, vva.w };
            const float vb4[4] = { vvb.x, vvb.y, vvb.z, vvb.w };
            #pragma unroll
            for (int j = 0; j < 4; j++) {
                const int si = (d4 + j) * VSTR + n;
                __nv_bfloat16 hv = __float2bfloat16(va4[j]);
                sVaH[si] = hv;
                sVaL[si] = __float2bfloat16(va4[j] - __bfloat162float(hv));
                __nv_bfloat16 hw = __float2bfloat16(vb4[j]);
                sVbH[si] = hw;
                sVbL[si] = __float2bfloat16(vb4[j] - __bfloat162float(hw));
            }
        }
        __syncthreads();

        const int wrow = r0 + wid * 16;
        if (k0 > wrow + 15) continue;

        float sa[4][4] = {};
        float sb[4][4] = {};
        #pragma unroll
        for (int ks = 0; ks < 4; ks++) {
            const int sk = ks * 16;
            #pragma unroll
            for (int pb = 0; pb < 2; pb++) {
                const int ko = pb * 16 * KSTR + koff + sk;
                unsigned kaH[4], kaL[4], kbH[4], kbL[4], kjH[4], kjL[4];
                ldsm_x4(kaH, sKaH + ko);
                ldsm_x4(kaL, sKaL + ko);
                ldsm_x4(kbH, sKbH + ko);
                ldsm_x4(kbL, sKbL + ko);
                ldsm_x4(kjH, sKjH + ko);
                ldsm_x4(kjL, sKjL + ko);

                #pragma unroll
                for (int half = 0; half < 2; half++) {
                    const int nf = pb * 2 + half;
                    const int o = half * 2;
                    mma_bf16(sa[nf], qaH[ks], kaH + o);
                    mma_bf16(sa[nf], qaH[ks], kaL + o);
                    mma_bf16(sa[nf], qaL[ks], kaH + o);
                    mma_bf16(sa[nf], qbH[ks], kjH + o);
                    mma_bf16(sa[nf], qbH[ks], kjL + o);
                    mma_bf16(sa[nf], qbL[ks], kjH + o);
                    mma_bf16(sb[nf], qaH[ks], kbH + o);
                    mma_bf16(sb[nf], qaH[ks], kbL + o);
                    mma_bf16(sb[nf], qaL[ks], kbH + o);
                    mma_bf16(sb[nf], qbH[ks], kaH + o);
                    mma_bf16(sb[nf], qbH[ks], kaL + o);
                    mma_bf16(sb[nf], qbL[ks], kaH + o);
                }
            }
        }

        const bool full = (k0 + 31 <= wrow);
        float mt0 = -1e30f, mt1 = -1e30f;
        #pragma unroll
        for (int nf = 0; nf < 4; nf++) {
            #pragma unroll
            for (int c = 0; c < 4; c++) {
                float v = sqrtf(sa[nf][c] * sa[nf][c] + sb[nf][c] * sb[nf][c] + 1e-8f) * 0.125f;
                if (!full) {
                    const int col = k0 + nf * 8 + 2 * t + (c & 1);
                    const int row = wrow + g + ((c & 2) ? 8 : 0);
                    if (col > row) v = -1e9f;
                }
                sa[nf][c] = v;
                if (c & 2) mt1 = fmaxf(mt1, v); else mt0 = fmaxf(mt0, v);
            }
        }
        mt0 = fmaxf(mt0, __shfl_xor_sync(0xffffffffu, mt0, 1));
        mt0 = fmaxf(mt0, __shfl_xor_sync(0xffffffffu, mt0, 2));
        mt1 = fmaxf(mt1, __shfl_xor_sync(0xffffffffu, mt1, 1));
        mt1 = fmaxf(mt1, __shfl_xor_sync(0xffffffffu, mt1, 2));

        const float mn0 = fmaxf(mrow0, mt0);
        const float mn1 = fmaxf(mrow1, mt1);

        float ps0 = 0.0f, ps1 = 0.0f;
        #pragma unroll
        for (int nf = 0; nf < 4; nf++) {
            #pragma unroll
            for (int c = 0; c < 4; c++) {
                const float p = __expf(sa[nf][c] - ((c & 2) ? mn1 : mn0));
                sa[nf][c] = p;
                if (c & 2) ps1 += p; else ps0 += p;
            }
        }
        ps0 += __shfl_xor_sync(0xffffffffu, ps0, 1);
        ps0 += __shfl_xor_sync(0xffffffffu, ps0, 2);
        ps1 += __shfl_xor_sync(0xffffffffu, ps1, 1);
        ps1 += __shfl_xor_sync(0xffffffffu, ps1, 2);

        const float sc0 = __expf(mrow0 - mn0);
        const float sc1 = __expf(mrow1 - mn1);
        lrow0 = lrow0 * sc0 + ps0;  mrow0 = mn0;
        lrow1 = lrow1 * sc1 + ps1;  mrow1 = mn1;
        #pragma unroll
        for (int nf = 0; nf < 8; nf++) {
            oa[nf][0] *= sc0; oa[nf][1] *= sc0; oa[nf][2] *= sc1; oa[nf][3] *= sc1;
            ob[nf][0] *= sc0; ob[nf][1] *= sc0; ob[nf][2] *= sc1; ob[nf][3] *= sc1;
        }

        unsigned pH[2][4], pL[2][4];
        #pragma unroll
        for (int kc = 0; kc < 2; kc++) {
            const int f = 2 * kc;
            pH[kc][0] = pack_hi2(sa[f][0],     sa[f][1]);
            pL[kc][0] = pack_lo2(sa[f][0],     sa[f][1]);
            pH[kc][1] = pack_hi2(sa[f][2],     sa[f][3]);
            pL[kc][1] = pack_lo2(sa[f][2],     sa[f][3]);
            pH[kc][2] = pack_hi2(sa[f + 1][0], sa[f + 1][1]);
            pL[kc][2] = pack_lo2(sa[f + 1][0], sa[f + 1][1]);
            pH[kc][3] = pack_hi2(sa[f + 1][2], sa[f + 1][3]);
            pL[kc][3] = pack_lo2(sa[f + 1][2], sa[f + 1][3]);
        }

        #pragma unroll
        for (int pv = 0; pv < 4; pv++) {
            #pragma unroll
            for (int kc = 0; kc < 2; kc++) {
                const int vo = pv * 16 * VSTR + voff + kc * 16;
                unsigned vaH[4], vaL[4], vbH[4], vbL[4];
                ldsm_x4(vaH, sVaH + vo);
                ldsm_x4(vaL, sVaL + vo);
                ldsm_x4(vbH, sVbH + vo);
                ldsm_x4(vbL, sVbL + vo);

                #pragma unroll
                for (int half = 0; half < 2; half++) {
                    const int nf = pv * 2 + half;
                    const int o = half * 2;
                    mma_bf16(oa[nf], pH[kc], vaH + o);
                    mma_bf16(oa[nf], pL[kc], vaH + o);
                    mma_bf16(oa[nf], pH[kc], vaL + o);
                    mma_bf16(ob[nf], pH[kc], vbH + o);
                    mma_bf16(ob[nf], pL[kc], vbH + o);
                    mma_bf16(ob[nf], pH[kc], vbL + o);
                }
            }
        }
    }

    // epilogue: write bf16 hi/lo for oa (6), ob (7), and os = oa+ob (8)
    const float inv0 = 1.0f / lrow0;
    const float inv1 = 1.0f / lrow1;
    const int row0 = r0 + wid * 16 + g;
    const int base0 = (b * SG + row0) * EG + h * DH;
    const int base1 = base0 + 8 * EG;
    __nv_bfloat16* xh6 = g_xH[6];  __nv_bfloat16* xl6 = g_xL[6];
    __nv_bfloat16* xh7 = g_xH[7];  __nv_bfloat16* xl7 = g_xL[7];
    __nv_bfloat16* xh8 = g_xH[8];  __nv_bfloat16* xl8 = g_xL[8];
    #pragma unroll
    for (int nf = 0; nf < 8; nf++) {
        const int d = nf * 8 + 2 * t;
        float a00 = oa[nf][0] * inv0, a01 = oa[nf][1] * inv0;
        float a10 = oa[nf][2] * inv1, a11 = oa[nf][3] * inv1;
        float b00 = ob[nf][0] * inv0, b01 = ob[nf][1] * inv0;
        float b10 = ob[nf][2] * inv1, b11 = ob[nf][3] * inv1;
        float s00 = a00 + b00, s01 = a01 + b01;
        float s10 = a10 + b10, s11 = a11 + b11;
        *(unsigned*)&xh6[base0 + d] = pack_hi2(a00, a01);
        *(unsigned*)&xl6[base0 + d] = pack_lo2(a00, a01);
        *(unsigned*)&xh6[base1 + d] = pack_hi2(a10, a11);
        *(unsigned*)&xl6[base1 + d] = pack_lo2(a10, a11);
        *(unsigned*)&xh7[base0 + d] = pack_hi2(b00, b01);
        *(unsigned*)&xl7[base0 + d] = pack_lo2(b00, b01);
        *(unsigned*)&xh7[base1 + d] = pack_hi2(b10, b11);
        *(unsigned*)&xl7[base1 + d] = pack_lo2(b10, b11);
        *(unsigned*)&xh8[base0 + d] = pack_hi2(s00, s01);
        *(unsigned*)&xl8[base0 + d] = pack_lo2(s00, s01);
        *(unsigned*)&xh8[base1 + d] = pack_hi2(s10, s11);
        *(unsigned*)&xl8[base1 + d] = pack_lo2(s10, s11);
    }
}

// ---------------------------------------------------------------------------
extern "C" void kernel_launch(void* const* d_in, const int* in_sizes, int n_in,
                              void* d_out, int out_size)
{
    const float* x_q_a  = (const float*)d_in[0];
    const float* x_q_b  = (const float*)d_in[1];
    const float* x_kv_a = (const float*)d_in[2];
    const float* x_kv_b = (const float*)d_in[3];
    // d_in[4] = mask -- causal, encoded in the attention kernel
    const float* layer_theta = (const float*)d_in[5];
    const float* thetas_head = (const float*)d_in[6];
    const float* q_wa = (const float*)d_in[7];
    const float* q_wb = (const float*)d_in[8];
    const float* q_ba = (const float*)d_in[9];
    const float* q_bb = (const float*)d_in[10];
    const float* k_wa = (const float*)d_in[11];
    const float* k_wb = (const float*)d_in[12];
    const float* k_ba = (const float*)d_in[13];
    const float* k_bb = (const float*)d_in[14];
    const float* v_wa = (const float*)d_in[15];
    const float* v_wb = (const float*)d_in[16];
    const float* v_ba = (const float*)d_in[17];
    const float* v_bb = (const float*)d_in[18];
    const float* o_wa = (const float*)d_in[19];
    const float* o_wb = (const float*)d_in[20];
    const float* o_ba = (const float*)d_in[21];
    const float* o_bb = (const float*)d_in[22];

    __nv_bfloat16 *wH, *wL, *xH, *xL;
    cudaGetSymbolAddress((void**)&wH, g_wH);
    cudaGetSymbolAddress((void**)&wL, g_wL);
    cudaGetSymbolAddress((void**)&xH, g_xH);
    cudaGetSymbolAddress((void**)&xL, g_xL);
    const size_t WSZ = (size_t)EG * EG;
    const size_t XSZ = (size_t)MG * EG;
    auto whi = [&](int i) { return wH + i * WSZ; };
    auto wlo = [&](int i) { return wL + i * WSZ; };
    auto xhi = [&](int i) { return xH + i * XSZ; };
    auto xlo = [&](int i) { return xL + i * XSZ; };

    float *qa, *qb;
    cudaGetSymbolAddress((void**)&qa, g_qa);
    cudaGetSymbolAddress((void**)&qb, g_qb);
    float *ka, *kb, *va, *vb;
    cudaGetSymbolAddress((void**)&ka, g_ka);
    cudaGetSymbolAddress((void**)&kb, g_kb);
    cudaGetSymbolAddress((void**)&va, g_va);
    cudaGetSymbolAddress((void**)&vb, g_vb);

    float* outA = (float*)d_out;
    float* outB = (float*)d_out + (size_t)MG * EG;

    const int GSMEM = NSTAGES * KSTAGE * (int)sizeof(__nv_bfloat16);  // 110592
    cudaFuncSetAttribute(qc_gemm_bf16_kernel,
                         cudaFuncAttributeMaxDynamicSharedMemorySize, GSMEM);

    // ---- split weights (8 matrices + 4 sums) ----
    {
        SplitBatch sb = {};
        const float* s1[12] = { q_wa, q_wb, q_wa, k_wa, k_wb, k_wa,
                                v_wa, v_wb, v_wa, o_wa, o_wb, o_wa };
        const float* s2[12] = { 0, 0, q_wb, 0, 0, k_wb,
                                0, 0, v_wb, 0, 0, o_wb };
        for (int i = 0; i < 12; i++) {
            sb.s1[i] = s1[i]; sb.s2[i] = s2[i];
            sb.hi[i] = whi(i); sb.lo[i] = wlo(i);
        }
        split_kernel<<<dim3((unsigned)(WSZ / 4 / 256), 12), 256>>>(sb, (int)(WSZ / 4));
    }
    // ---- split input activations (4 tensors + 2 sums) ----
    {
        SplitBatch sb = {};
        const float* s1[6] = { x_q_a, x_q_b, x_q_a, x_kv_a, x_kv_b, x_kv_a };
        const float* s2[6] = { 0, 0, x_q_b, 0, 0, x_kv_b };
        for (int i = 0; i < 6; i++) {
            sb.s1[i] = s1[i]; sb.s2[i] = s2[i];
            sb.hi[i] = xhi(i); sb.lo[i] = xlo(i);
        }
        split_kernel<<<dim3((unsigned)(XSZ / 4 / 256), 6), 256>>>(sb, (int)(XSZ / 4));
    }

    const dim3 gg(EG / 64, MG / 64);

    // q / k / v projections (Karatsuba)
    qc_gemm_bf16_kernel<<<gg, 256, GSMEM>>>(
        xhi(0), xlo(0), xhi(1), xlo(1), xhi(2), xlo(2),
        whi(0), wlo(0), whi(1), wlo(1), whi(2), wlo(2),
        q_ba, q_bb, layer_theta, qa, qb);
    qc_gemm_bf16_kernel<<<gg, 256, GSMEM>>>(
        xhi(3), xlo(3), xhi(4), xlo(4), xhi(5), xlo(5),
        whi(3), wlo(3), whi(4), wlo(4), whi(5), wlo(5),
        k_ba, k_bb, layer_theta, ka, kb);
    qc_gemm_bf16_kernel<<<gg, 256, GSMEM>>>(
        xhi(3), xlo(3), xhi(4), xlo(4), xhi(5), xlo(5),
        whi(6), wlo(6), whi(7), wlo(7), whi(8), wlo(8),
        v_ba, v_bb, layer_theta, va, vb);

    // RoPE on qa,qb,ka,kb (in place)
    rope_kernel<<<(4 * MG * (EG / 2)) / 256, 256>>>();

    // tensor-core flash attention -> writes pre-split oa/ob/os (g_xH/L[6..8])
    attn_mma_kernel<<<dim3(SG / 128, HG, 2), 256>>>(thetas_head);

    // output projection straight into d_out (out_a then out_b)
    qc_gemm_bf16_kernel<<<gg, 256, GSMEM>>>(
        xhi(6), xlo(6), xhi(7), xlo(7), xhi(8), xlo(8),
        whi(9), wlo(9), whi(10), wlo(10), whi(11), wlo(11),
        o_ba, o_bb, layer_theta, outA, outB);
}

// round 11
// speedup vs baseline: 1.2345x; 1.2345x over previous
#include <cuda_runtime.h>
#include <cuda_bf16.h>
#include <math.h>

// Problem constants
#define EG 1024      // embed dim
#define MG 2048      // B*S rows
#define SG 1024      // seq len
#define HG 16        // heads
#define DH 64        // head dim

// ---------------- scratch (device globals: no runtime allocation allowed) ----
__device__ float g_qa[MG * EG];
__device__ float g_qb[MG * EG];
__device__ float g_ka[MG * EG];
__device__ float g_kb[MG * EG];
__device__ float g_va[MG * EG];
__device__ float g_vb[MG * EG];

// pre-split bf16 hi/lo buffers
// weights: 0 q_wa, 1 q_wb, 2 k_wa, 3 k_wb, 4 v_wa, 5 v_wb, 6 o_wa, 7 o_wb
__device__ __nv_bfloat16 g_wH[8][EG * EG];
__device__ __nv_bfloat16 g_wL[8][EG * EG];
// activations: 0 x_q_a, 1 x_q_b, 2 x_kv_a, 3 x_kv_b, 4 oa, 5 ob
__device__ __nv_bfloat16 g_xH[6][MG * EG];
__device__ __nv_bfloat16 g_xL[6][MG * EG];

// ---------------------------------------------------------------------------
// helpers
// ---------------------------------------------------------------------------
__device__ __forceinline__ void mma_bf16(float* c, const unsigned* a, const unsigned* b)
{
    asm volatile(
        "mma.sync.aligned.m16n8k16.row.col.f32.bf16.bf16.f32 "
        "{%0,%1,%2,%3}, {%4,%5,%6,%7}, {%8,%9}, {%0,%1,%2,%3};"
        : "+f"(c[0]), "+f"(c[1]), "+f"(c[2]), "+f"(c[3])
        : "r"(a[0]), "r"(a[1]), "r"(a[2]), "r"(a[3]),
          "r"(b[0]), "r"(b[1]));
}

__device__ __forceinline__ void ldsm_x4(unsigned* r, const __nv_bfloat16* p)
{
    unsigned addr = (unsigned)__cvta_generic_to_shared(p);
    asm volatile("ldmatrix.sync.aligned.m8n8.x4.shared.b16 {%0,%1,%2,%3}, [%4];"
                 : "=r"(r[0]), "=r"(r[1]), "=r"(r[2]), "=r"(r[3]) : "r"(addr));
}

__device__ __forceinline__ unsigned pack_hi2(float x, float y)
{
    __nv_bfloat162 h(__float2bfloat16(x), __float2bfloat16(y));
    return *reinterpret_cast<unsigned*>(&h);
}
__device__ __forceinline__ unsigned pack_lo2(float x, float y)
{
    float hx = __bfloat162float(__float2bfloat16(x));
    float hy = __bfloat162float(__float2bfloat16(y));
    __nv_bfloat162 l(__float2bfloat16(x - hx), __float2bfloat16(y - hy));
    return *reinterpret_cast<unsigned*>(&l);
}

__device__ __forceinline__ void cp_async16(unsigned daddr, const void* src)
{
    asm volatile("cp.async.cg.shared.global [%0], [%1], 16;" :: "r"(daddr), "l"(src));
}
__device__ __forceinline__ void cp_commit()
{
    asm volatile("cp.async.commit_group;");
}
template<int N>
__device__ __forceinline__ void cp_wait()
{
    asm volatile("cp.async.wait_group %0;" :: "n"(N));
}

// smem tile strides (bf16 halfword units). BK=32 + pad 8 -> conflict-free frags.
#define TSTR 40
#define TILE_HF (64 * TSTR)

// split fp32 -> bf16 hi/lo, write pairs into smem tiles (used in attention)
__device__ __forceinline__ void split_store4(
    __nv_bfloat16* shi, __nv_bfloat16* slo, int idx, float4 v)
{
    __nv_bfloat16 hx = __float2bfloat16(v.x);
    __nv_bfloat16 hy = __float2bfloat16(v.y);
    __nv_bfloat16 hz = __float2bfloat16(v.z);
    __nv_bfloat16 hw = __float2bfloat16(v.w);
    __nv_bfloat16 lx = __float2bfloat16(v.x - __bfloat162float(hx));
    __nv_bfloat16 ly = __float2bfloat16(v.y - __bfloat162float(hy));
    __nv_bfloat16 lz = __float2bfloat16(v.z - __bfloat162float(hz));
    __nv_bfloat16 lw = __float2bfloat16(v.w - __bfloat162float(hw));
    *reinterpret_cast<__nv_bfloat162*>(&shi[idx])     = __nv_bfloat162(hx, hy);
    *reinterpret_cast<__nv_bfloat162*>(&shi[idx + 2]) = __nv_bfloat162(hz, hw);
    *reinterpret_cast<__nv_bfloat162*>(&slo[idx])     = __nv_bfloat162(lx, ly);
    *reinterpret_cast<__nv_bfloat162*>(&slo[idx + 2]) = __nv_bfloat162(lz, lw);
}

// load B fragment (k16 x n8, col layout == W[n][k] row-major) from [n][stride]
template<int STRIDE>
__device__ __forceinline__ void load_bfragS(
    unsigned* b, const __nv_bfloat16* s, int nbase, int sk, int g, int t)
{
    const int r = (nbase + g) * STRIDE + sk + 2 * t;
    b[0] = *reinterpret_cast<const unsigned*>(&s[r]);
    b[1] = *reinterpret_cast<const unsigned*>(&s[r + 8]);
}

// ---------------------------------------------------------------------------
// Batched fp32 -> bf16 hi/lo split. blockIdx.y selects the tensor.
// ---------------------------------------------------------------------------
struct SplitBatch {
    const float* src[8];
    __nv_bfloat16* hi[8];
    __nv_bfloat16* lo[8];
};

__global__ __launch_bounds__(256) void split_kernel(SplitBatch sb, int nvec)
{
    const int t = blockIdx.x * 256 + threadIdx.x;
    if (t >= nvec) return;
    const int w = blockIdx.y;
    const float4 v = reinterpret_cast<const float4*>(sb.src[w])[t];

    unsigned h0 = pack_hi2(v.x, v.y);
    unsigned h1 = pack_hi2(v.z, v.w);
    unsigned l0 = pack_lo2(v.x, v.y);
    unsigned l1 = pack_lo2(v.z, v.w);

    reinterpret_cast<uint2*>(sb.hi[w])[t] = make_uint2(h0, h1);
    reinterpret_cast<uint2*>(sb.lo[w])[t] = make_uint2(l0, l1);
}

// ---------------------------------------------------------------------------
// Fused quaternion-complex dense on tensor cores, pre-split bf16 inputs,
// cp.async double-buffered mainloop, ldmatrix fragment loads.
//   outA = Xa.Wa^T + j2 * Xb.Wb^T + ba ;  outB = Xa.Wb^T + Xb.Wa^T + bb
// 64x64 CTA tile, BK=32, 256 threads = 8 warps (4x2), warp tile 16x32.
// __launch_bounds__(256, 2): cap regs at 128 so 2 CTAs/SM always fit
// (R9 lesson: ldmatrix alone pushed regs to 134 -> 1 CTA/SM -> regression).
// ---------------------------------------------------------------------------
__global__ __launch_bounds__(256, 2) void qc_gemm_bf16_kernel(
    const __nv_bfloat16* __restrict__ xaH, const __nv_bfloat16* __restrict__ xaL,
    const __nv_bfloat16* __restrict__ xbH, const __nv_bfloat16* __restrict__ xbL,
    const __nv_bfloat16* __restrict__ waH, const __nv_bfloat16* __restrict__ waL,
    const __nv_bfloat16* __restrict__ wbH, const __nv_bfloat16* __restrict__ wbL,
    const float* __restrict__ ba, const float* __restrict__ bb,
    const float* __restrict__ theta_ptr,
    float* __restrict__ outA, float* __restrict__ outB)
{
    extern __shared__ __nv_bfloat16 sbuf[];

    const int tid = threadIdx.x;
    const int lane = tid & 31;
    const int wid = tid >> 5;
    const int warp_m = wid >> 1;
    const int warp_n = wid & 1;
    const int g = lane >> 2;
    const int t = lane & 3;

    const int m0 = blockIdx.y * 64;
    const int n0 = blockIdx.x * 64;

    const float j2 = sinf(2.0f * theta_ptr[0]) - 1.0f;

    // ldmatrix per-lane offsets (within a [rows][TSTR] tile, before +sk)
    const int aoff = (warp_m * 16 + (lane & 15)) * TSTR + ((lane >> 4) << 3);
    const int boff = ((lane & 7) + ((lane & 16) >> 1)) * TSTR + (((lane >> 3) & 1) << 3);

    // loader mapping: full 4096B tile coverage, 16B-aligned chunks
    const int losel = tid >> 7;           // 0 hi, 1 lo
    const int tt    = tid & 127;
    const int lr0   = tt >> 2;            // rows 0..31 (chunk j=0)
    const int lc0   = (tt & 3) << 3;      // cols 0,8,16,24 (elements)

    const __nv_bfloat16* sxa = (losel ? xaL : xaH) + (size_t)(m0 + lr0) * EG + lc0;
    const __nv_bfloat16* sxb = (losel ? xbL : xbH) + (size_t)(m0 + lr0) * EG + lc0;
    const __nv_bfloat16* swa = (losel ? waL : waH) + (size_t)(n0 + lr0) * EG + lc0;
    const __nv_bfloat16* swb = (losel ? wbL : wbH) + (size_t)(n0 + lr0) * EG + lc0;
    const size_t GROW = (size_t)32 * EG;  // +32 rows in gmem

    const int doff0 = lr0 * TSTR + lc0;
    const int doff1 = doff0 + 32 * TSTR;
    unsigned dxa[2][2], dxb[2][2], dwa[2][2], dwb[2][2];
    #pragma unroll
    for (int st = 0; st < 2; st++) {
        __nv_bfloat16* base = sbuf + st * 8 * TILE_HF;
        __nv_bfloat16* bxa = base + (0 + losel) * TILE_HF;
        __nv_bfloat16* bxb = base + (2 + losel) * TILE_HF;
        __nv_bfloat16* bwa = base + (4 + losel) * TILE_HF;
        __nv_bfloat16* bwb = base + (6 + losel) * TILE_HF;
        dxa[st][0] = (unsigned)__cvta_generic_to_shared(bxa + doff0);
        dxa[st][1] = (unsigned)__cvta_generic_to_shared(bxa + doff1);
        dxb[st][0] = (unsigned)__cvta_generic_to_shared(bxb + doff0);
        dxb[st][1] = (unsigned)__cvta_generic_to_shared(bxb + doff1);
        dwa[st][0] = (unsigned)__cvta_generic_to_shared(bwa + doff0);
        dwa[st][1] = (unsigned)__cvta_generic_to_shared(bwa + doff1);
        dwb[st][0] = (unsigned)__cvta_generic_to_shared(bwb + doff0);
        dwb[st][1] = (unsigned)__cvta_generic_to_shared(bwb + doff1);
    }

    float accA1[4][4] = {};
    float accA2[4][4] = {};
    float accB [4][4] = {};

    // prologue: stage 0, k0 = 0
    cp_async16(dxa[0][0], sxa);          cp_async16(dxa[0][1], sxa + GROW);
    cp_async16(dxb[0][0], sxb);          cp_async16(dxb[0][1], sxb + GROW);
    cp_async16(dwa[0][0], swa);          cp_async16(dwa[0][1], swa + GROW);
    cp_async16(dwb[0][0], swb);          cp_async16(dwb[0][1], swb + GROW);
    cp_commit();

    const int NIT = EG / 32;
    for (int it = 0; it < NIT; it++) {
        const int cur = it & 1;
        if (it + 1 < NIT) {
            const int nk = (it + 1) * 32;
            const int ns = 1 - cur;
            cp_async16(dxa[ns][0], sxa + nk);   cp_async16(dxa[ns][1], sxa + nk + GROW);
            cp_async16(dxb[ns][0], sxb + nk);   cp_async16(dxb[ns][1], sxb + nk + GROW);
            cp_async16(dwa[ns][0], swa + nk);   cp_async16(dwa[ns][1], swa + nk + GROW);
            cp_async16(dwb[ns][0], swb + nk);   cp_async16(dwb[ns][1], swb + nk + GROW);
            cp_commit();
            cp_wait<1>();
        } else {
            cp_wait<0>();
        }
        __syncthreads();

        const __nv_bfloat16* cb = sbuf + cur * 8 * TILE_HF;
        const __nv_bfloat16* sXaH = cb + 0 * TILE_HF;
        const __nv_bfloat16* sXaL = cb + 1 * TILE_HF;
        const __nv_bfloat16* sXbH = cb + 2 * TILE_HF;
        const __nv_bfloat16* sXbL = cb + 3 * TILE_HF;
        const __nv_bfloat16* sWaH = cb + 4 * TILE_HF;
        const __nv_bfloat16* sWaL = cb + 5 * TILE_HF;
        const __nv_bfloat16* sWbH = cb + 6 * TILE_HF;
        const __nv_bfloat16* sWbL = cb + 7 * TILE_HF;

        #pragma unroll
        for (int ks = 0; ks < 2; ks++) {
            const int sk = ks * 16;
            unsigned aXaH[4], aXaL[4], aXbH[4], aXbL[4];
            ldsm_x4(aXaH, sXaH + aoff + sk);
            ldsm_x4(aXaL, sXaL + aoff + sk);
            ldsm_x4(aXbH, sXbH + aoff + sk);
            ldsm_x4(aXbL, sXbL + aoff + sk);

            #pragma unroll
            for (int fp = 0; fp < 2; fp++) {
                const int bo = (warp_n * 32 + fp * 16) * TSTR + boff + sk;
                unsigned bWaH[4], bWaL[4], bWbH[4], bWbL[4];
                ldsm_x4(bWaH, sWaH + bo);
                ldsm_x4(bWaL, sWaL + bo);
                ldsm_x4(bWbH, sWbH + bo);
                ldsm_x4(bWbL, sWbL + bo);

                #pragma unroll
                for (int half = 0; half < 2; half++) {
                    const int f = fp * 2 + half;
                    const int o = half * 2;
                    mma_bf16(accA1[f], aXaH, bWaH + o);
                    mma_bf16(accA1[f], aXaH, bWaL + o);
                    mma_bf16(accA1[f], aXaL, bWaH + o);
                    mma_bf16(accA2[f], aXbH, bWbH + o);
                    mma_bf16(accA2[f], aXbH, bWbL + o);
                    mma_bf16(accA2[f], aXbL, bWbH + o);
                    mma_bf16(accB[f], aXaH, bWbH + o);
                    mma_bf16(accB[f], aXaH, bWbL + o);
                    mma_bf16(accB[f], aXaL, bWbH + o);
                    mma_bf16(accB[f], aXbH, bWaH + o);
                    mma_bf16(accB[f], aXbH, bWaL + o);
                    mma_bf16(accB[f], aXbL, bWaH + o);
                }
            }
        }
        __syncthreads();   // compute done before this stage is refilled
    }

    #pragma unroll
    for (int f = 0; f < 4; f++) {
        const int n = n0 + warp_n * 32 + f * 8 + 2 * t;
        const int r0 = m0 + warp_m * 16 + g;
        const int r1 = r0 + 8;
        const float ba0 = ba[n], ba1 = ba[n + 1];
        const float bb0 = bb[n], bb1 = bb[n + 1];

        float2 oa0 = { accA1[f][0] + j2 * accA2[f][0] + ba0,
                       accA1[f][1] + j2 * accA2[f][1] + ba1 };
        float2 oa1 = { accA1[f][2] + j2 * accA2[f][2] + ba0,
                       accA1[f][3] + j2 * accA2[f][3] + ba1 };
        float2 ob0 = { accB[f][0] + bb0, accB[f][1] + bb1 };
        float2 ob1 = { accB[f][2] + bb0, accB[f][3] + bb1 };

        *(float2*)&outA[r0 * EG + n] = oa0;
        *(float2*)&outA[r1 * EG + n] = oa1;
        *(float2*)&outB[r0 * EG + n] = ob0;
        *(float2*)&outB[r1 * EG + n] = ob1;
    }
}

// ---------------------------------------------------------------------------
// RoPE applied in place to g_qa, g_qb, g_ka, g_kb (fp32 throughout).
// ---------------------------------------------------------------------------
__global__ __launch_bounds__(256) void rope_kernel()
{
    const int PAIRS = MG * (EG / 2);
    int tt = blockIdx.x * blockDim.x + threadIdx.x;
    if (tt >= 4 * PAIRS) return;

    const int w = tt / PAIRS;
    const int p = tt % PAIRS;
    float* X = (w == 0) ? g_qa : (w == 1) ? g_qb : (w == 2) ? g_ka : g_kb;

    const int row = p >> 9;
    const int pp  = p & 511;
    const int h   = pp >> 5;
    const int i   = pp & 31;
    const int s   = row & (SG - 1);

    const float freq = exp2f(-(float)i * (13.287712379549449f / 32.0f));
    float sn, cs;
    sincosf((float)s * freq, &sn, &cs);

    const int base = row * EG + h * DH + i;
    const float x1 = X[base];
    const float x2 = X[base + 32];
    X[base]      = x1 * cs - x2 * sn;
    X[base + 32] = x2 * cs + x1 * sn;
}

// ---------------------------------------------------------------------------
// Tensor-core flash attention with complex-magnitude scores, bf16 hi/lo split.
// (R5-validated fragment-load path; epilogue writes pre-split bf16 hi/lo.)
// ---------------------------------------------------------------------------
#define KSTR 72
#define VSTR 40

__global__ __launch_bounds__(256) void attn_mma_kernel(const float* __restrict__ thetas_head)
{
    __shared__ __nv_bfloat16 sKaH[32 * KSTR], sKaL[32 * KSTR];
    __shared__ __nv_bfloat16 sKbH[32 * KSTR], sKbL[32 * KSTR];
    __shared__ __nv_bfloat16 sKjH[32 * KSTR], sKjL[32 * KSTR];
    __shared__ __nv_bfloat16 sVaH[64 * VSTR], sVaL[64 * VSTR];
    __shared__ __nv_bfloat16 sVbH[64 * VSTR], sVbL[64 * VSTR];

    const int b   = blockIdx.z;
    const int h   = blockIdx.y;
    const int r0  = blockIdx.x * 128;
    const int tid = threadIdx.x;
    const int lane = tid & 31;
    const int wid  = tid >> 5;
    const int g = lane >> 2;
    const int t = lane & 3;

    const float j2h = sinf(2.0f * thetas_head[h]) - 1.0f;

    unsigned qaH[4][4], qaL[4][4], qbH[4][4], qbL[4][4];
    {
        const int row0 = r0 + wid * 16 + g;
        const int base0 = (b * SG + row0) * EG + h * DH;
        const int base1 = base0 + 8 * EG;
        #pragma unroll
        for (int ks = 0; ks < 4; ks++) {
            const int col = ks * 16 + 2 * t;
            float2 a0 = *(const float2*)&g_qa[base0 + col];
            float2 a1 = *(const float2*)&g_qa[base1 + col];
            float2 a2 = *(const float2*)&g_qa[base0 + col + 8];
            float2 a3 = *(const float2*)&g_qa[base1 + col + 8];
            qaH[ks][0] = pack_hi2(a0.x, a0.y); qaL[ks][0] = pack_lo2(a0.x, a0.y);
            qaH[ks][1] = pack_hi2(a1.x, a1.y); qaL[ks][1] = pack_lo2(a1.x, a1.y);
            qaH[ks][2] = pack_hi2(a2.x, a2.y); qaL[ks][2] = pack_lo2(a2.x, a2.y);
            qaH[ks][3] = pack_hi2(a3.x, a3.y); qaL[ks][3] = pack_lo2(a3.x, a3.y);
            float2 b0 = *(const float2*)&g_qb[base0 + col];
            float2 b1 = *(const float2*)&g_qb[base1 + col];
            float2 b2 = *(const float2*)&g_qb[base0 + col + 8];
            float2 b3 = *(const float2*)&g_qb[base1 + col + 8];
            qbH[ks][0] = pack_hi2(b0.x, b0.y); qbL[ks][0] = pack_lo2(b0.x, b0.y);
            qbH[ks][1] = pack_hi2(b1.x, b1.y); qbL[ks][1] = pack_lo2(b1.x, b1.y);
            qbH[ks][2] = pack_hi2(b2.x, b2.y); qbL[ks][2] = pack_lo2(b2.x, b2.y);
            qbH[ks][3] = pack_hi2(b3.x, b3.y); qbL[ks][3] = pack_lo2(b3.x, b3.y);
        }
    }

    float oa[8][4] = {};
    float ob[8][4] = {};
    float mrow0 = -1e30f, mrow1 = -1e30f;
    float lrow0 = 0.0f,   lrow1 = 0.0f;

    const int ntiles = (r0 >> 5) + 4;
    for (int tile = 0; tile < ntiles; tile++) {
        const int k0 = tile * 32;

        __syncthreads();

        #pragma unroll
        for (int it = 0; it < 2; it++) {
            const int idx = tid + it * 256;
            const int n  = idx >> 4;
            const int d4 = (idx & 15) << 2;
            const int ga = (b * SG + k0 + n) * EG + h * DH + d4;
            float4 vka = *(const float4*)&g_ka[ga];
            float4 vkb = *(const float4*)&g_kb[ga];
            const int si = n * KSTR + d4;
            split_store4(sKaH, sKaL, si, vka);
            split_store4(sKbH, sKbL, si, vkb);
            float4 vkj = { j2h * vkb.x, j2h * vkb.y, j2h * vkb.z, j2h * vkb.w };
            split_store4(sKjH, sKjL, si, vkj);
        }
        #pragma unroll
        for (int it = 0; it < 2; it++) {
            const int idx = tid + it * 256;
            const int n  = idx >> 4;
            const int d4 = (idx & 15) << 2;
            const int ga = (b * SG + k0 + n) * EG + h * DH + d4;
            float4 vva = *(const float4*)&g_va[ga];
            float4 vvb = *(const float4*)&g_vb[ga];
            const float va4[4] = { vva.x, vva.y, vva.z, vva.w };
            const float vb4[4] = { vvb.x, vvb.y, vvb.z, vvb.w };
            #pragma unroll
            for (int j = 0; j < 4; j++) {
                const int si = (d4 + j) * VSTR + n;
                __nv_bfloat16 hv = __float2bfloat16(va4[j]);
                sVaH[si] = hv;
                sVaL[si] = __float2bfloat16(va4[j] - __bfloat162float(hv));
                __nv_bfloat16 hw = __float2bfloat16(vb4[j]);
                sVbH[si] = hw;
                sVbL[si] = __float2bfloat16(vb4[j] - __bfloat162float(hw));
            }
        }
        __syncthreads();

        const int wrow = r0 + wid * 16;
        if (k0 > wrow + 15) continue;

        float sa[4][4] = {};
        float sb[4][4] = {};
        #pragma unroll
        for (int ks = 0; ks < 4; ks++) {
            const int sk = ks * 16;
            #pragma unroll
            for (int nf = 0; nf < 4; nf++) {
                const int nb = nf * 8;
                unsigned kaH[2], kaL[2], kbH[2], kbL[2], kjH[2], kjL[2];
                load_bfragS<KSTR>(kaH, sKaH, nb, sk, g, t);
                load_bfragS<KSTR>(kaL, sKaL, nb, sk, g, t);
                load_bfragS<KSTR>(kbH, sKbH, nb, sk, g, t);
                load_bfragS<KSTR>(kbL, sKbL, nb, sk, g, t);
                load_bfragS<KSTR>(kjH, sKjH, nb, sk, g, t);
                load_bfragS<KSTR>(kjL, sKjL, nb, sk, g, t);

                mma_bf16(sa[nf], qaH[ks], kaH);
                mma_bf16(sa[nf], qaH[ks], kaL);
                mma_bf16(sa[nf], qaL[ks], kaH);
                mma_bf16(sa[nf], qbH[ks], kjH);
                mma_bf16(sa[nf], qbH[ks], kjL);
                mma_bf16(sa[nf], qbL[ks], kjH);
                mma_bf16(sb[nf], qaH[ks], kbH);
                mma_bf16(sb[nf], qaH[ks], kbL);
                mma_bf16(sb[nf], qaL[ks], kbH);
                mma_bf16(sb[nf], qbH[ks], kaH);
                mma_bf16(sb[nf], qbH[ks], kaL);
                mma_bf16(sb[nf], qbL[ks], kaH);
            }
        }

        const bool full = (k0 + 31 <= wrow);
        float mt0 = -1e30f, mt1 = -1e30f;
        #pragma unroll
        for (int nf = 0; nf < 4; nf++) {
            #pragma unroll
            for (int c = 0; c < 4; c++) {
                float v = sqrtf(sa[nf][c] * sa[nf][c] + sb[nf][c] * sb[nf][c] + 1e-8f) * 0.125f;
                if (!full) {
                    const int col = k0 + nf * 8 + 2 * t + (c & 1);
                    const int row = wrow + g + ((c & 2) ? 8 : 0);
                    if (col > row) v = -1e9f;
                }
                sa[nf][c] = v;
                if (c & 2) mt1 = fmaxf(mt1, v); else mt0 = fmaxf(mt0, v);
            }
        }
        mt0 = fmaxf(mt0, __shfl_xor_sync(0xffffffffu, mt0, 1));
        mt0 = fmaxf(mt0, __shfl_xor_sync(0xffffffffu, mt0, 2));
        mt1 = fmaxf(mt1, __shfl_xor_sync(0xffffffffu, mt1, 1));
        mt1 = fmaxf(mt1, __shfl_xor_sync(0xffffffffu, mt1, 2));

        const float mn0 = fmaxf(mrow0, mt0);
        const float mn1 = fmaxf(mrow1, mt1);

        float ps0 = 0.0f, ps1 = 0.0f;
        #pragma unroll
        for (int nf = 0; nf < 4; nf++) {
            #pragma unroll
            for (int c = 0; c < 4; c++) {
                const float p = __expf(sa[nf][c] - ((c & 2) ? mn1 : mn0));
                sa[nf][c] = p;
                if (c & 2) ps1 += p; else ps0 += p;
            }
        }
        ps0 += __shfl_xor_sync(0xffffffffu, ps0, 1);
        ps0 += __shfl_xor_sync(0xffffffffu, ps0, 2);
        ps1 += __shfl_xor_sync(0xffffffffu, ps1, 1);
        ps1 += __shfl_xor_sync(0xffffffffu, ps1, 2);

        const float sc0 = __expf(mrow0 - mn0);
        const float sc1 = __expf(mrow1 - mn1);
        lrow0 = lrow0 * sc0 + ps0;  mrow0 = mn0;
        lrow1 = lrow1 * sc1 + ps1;  mrow1 = mn1;
        #pragma unroll
        for (int nf = 0; nf < 8; nf++) {
            oa[nf][0] *= sc0; oa[nf][1] *= sc0; oa[nf][2] *= sc1; oa[nf][3] *= sc1;
            ob[nf][0] *= sc0; ob[nf][1] *= sc0; ob[nf][2] *= sc1; ob[nf][3] *= sc1;
        }

        unsigned pH[2][4], pL[2][4];
        #pragma unroll
        for (int kc = 0; kc < 2; kc++) {
            const int f = 2 * kc;
            pH[kc][0] = pack_hi2(sa[f][0],     sa[f][1]);
            pL[kc][0] = pack_lo2(sa[f][0],     sa[f][1]);
            pH[kc][1] = pack_hi2(sa[f][2],     sa[f][3]);
            pL[kc][1] = pack_lo2(sa[f][2],     sa[f][3]);
            pH[kc][2] = pack_hi2(sa[f + 1][0], sa[f + 1][1]);
            pL[kc][2] = pack_lo2(sa[f + 1][0], sa[f + 1][1]);
            pH[kc][3] = pack_hi2(sa[f + 1][2], sa[f + 1][3]);
            pL[kc][3] = pack_lo2(sa[f + 1][2], sa[f + 1][3]);
        }

        #pragma unroll
        for (int nf = 0; nf < 8; nf++) {
            const int nb = nf * 8;
            #pragma unroll
            for (int kc = 0; kc < 2; kc++) {
                const int sk = kc * 16;
                unsigned vaH[2], vaL[2], vbH[2], vbL[2];
                load_bfragS<VSTR>(vaH, sVaH, nb, sk, g, t);
                load_bfragS<VSTR>(vaL, sVaL, nb, sk, g, t);
                load_bfragS<VSTR>(vbH, sVbH, nb, sk, g, t);
                load_bfragS<VSTR>(vbL, sVbL, nb, sk, g, t);

                mma_bf16(oa[nf], pH[kc], vaH);
                mma_bf16(oa[nf], pL[kc], vaH);
                mma_bf16(oa[nf], pH[kc], vaL);
                mma_bf16(ob[nf], pH[kc], vbH);
                mma_bf16(ob[nf], pL[kc], vbH);
                mma_bf16(ob[nf], pH[kc], vbL);
            }
        }
    }

    // epilogue: write bf16 hi/lo directly (identical split of the fp32 value)
    const float inv0 = 1.0f / lrow0;
    const float inv1 = 1.0f / lrow1;
    const int row0 = r0 + wid * 16 + g;
    const int base0 = (b * SG + row0) * EG + h * DH;
    const int base1 = base0 + 8 * EG;
    __nv_bfloat16* xh4 = g_xH[4];  __nv_bfloat16* xl4 = g_xL[4];
    __nv_bfloat16* xh5 = g_xH[5];  __nv_bfloat16* xl5 = g_xL[5];
    #pragma unroll
    for (int nf = 0; nf < 8; nf++) {
        const int d = nf * 8 + 2 * t;
        float a00 = oa[nf][0] * inv0, a01 = oa[nf][1] * inv0;
        float a10 = oa[nf][2] * inv1, a11 = oa[nf][3] * inv1;
        float b00 = ob[nf][0] * inv0, b01 = ob[nf][1] * inv0;
        float b10 = ob[nf][2] * inv1, b11 = ob[nf][3] * inv1;
        *(unsigned*)&xh4[base0 + d] = pack_hi2(a00, a01);
        *(unsigned*)&xl4[base0 + d] = pack_lo2(a00, a01);
        *(unsigned*)&xh4[base1 + d] = pack_hi2(a10, a11);
        *(unsigned*)&xl4[base1 + d] = pack_lo2(a10, a11);
        *(unsigned*)&xh5[base0 + d] = pack_hi2(b00, b01);
        *(unsigned*)&xl5[base0 + d] = pack_lo2(b00, b01);
        *(unsigned*)&xh5[base1 + d] = pack_hi2(b10, b11);
        *(unsigned*)&xl5[base1 + d] = pack_lo2(b10, b11);
    }
}

// ---------------------------------------------------------------------------
extern "C" void kernel_launch(void* const* d_in, const int* in_sizes, int n_in,
                              void* d_out, int out_size)
{
    const float* x_q_a  = (const float*)d_in[0];
    const float* x_q_b  = (const float*)d_in[1];
    const float* x_kv_a = (const float*)d_in[2];
    const float* x_kv_b = (const float*)d_in[3];
    // d_in[4] = mask -- causal, encoded in the attention kernel
    const float* layer_theta = (const float*)d_in[5];
    const float* thetas_head = (const float*)d_in[6];
    const float* q_wa = (const float*)d_in[7];
    const float* q_wb = (const float*)d_in[8];
    const float* q_ba = (const float*)d_in[9];
    const float* q_bb = (const float*)d_in[10];
    const float* k_wa = (const float*)d_in[11];
    const float* k_wb = (const float*)d_in[12];
    const float* k_ba = (const float*)d_in[13];
    const float* k_bb = (const float*)d_in[14];
    const float* v_wa = (const float*)d_in[15];
    const float* v_wb = (const float*)d_in[16];
    const float* v_ba = (const float*)d_in[17];
    const float* v_bb = (const float*)d_in[18];
    const float* o_wa = (const float*)d_in[19];
    const float* o_wb = (const float*)d_in[20];
    const float* o_ba = (const float*)d_in[21];
    const float* o_bb = (const float*)d_in[22];

    float *qa, *qb, *ka, *kb, *va, *vb;
    cudaGetSymbolAddress((void**)&qa, g_qa);
    cudaGetSymbolAddress((void**)&qb, g_qb);
    cudaGetSymbolAddress((void**)&ka, g_ka);
    cudaGetSymbolAddress((void**)&kb, g_kb);
    cudaGetSymbolAddress((void**)&va, g_va);
    cudaGetSymbolAddress((void**)&vb, g_vb);

    __nv_bfloat16 *wH, *wL, *xH, *xL;
    cudaGetSymbolAddress((void**)&wH, g_wH);
    cudaGetSymbolAddress((void**)&wL, g_wL);
    cudaGetSymbolAddress((void**)&xH, g_xH);
    cudaGetSymbolAddress((void**)&xL, g_xL);
    const size_t WSZ = (size_t)EG * EG;
    const size_t XSZ = (size_t)MG * EG;
    auto whi = [&](int i) { return wH + i * WSZ; };
    auto wlo = [&](int i) { return wL + i * WSZ; };
    auto xhi = [&](int i) { return xH + i * XSZ; };
    auto xlo = [&](int i) { return xL + i * XSZ; };

    float* outA = (float*)d_out;
    float* outB = (float*)d_out + (size_t)MG * EG;

    const int GSMEM = 2 * 8 * TILE_HF * (int)sizeof(__nv_bfloat16);  // 81920
    cudaFuncSetAttribute(qc_gemm_bf16_kernel,
                         cudaFuncAttributeMaxDynamicSharedMemorySize, GSMEM);

    // ---- split weights (8 matrices) ----
    {
        SplitBatch sb = {};
        const float* srcs[8] = { q_wa, q_wb, k_wa, k_wb, v_wa, v_wb, o_wa, o_wb };
        for (int i = 0; i < 8; i++) { sb.src[i] = srcs[i]; sb.hi[i] = whi(i); sb.lo[i] = wlo(i); }
        split_kernel<<<dim3((unsigned)(WSZ / 4 / 256), 8), 256>>>(sb, (int)(WSZ / 4));
    }
    // ---- split input activations (4 tensors) ----
    {
        SplitBatch sb = {};
        const float* srcs[4] = { x_q_a, x_q_b, x_kv_a, x_kv_b };
        for (int i = 0; i < 4; i++) { sb.src[i] = srcs[i]; sb.hi[i] = xhi(i); sb.lo[i] = xlo(i); }
        split_kernel<<<dim3((unsigned)(XSZ / 4 / 256), 4), 256>>>(sb, (int)(XSZ / 4));
    }

    const dim3 gg(EG / 64, MG / 64);

    // q / k / v projections
    qc_gemm_bf16_kernel<<<gg, 256, GSMEM>>>(
        xhi(0), xlo(0), xhi(1), xlo(1), whi(0), wlo(0), whi(1), wlo(1),
        q_ba, q_bb, layer_theta, qa, qb);
    qc_gemm_bf16_kernel<<<gg, 256, GSMEM>>>(
        xhi(2), xlo(2), xhi(3), xlo(3), whi(2), wlo(2), whi(3), wlo(3),
        k_ba, k_bb, layer_theta, ka, kb);
    qc_gemm_bf16_kernel<<<gg, 256, GSMEM>>>(
        xhi(2), xlo(2), xhi(3), xlo(3), whi(4), wlo(4), whi(5), wlo(5),
        v_ba, v_bb, layer_theta, va, vb);

    // RoPE on qa,qb,ka,kb (in place)
    rope_kernel<<<(4 * MG * (EG / 2)) / 256, 256>>>();

    // tensor-core flash attention -> writes pre-split bf16 hi/lo (g_xH/L[4,5])
    attn_mma_kernel<<<dim3(SG / 128, HG, 2), 256>>>(thetas_head);

    // output projection straight into d_out (out_a then out_b)
    qc_gemm_bf16_kernel<<<gg, 256, GSMEM>>>(
        xhi(4), xlo(4), xhi(5), xlo(5), whi(6), wlo(6), whi(7), wlo(7),
        o_ba, o_bb, layer_theta, outA, outB);
}

// round 12
// speedup vs baseline: 1.2628x; 1.0229x over previous
#include <cuda_runtime.h>
#include <cuda_bf16.h>
#include <math.h>

// Problem constants
#define EG 1024      // embed dim
#define MG 2048      // B*S rows
#define SG 1024      // seq len
#define HG 16        // heads
#define DH 64        // head dim

// ---------------- scratch (device globals: no runtime allocation allowed) ----
__device__ float g_qa[MG * EG];
__device__ float g_qb[MG * EG];
__device__ float g_ka[MG * EG];
__device__ float g_kb[MG * EG];
__device__ float g_va[MG * EG];
__device__ float g_vb[MG * EG];

// pre-split bf16 hi/lo buffers
// weights: 0 q_wa, 1 q_wb, 2 k_wa, 3 k_wb, 4 v_wa, 5 v_wb, 6 o_wa, 7 o_wb
__device__ __nv_bfloat16 g_wH[8][EG * EG];
__device__ __nv_bfloat16 g_wL[8][EG * EG];
// activations: 0 x_q_a, 1 x_q_b, 2 x_kv_a, 3 x_kv_b, 4 oa, 5 ob
__device__ __nv_bfloat16 g_xH[6][MG * EG];
__device__ __nv_bfloat16 g_xL[6][MG * EG];

// attention pre-split buffers (post-rope K, j2h folded; V transposed [b,h,d,s])
__device__ __nv_bfloat16 g_kaH[MG * EG], g_kaL[MG * EG];
__device__ __nv_bfloat16 g_kbH[MG * EG], g_kbL[MG * EG];
__device__ __nv_bfloat16 g_kjH[MG * EG], g_kjL[MG * EG];
__device__ __nv_bfloat16 g_vaTH[MG * EG], g_vaTL[MG * EG];
__device__ __nv_bfloat16 g_vbTH[MG * EG], g_vbTL[MG * EG];

// ---------------------------------------------------------------------------
// helpers
// ---------------------------------------------------------------------------
__device__ __forceinline__ void mma_bf16(float* c, const unsigned* a, const unsigned* b)
{
    asm volatile(
        "mma.sync.aligned.m16n8k16.row.col.f32.bf16.bf16.f32 "
        "{%0,%1,%2,%3}, {%4,%5,%6,%7}, {%8,%9}, {%0,%1,%2,%3};"
        : "+f"(c[0]), "+f"(c[1]), "+f"(c[2]), "+f"(c[3])
        : "r"(a[0]), "r"(a[1]), "r"(a[2]), "r"(a[3]),
          "r"(b[0]), "r"(b[1]));
}

__device__ __forceinline__ void ldsm_x4(unsigned* r, const __nv_bfloat16* p)
{
    unsigned addr = (unsigned)__cvta_generic_to_shared(p);
    asm volatile("ldmatrix.sync.aligned.m8n8.x4.shared.b16 {%0,%1,%2,%3}, [%4];"
                 : "=r"(r[0]), "=r"(r[1]), "=r"(r[2]), "=r"(r[3]) : "r"(addr));
}

__device__ __forceinline__ unsigned pack_hi2(float x, float y)
{
    __nv_bfloat162 h(__float2bfloat16(x), __float2bfloat16(y));
    return *reinterpret_cast<unsigned*>(&h);
}
__device__ __forceinline__ unsigned pack_lo2(float x, float y)
{
    float hx = __bfloat162float(__float2bfloat16(x));
    float hy = __bfloat162float(__float2bfloat16(y));
    __nv_bfloat162 l(__float2bfloat16(x - hx), __float2bfloat16(y - hy));
    return *reinterpret_cast<unsigned*>(&l);
}

__device__ __forceinline__ void cp_async16(unsigned daddr, const void* src)
{
    asm volatile("cp.async.cg.shared.global [%0], [%1], 16;" :: "r"(daddr), "l"(src));
}
__device__ __forceinline__ void cp_commit()
{
    asm volatile("cp.async.commit_group;");
}
template<int N>
__device__ __forceinline__ void cp_wait()
{
    asm volatile("cp.async.wait_group %0;" :: "n"(N));
}

// smem tile strides (bf16 halfword units). BK=32 + pad 8 -> conflict-free frags.
#define TSTR 40
#define TILE_HF (64 * TSTR)

// load B fragment (k16 x n8, col layout == W[n][k] row-major) from [n][stride]
template<int STRIDE>
__device__ __forceinline__ void load_bfragS(
    unsigned* b, const __nv_bfloat16* s, int nbase, int sk, int g, int t)
{
    const int r = (nbase + g) * STRIDE + sk + 2 * t;
    b[0] = *reinterpret_cast<const unsigned*>(&s[r]);
    b[1] = *reinterpret_cast<const unsigned*>(&s[r + 8]);
}

// ---------------------------------------------------------------------------
// Batched fp32 -> bf16 hi/lo split. blockIdx.y selects the tensor.
// ---------------------------------------------------------------------------
struct SplitBatch {
    const float* src[8];
    __nv_bfloat16* hi[8];
    __nv_bfloat16* lo[8];
};

__global__ __launch_bounds__(256) void split_kernel(SplitBatch sb, int nvec)
{
    const int t = blockIdx.x * 256 + threadIdx.x;
    if (t >= nvec) return;
    const int w = blockIdx.y;
    const float4 v = reinterpret_cast<const float4*>(sb.src[w])[t];

    unsigned h0 = pack_hi2(v.x, v.y);
    unsigned h1 = pack_hi2(v.z, v.w);
    unsigned l0 = pack_lo2(v.x, v.y);
    unsigned l1 = pack_lo2(v.z, v.w);

    reinterpret_cast<uint2*>(sb.hi[w])[t] = make_uint2(h0, h1);
    reinterpret_cast<uint2*>(sb.lo[w])[t] = make_uint2(l0, l1);
}

// ---------------------------------------------------------------------------
// prep_k: post-rope K -> bf16 hi/lo (ka, kb, kj = j2h(h)*kb), same layout.
// One thread per 4 contiguous columns. MG*EG/4 threads.
// ---------------------------------------------------------------------------
__global__ __launch_bounds__(256) void prep_k_kernel(const float* __restrict__ thetas_head)
{
    const int t = blockIdx.x * 256 + threadIdx.x;     // 0 .. MG*EG/4-1
    const int row = t >> 8;                           // EG/4 = 256 groups/row
    const int c4  = (t & 255) << 2;
    const int h   = c4 >> 6;
    const float j2h = sinf(2.0f * thetas_head[h]) - 1.0f;

    const size_t off = (size_t)row * EG + c4;
    float4 ka = *(const float4*)&g_ka[off];
    float4 kb = *(const float4*)&g_kb[off];
    float4 kj = { j2h * kb.x, j2h * kb.y, j2h * kb.z, j2h * kb.w };

    *(uint2*)&g_kaH[off] = make_uint2(pack_hi2(ka.x, ka.y), pack_hi2(ka.z, ka.w));
    *(uint2*)&g_kaL[off] = make_uint2(pack_lo2(ka.x, ka.y), pack_lo2(ka.z, ka.w));
    *(uint2*)&g_kbH[off] = make_uint2(pack_hi2(kb.x, kb.y), pack_hi2(kb.z, kb.w));
    *(uint2*)&g_kbL[off] = make_uint2(pack_lo2(kb.x, kb.y), pack_lo2(kb.z, kb.w));
    *(uint2*)&g_kjH[off] = make_uint2(pack_hi2(kj.x, kj.y), pack_hi2(kj.z, kj.w));
    *(uint2*)&g_kjL[off] = make_uint2(pack_lo2(kj.x, kj.y), pack_lo2(kj.z, kj.w));
}

// ---------------------------------------------------------------------------
// prep_v: V -> bf16 hi/lo TRANSPOSED to [b,h,d,s] (s contiguous).
// One thread per 4 consecutive s for one (b,h,d). MG*EG/4 threads.
// ---------------------------------------------------------------------------
__global__ __launch_bounds__(256) void prep_v_kernel()
{
    const int t = blockIdx.x * 256 + threadIdx.x;     // 0 .. MG*EG/4-1
    const int bhd = t >> 8;                           // SG/4 = 256 groups
    const int s4  = (t & 255) << 2;
    const int b   = bhd >> 10;                        // HG*DH = 1024
    const int hd  = bhd & 1023;

    const size_t ib = ((size_t)b * SG + s4) * EG + hd;
    float a0 = g_va[ib], a1 = g_va[ib + EG], a2 = g_va[ib + 2 * EG], a3 = g_va[ib + 3 * EG];
    float b0 = g_vb[ib], b1 = g_vb[ib + EG], b2 = g_vb[ib + 2 * EG], b3 = g_vb[ib + 3 * EG];

    const size_t ob = (size_t)bhd * SG + s4;
    *(uint2*)&g_vaTH[ob] = make_uint2(pack_hi2(a0, a1), pack_hi2(a2, a3));
    *(uint2*)&g_vaTL[ob] = make_uint2(pack_lo2(a0, a1), pack_lo2(a2, a3));
    *(uint2*)&g_vbTH[ob] = make_uint2(pack_hi2(b0, b1), pack_hi2(b2, b3));
    *(uint2*)&g_vbTL[ob] = make_uint2(pack_lo2(b0, b1), pack_lo2(b2, b3));
}

// ---------------------------------------------------------------------------
// Fused quaternion-complex dense on tensor cores, pre-split bf16 inputs,
// cp.async double-buffered mainloop, ldmatrix fragment loads.
//   outA = Xa.Wa^T + j2 * Xb.Wb^T + ba ;  outB = Xa.Wb^T + Xb.Wa^T + bb
// 64x64 CTA tile, BK=32, 256 threads = 8 warps (4x2), warp tile 16x32.
// __launch_bounds__(256, 2): cap regs at 128 so 2 CTAs/SM always fit.
// MMA block interleaved across the two `half` accumulator sets so
// same-accumulator ops are >=2 apart (shorter HMMA RAW chains).
// ---------------------------------------------------------------------------
__global__ __launch_bounds__(256, 2) void qc_gemm_bf16_kernel(
    const __nv_bfloat16* __restrict__ xaH, const __nv_bfloat16* __restrict__ xaL,
    const __nv_bfloat16* __restrict__ xbH, const __nv_bfloat16* __restrict__ xbL,
    const __nv_bfloat16* __restrict__ waH, const __nv_bfloat16* __restrict__ waL,
    const __nv_bfloat16* __restrict__ wbH, const __nv_bfloat16* __restrict__ wbL,
    const float* __restrict__ ba, const float* __restrict__ bb,
    const float* __restrict__ theta_ptr,
    float* __restrict__ outA, float* __restrict__ outB)
{
    extern __shared__ __nv_bfloat16 sbuf[];

    const int tid = threadIdx.x;
    const int lane = tid & 31;
    const int wid = tid >> 5;
    const int warp_m = wid >> 1;
    const int warp_n = wid & 1;
    const int g = lane >> 2;
    const int t = lane & 3;

    const int m0 = blockIdx.y * 64;
    const int n0 = blockIdx.x * 64;

    const float j2 = sinf(2.0f * theta_ptr[0]) - 1.0f;

    // ldmatrix per-lane offsets (within a [rows][TSTR] tile, before +sk)
    const int aoff = (warp_m * 16 + (lane & 15)) * TSTR + ((lane >> 4) << 3);
    const int boff = ((lane & 7) + ((lane & 16) >> 1)) * TSTR + (((lane >> 3) & 1) << 3);

    // loader mapping: full 4096B tile coverage, 16B-aligned chunks
    const int losel = tid >> 7;           // 0 hi, 1 lo
    const int tt    = tid & 127;
    const int lr0   = tt >> 2;            // rows 0..31 (chunk j=0)
    const int lc0   = (tt & 3) << 3;      // cols 0,8,16,24 (elements)

    const __nv_bfloat16* sxa = (losel ? xaL : xaH) + (size_t)(m0 + lr0) * EG + lc0;
    const __nv_bfloat16* sxb = (losel ? xbL : xbH) + (size_t)(m0 + lr0) * EG + lc0;
    const __nv_bfloat16* swa = (losel ? waL : waH) + (size_t)(n0 + lr0) * EG + lc0;
    const __nv_bfloat16* swb = (losel ? wbL : wbH) + (size_t)(n0 + lr0) * EG + lc0;
    const size_t GROW = (size_t)32 * EG;  // +32 rows in gmem

    const int doff0 = lr0 * TSTR + lc0;
    const int doff1 = doff0 + 32 * TSTR;
    unsigned dxa[2][2], dxb[2][2], dwa[2][2], dwb[2][2];
    #pragma unroll
    for (int st = 0; st < 2; st++) {
        __nv_bfloat16* base = sbuf + st * 8 * TILE_HF;
        __nv_bfloat16* bxa = base + (0 + losel) * TILE_HF;
        __nv_bfloat16* bxb = base + (2 + losel) * TILE_HF;
        __nv_bfloat16* bwa = base + (4 + losel) * TILE_HF;
        __nv_bfloat16* bwb = base + (6 + losel) * TILE_HF;
        dxa[st][0] = (unsigned)__cvta_generic_to_shared(bxa + doff0);
        dxa[st][1] = (unsigned)__cvta_generic_to_shared(bxa + doff1);
        dxb[st][0] = (unsigned)__cvta_generic_to_shared(bxb + doff0);
        dxb[st][1] = (unsigned)__cvta_generic_to_shared(bxb + doff1);
        dwa[st][0] = (unsigned)__cvta_generic_to_shared(bwa + doff0);
        dwa[st][1] = (unsigned)__cvta_generic_to_shared(bwa + doff1);
        dwb[st][0] = (unsigned)__cvta_generic_to_shared(bwb + doff0);
        dwb[st][1] = (unsigned)__cvta_generic_to_shared(bwb + doff1);
    }

    float accA1[4][4] = {};
    float accA2[4][4] = {};
    float accB [4][4] = {};

    // prologue: stage 0, k0 = 0
    cp_async16(dxa[0][0], sxa);          cp_async16(dxa[0][1], sxa + GROW);
    cp_async16(dxb[0][0], sxb);          cp_async16(dxb[0][1], sxb + GROW);
    cp_async16(dwa[0][0], swa);          cp_async16(dwa[0][1], swa + GROW);
    cp_async16(dwb[0][0], swb);          cp_async16(dwb[0][1], swb + GROW);
    cp_commit();

    const int NIT = EG / 32;
    for (int it = 0; it < NIT; it++) {
        const int cur = it & 1;
        if (it + 1 < NIT) {
            const int nk = (it + 1) * 32;
            const int ns = 1 - cur;
            cp_async16(dxa[ns][0], sxa + nk);   cp_async16(dxa[ns][1], sxa + nk + GROW);
            cp_async16(dxb[ns][0], sxb + nk);   cp_async16(dxb[ns][1], sxb + nk + GROW);
            cp_async16(dwa[ns][0], swa + nk);   cp_async16(dwa[ns][1], swa + nk + GROW);
            cp_async16(dwb[ns][0], swb + nk);   cp_async16(dwb[ns][1], swb + nk + GROW);
            cp_commit();
            cp_wait<1>();
        } else {
            cp_wait<0>();
        }
        __syncthreads();

        const __nv_bfloat16* cb = sbuf + cur * 8 * TILE_HF;
        const __nv_bfloat16* sXaH = cb + 0 * TILE_HF;
        const __nv_bfloat16* sXaL = cb + 1 * TILE_HF;
        const __nv_bfloat16* sXbH = cb + 2 * TILE_HF;
        const __nv_bfloat16* sXbL = cb + 3 * TILE_HF;
        const __nv_bfloat16* sWaH = cb + 4 * TILE_HF;
        const __nv_bfloat16* sWaL = cb + 5 * TILE_HF;
        const __nv_bfloat16* sWbH = cb + 6 * TILE_HF;
        const __nv_bfloat16* sWbL = cb + 7 * TILE_HF;

        #pragma unroll
        for (int ks = 0; ks < 2; ks++) {
            const int sk = ks * 16;
            unsigned aXaH[4], aXaL[4], aXbH[4], aXbL[4];
            ldsm_x4(aXaH, sXaH + aoff + sk);
            ldsm_x4(aXaL, sXaL + aoff + sk);
            ldsm_x4(aXbH, sXbH + aoff + sk);
            ldsm_x4(aXbL, sXbL + aoff + sk);

            #pragma unroll
            for (int fp = 0; fp < 2; fp++) {
                const int bo = (warp_n * 32 + fp * 16) * TSTR + boff + sk;
                unsigned bWaH[4], bWaL[4], bWbH[4], bWbL[4];
                ldsm_x4(bWaH, sWaH + bo);
                ldsm_x4(bWaL, sWaL + bo);
                ldsm_x4(bWbH, sWbH + bo);
                ldsm_x4(bWbL, sWbL + bo);

                const int f0 = fp * 2, f1 = fp * 2 + 1;
                // term H*H
                mma_bf16(accA1[f0], aXaH, bWaH + 0);  mma_bf16(accA1[f1], aXaH, bWaH + 2);
                mma_bf16(accA2[f0], aXbH, bWbH + 0);  mma_bf16(accA2[f1], aXbH, bWbH + 2);
                mma_bf16(accB [f0], aXaH, bWbH + 0);  mma_bf16(accB [f1], aXaH, bWbH + 2);
                // term H*L
                mma_bf16(accA1[f0], aXaH, bWaL + 0);  mma_bf16(accA1[f1], aXaH, bWaL + 2);
                mma_bf16(accA2[f0], aXbH, bWbL + 0);  mma_bf16(accA2[f1], aXbH, bWbL + 2);
                mma_bf16(accB [f0], aXbH, bWaH + 0);  mma_bf16(accB [f1], aXbH, bWaH + 2);
                // term L*H
                mma_bf16(accA1[f0], aXaL, bWaH + 0);  mma_bf16(accA1[f1], aXaL, bWaH + 2);
                mma_bf16(accA2[f0], aXbL, bWbH + 0);  mma_bf16(accA2[f1], aXbL, bWbH + 2);
                mma_bf16(accB [f0], aXaH, bWbL + 0);  mma_bf16(accB [f1], aXaH, bWbL + 2);
                // remaining B terms
                mma_bf16(accB [f0], aXbH, bWaL + 0);  mma_bf16(accB [f1], aXbH, bWaL + 2);
                mma_bf16(accB [f0], aXaL, bWbH + 0);  mma_bf16(accB [f1], aXaL, bWbH + 2);
                mma_bf16(accB [f0], aXbL, bWaH + 0);  mma_bf16(accB [f1], aXbL, bWaH + 2);
            }
        }
        __syncthreads();   // compute done before this stage is refilled
    }

    #pragma unroll
    for (int f = 0; f < 4; f++) {
        const int n = n0 + warp_n * 32 + f * 8 + 2 * t;
        const int r0 = m0 + warp_m * 16 + g;
        const int r1 = r0 + 8;
        const float ba0 = ba[n], ba1 = ba[n + 1];
        const float bb0 = bb[n], bb1 = bb[n + 1];

        float2 oa0 = { accA1[f][0] + j2 * accA2[f][0] + ba0,
                       accA1[f][1] + j2 * accA2[f][1] + ba1 };
        float2 oa1 = { accA1[f][2] + j2 * accA2[f][2] + ba0,
                       accA1[f][3] + j2 * accA2[f][3] + ba1 };
        float2 ob0 = { accB[f][0] + bb0, accB[f][1] + bb1 };
        float2 ob1 = { accB[f][2] + bb0, accB[f][3] + bb1 };

        *(float2*)&outA[r0 * EG + n] = oa0;
        *(float2*)&outA[r1 * EG + n] = oa1;
        *(float2*)&outB[r0 * EG + n] = ob0;
        *(float2*)&outB[r1 * EG + n] = ob1;
    }
}

// ---------------------------------------------------------------------------
// RoPE applied in place to g_qa, g_qb, g_ka, g_kb (fp32 throughout).
// ---------------------------------------------------------------------------
__global__ __launch_bounds__(256) void rope_kernel()
{
    const int PAIRS = MG * (EG / 2);
    int tt = blockIdx.x * blockDim.x + threadIdx.x;
    if (tt >= 4 * PAIRS) return;

    const int w = tt / PAIRS;
    const int p = tt % PAIRS;
    float* X = (w == 0) ? g_qa : (w == 1) ? g_qb : (w == 2) ? g_ka : g_kb;

    const int row = p >> 9;
    const int pp  = p & 511;
    const int h   = pp >> 5;
    const int i   = pp & 31;
    const int s   = row & (SG - 1);

    const float freq = exp2f(-(float)i * (13.287712379549449f / 32.0f));
    float sn, cs;
    sincosf((float)s * freq, &sn, &cs);

    const int base = row * EG + h * DH + i;
    const float x1 = X[base];
    const float x2 = X[base + 32];
    X[base]      = x1 * cs - x2 * sn;
    X[base + 32] = x2 * cs + x1 * sn;
}

// ---------------------------------------------------------------------------
// Tensor-core flash attention with complex-magnitude scores, bf16 hi/lo split.
// Producers are now pure copies from pre-split global buffers (prep_k/prep_v).
// ---------------------------------------------------------------------------
#define KSTR 72
#define VSTR 40

__global__ __launch_bounds__(256) void attn_mma_kernel(const float* __restrict__ thetas_head)
{
    __shared__ __nv_bfloat16 sKaH[32 * KSTR], sKaL[32 * KSTR];
    __shared__ __nv_bfloat16 sKbH[32 * KSTR], sKbL[32 * KSTR];
    __shared__ __nv_bfloat16 sKjH[32 * KSTR], sKjL[32 * KSTR];
    __shared__ __nv_bfloat16 sVaH[64 * VSTR], sVaL[64 * VSTR];
    __shared__ __nv_bfloat16 sVbH[64 * VSTR], sVbL[64 * VSTR];

    const int b   = blockIdx.z;
    const int h   = blockIdx.y;
    const int r0  = blockIdx.x * 128;
    const int tid = threadIdx.x;
    const int lane = tid & 31;
    const int wid  = tid >> 5;
    const int g = lane >> 2;
    const int t = lane & 3;

    unsigned qaH[4][4], qaL[4][4], qbH[4][4], qbL[4][4];
    {
        const int row0 = r0 + wid * 16 + g;
        const int base0 = (b * SG + row0) * EG + h * DH;
        const int base1 = base0 + 8 * EG;
        #pragma unroll
        for (int ks = 0; ks < 4; ks++) {
            const int col = ks * 16 + 2 * t;
            float2 a0 = *(const float2*)&g_qa[base0 + col];
            float2 a1 = *(const float2*)&g_qa[base1 + col];
            float2 a2 = *(const float2*)&g_qa[base0 + col + 8];
            float2 a3 = *(const float2*)&g_qa[base1 + col + 8];
            qaH[ks][0] = pack_hi2(a0.x, a0.y); qaL[ks][0] = pack_lo2(a0.x, a0.y);
            qaH[ks][1] = pack_hi2(a1.x, a1.y); qaL[ks][1] = pack_lo2(a1.x, a1.y);
            qaH[ks][2] = pack_hi2(a2.x, a2.y); qaL[ks][2] = pack_lo2(a2.x, a2.y);
            qaH[ks][3] = pack_hi2(a3.x, a3.y); qaL[ks][3] = pack_lo2(a3.x, a3.y);
            float2 b0 = *(const float2*)&g_qb[base0 + col];
            float2 b1 = *(const float2*)&g_qb[base1 + col];
            float2 b2 = *(const float2*)&g_qb[base0 + col + 8];
            float2 b3 = *(const float2*)&g_qb[base1 + col + 8];
            qbH[ks][0] = pack_hi2(b0.x, b0.y); qbL[ks][0] = pack_lo2(b0.x, b0.y);
            qbH[ks][1] = pack_hi2(b1.x, b1.y); qbL[ks][1] = pack_lo2(b1.x, b1.y);
            qbH[ks][2] = pack_hi2(b2.x, b2.y); qbL[ks][2] = pack_lo2(b2.x, b2.y);
            qbH[ks][3] = pack_hi2(b3.x, b3.y); qbL[ks][3] = pack_lo2(b3.x, b3.y);
        }
    }

    float oa[8][4] = {};
    float ob[8][4] = {};
    float mrow0 = -1e30f, mrow1 = -1e30f;
    float lrow0 = 0.0f,   lrow1 = 0.0f;

    const int ntiles = (r0 >> 5) + 4;
    for (int tile = 0; tile < ntiles; tile++) {
        const int k0 = tile * 32;

        __syncthreads();

        // ---- K producer: pure uint2 copies from pre-split globals ----
        #pragma unroll
        for (int it = 0; it < 2; it++) {
            const int idx = tid + it * 256;           // 0..511
            const int n  = idx >> 4;                  // key 0..31
            const int d4 = (idx & 15) << 2;           // dim 0,4,..,60
            const size_t ga = (size_t)(b * SG + k0 + n) * EG + h * DH + d4;
            const int si = n * KSTR + d4;
            *(uint2*)&sKaH[si] = *(const uint2*)&g_kaH[ga];
            *(uint2*)&sKaL[si] = *(const uint2*)&g_kaL[ga];
            *(uint2*)&sKbH[si] = *(const uint2*)&g_kbH[ga];
            *(uint2*)&sKbL[si] = *(const uint2*)&g_kbL[ga];
            *(uint2*)&sKjH[si] = *(const uint2*)&g_kjH[ga];
            *(uint2*)&sKjL[si] = *(const uint2*)&g_kjL[ga];
        }
        // ---- V producer: copies from pre-transposed [b,h,d,s] globals ----
        #pragma unroll
        for (int it = 0; it < 2; it++) {
            const int idx = tid + it * 256;           // 0..511
            const int d  = idx >> 3;                  // 0..63
            const int s4 = (idx & 7) << 2;            // 0,4,..,28
            const size_t ga = ((size_t)(b * HG + h) * DH + d) * SG + k0 + s4;
            const int si = d * VSTR + s4;
            *(uint2*)&sVaH[si] = *(const uint2*)&g_vaTH[ga];
            *(uint2*)&sVaL[si] = *(const uint2*)&g_vaTL[ga];
            *(uint2*)&sVbH[si] = *(const uint2*)&g_vbTH[ga];
            *(uint2*)&sVbL[si] = *(const uint2*)&g_vbTL[ga];
        }
        __syncthreads();

        const int wrow = r0 + wid * 16;
        if (k0 > wrow + 15) continue;

        float sa[4][4] = {};
        float sb[4][4] = {};
        #pragma unroll
        for (int ks = 0; ks < 4; ks++) {
            const int sk = ks * 16;
            #pragma unroll
            for (int nf = 0; nf < 4; nf++) {
                const int nb = nf * 8;
                unsigned kaH[2], kaL[2], kbH[2], kbL[2], kjH[2], kjL[2];
                load_bfragS<KSTR>(kaH, sKaH, nb, sk, g, t);
                load_bfragS<KSTR>(kaL, sKaL, nb, sk, g, t);
                load_bfragS<KSTR>(kbH, sKbH, nb, sk, g, t);
                load_bfragS<KSTR>(kbL, sKbL, nb, sk, g, t);
                load_bfragS<KSTR>(kjH, sKjH, nb, sk, g, t);
                load_bfragS<KSTR>(kjL, sKjL, nb, sk, g, t);

                mma_bf16(sa[nf], qaH[ks], kaH);
                mma_bf16(sb[nf], qaH[ks], kbH);
                mma_bf16(sa[nf], qaH[ks], kaL);
                mma_bf16(sb[nf], qaH[ks], kbL);
                mma_bf16(sa[nf], qaL[ks], kaH);
                mma_bf16(sb[nf], qaL[ks], kbH);
                mma_bf16(sa[nf], qbH[ks], kjH);
                mma_bf16(sb[nf], qbH[ks], kaH);
                mma_bf16(sa[nf], qbH[ks], kjL);
                mma_bf16(sb[nf], qbH[ks], kaL);
                mma_bf16(sa[nf], qbL[ks], kjH);
                mma_bf16(sb[nf], qbL[ks], kaH);
            }
        }

        const bool full = (k0 + 31 <= wrow);
        float mt0 = -1e30f, mt1 = -1e30f;
        #pragma unroll
        for (int nf = 0; nf < 4; nf++) {
            #pragma unroll
            for (int c = 0; c < 4; c++) {
                float v = sqrtf(sa[nf][c] * sa[nf][c] + sb[nf][c] * sb[nf][c] + 1e-8f) * 0.125f;
                if (!full) {
                    const int col = k0 + nf * 8 + 2 * t + (c & 1);
                    const int row = wrow + g + ((c & 2) ? 8 : 0);
                    if (col > row) v = -1e9f;
                }
                sa[nf][c] = v;
                if (c & 2) mt1 = fmaxf(mt1, v); else mt0 = fmaxf(mt0, v);
            }
        }
        mt0 = fmaxf(mt0, __shfl_xor_sync(0xffffffffu, mt0, 1));
        mt0 = fmaxf(mt0, __shfl_xor_sync(0xffffffffu, mt0, 2));
        mt1 = fmaxf(mt1, __shfl_xor_sync(0xffffffffu, mt1, 1));
        mt1 = fmaxf(mt1, __shfl_xor_sync(0xffffffffu, mt1, 2));

        const float mn0 = fmaxf(mrow0, mt0);
        const float mn1 = fmaxf(mrow1, mt1);

        float ps0 = 0.0f, ps1 = 0.0f;
        #pragma unroll
        for (int nf = 0; nf < 4; nf++) {
            #pragma unroll
            for (int c = 0; c < 4; c++) {
                const float p = __expf(sa[nf][c] - ((c & 2) ? mn1 : mn0));
                sa[nf][c] = p;
                if (c & 2) ps1 += p; else ps0 += p;
            }
        }
        ps0 += __shfl_xor_sync(0xffffffffu, ps0, 1);
        ps0 += __shfl_xor_sync(0xffffffffu, ps0, 2);
        ps1 += __shfl_xor_sync(0xffffffffu, ps1, 1);
        ps1 += __shfl_xor_sync(0xffffffffu, ps1, 2);

        const float sc0 = __expf(mrow0 - mn0);
        const float sc1 = __expf(mrow1 - mn1);
        lrow0 = lrow0 * sc0 + ps0;  mrow0 = mn0;
        lrow1 = lrow1 * sc1 + ps1;  mrow1 = mn1;
        #pragma unroll
        for (int nf = 0; nf < 8; nf++) {
            oa[nf][0] *= sc0; oa[nf][1] *= sc0; oa[nf][2] *= sc1; oa[nf][3] *= sc1;
            ob[nf][0] *= sc0; ob[nf][1] *= sc0; ob[nf][2] *= sc1; ob[nf][3] *= sc1;
        }

        unsigned pH[2][4], pL[2][4];
        #pragma unroll
        for (int kc = 0; kc < 2; kc++) {
            const int f = 2 * kc;
            pH[kc][0] = pack_hi2(sa[f][0],     sa[f][1]);
            pL[kc][0] = pack_lo2(sa[f][0],     sa[f][1]);
            pH[kc][1] = pack_hi2(sa[f][2],     sa[f][3]);
            pL[kc][1] = pack_lo2(sa[f][2],     sa[f][3]);
            pH[kc][2] = pack_hi2(sa[f + 1][0], sa[f + 1][1]);
            pL[kc][2] = pack_lo2(sa[f + 1][0], sa[f + 1][1]);
            pH[kc][3] = pack_hi2(sa[f + 1][2], sa[f + 1][3]);
            pL[kc][3] = pack_lo2(sa[f + 1][2], sa[f + 1][3]);
        }

        #pragma unroll
        for (int nf = 0; nf < 8; nf++) {
            const int nb = nf * 8;
            #pragma unroll
            for (int kc = 0; kc < 2; kc++) {
                const int sk = kc * 16;
                unsigned vaH[2], vaL[2], vbH[2], vbL[2];
                load_bfragS<VSTR>(vaH, sVaH, nb, sk, g, t);
                load_bfragS<VSTR>(vaL, sVaL, nb, sk, g, t);
                load_bfragS<VSTR>(vbH, sVbH, nb, sk, g, t);
                load_bfragS<VSTR>(vbL, sVbL, nb, sk, g, t);

                mma_bf16(oa[nf], pH[kc], vaH);
                mma_bf16(ob[nf], pH[kc], vbH);
                mma_bf16(oa[nf], pL[kc], vaH);
                mma_bf16(ob[nf], pL[kc], vbH);
                mma_bf16(oa[nf], pH[kc], vaL);
                mma_bf16(ob[nf], pH[kc], vbL);
            }
        }
    }

    // epilogue: write bf16 hi/lo directly (identical split of the fp32 value)
    const float inv0 = 1.0f / lrow0;
    const float inv1 = 1.0f / lrow1;
    const int row0 = r0 + wid * 16 + g;
    const int base0 = (b * SG + row0) * EG + h * DH;
    const int base1 = base0 + 8 * EG;
    __nv_bfloat16* xh4 = g_xH[4];  __nv_bfloat16* xl4 = g_xL[4];
    __nv_bfloat16* xh5 = g_xH[5];  __nv_bfloat16* xl5 = g_xL[5];
    #pragma unroll
    for (int nf = 0; nf < 8; nf++) {
        const int d = nf * 8 + 2 * t;
        float a00 = oa[nf][0] * inv0, a01 = oa[nf][1] * inv0;
        float a10 = oa[nf][2] * inv1, a11 = oa[nf][3] * inv1;
        float b00 = ob[nf][0] * inv0, b01 = ob[nf][1] * inv0;
        float b10 = ob[nf][2] * inv1, b11 = ob[nf][3] * inv1;
        *(unsigned*)&xh4[base0 + d] = pack_hi2(a00, a01);
        *(unsigned*)&xl4[base0 + d] = pack_lo2(a00, a01);
        *(unsigned*)&xh4[base1 + d] = pack_hi2(a10, a11);
        *(unsigned*)&xl4[base1 + d] = pack_lo2(a10, a11);
        *(unsigned*)&xh5[base0 + d] = pack_hi2(b00, b01);
        *(unsigned*)&xl5[base0 + d] = pack_lo2(b00, b01);
        *(unsigned*)&xh5[base1 + d] = pack_hi2(b10, b11);
        *(unsigned*)&xl5[base1 + d] = pack_lo2(b10, b11);
    }
    (void)thetas_head;
}

// ---------------------------------------------------------------------------
extern "C" void kernel_launch(void* const* d_in, const int* in_sizes, int n_in,
                              void* d_out, int out_size)
{
    const float* x_q_a  = (const float*)d_in[0];
    const float* x_q_b  = (const float*)d_in[1];
    const float* x_kv_a = (const float*)d_in[2];
    const float* x_kv_b = (const float*)d_in[3];
    // d_in[4] = mask -- causal, encoded in the attention kernel
    const float* layer_theta = (const float*)d_in[5];
    const float* thetas_head = (const float*)d_in[6];
    const float* q_wa = (const float*)d_in[7];
    const float* q_wb = (const float*)d_in[8];
    const float* q_ba = (const float*)d_in[9];
    const float* q_bb = (const float*)d_in[10];
    const float* k_wa = (const float*)d_in[11];
    const float* k_wb = (const float*)d_in[12];
    const float* k_ba = (const float*)d_in[13];
    const float* k_bb = (const float*)d_in[14];
    const float* v_wa = (const float*)d_in[15];
    const float* v_wb = (const float*)d_in[16];
    const float* v_ba = (const float*)d_in[17];
    const float* v_bb = (const float*)d_in[18];
    const float* o_wa = (const float*)d_in[19];
    const float* o_wb = (const float*)d_in[20];
    const float* o_ba = (const float*)d_in[21];
    const float* o_bb = (const float*)d_in[22];

    float *qa, *qb, *ka, *kb, *va, *vb;
    cudaGetSymbolAddress((void**)&qa, g_qa);
    cudaGetSymbolAddress((void**)&qb, g_qb);
    cudaGetSymbolAddress((void**)&ka, g_ka);
    cudaGetSymbolAddress((void**)&kb, g_kb);
    cudaGetSymbolAddress((void**)&va, g_va);
    cudaGetSymbolAddress((void**)&vb, g_vb);

    __nv_bfloat16 *wH, *wL, *xH, *xL;
    cudaGetSymbolAddress((void**)&wH, g_wH);
    cudaGetSymbolAddress((void**)&wL, g_wL);
    cudaGetSymbolAddress((void**)&xH, g_xH);
    cudaGetSymbolAddress((void**)&xL, g_xL);
    const size_t WSZ = (size_t)EG * EG;
    const size_t XSZ = (size_t)MG * EG;
    auto whi = [&](int i) { return wH + i * WSZ; };
    auto wlo = [&](int i) { return wL + i * WSZ; };
    auto xhi = [&](int i) { return xH + i * XSZ; };
    auto xlo = [&](int i) { return xL + i * XSZ; };

    float* outA = (float*)d_out;
    float* outB = (float*)d_out + (size_t)MG * EG;

    const int GSMEM = 2 * 8 * TILE_HF * (int)sizeof(__nv_bfloat16);  // 81920
    cudaFuncSetAttribute(qc_gemm_bf16_kernel,
                         cudaFuncAttributeMaxDynamicSharedMemorySize, GSMEM);

    // ---- split weights (8 matrices) ----
    {
        SplitBatch sb = {};
        const float* srcs[8] = { q_wa, q_wb, k_wa, k_wb, v_wa, v_wb, o_wa, o_wb };
        for (int i = 0; i < 8; i++) { sb.src[i] = srcs[i]; sb.hi[i] = whi(i); sb.lo[i] = wlo(i); }
        split_kernel<<<dim3((unsigned)(WSZ / 4 / 256), 8), 256>>>(sb, (int)(WSZ / 4));
    }
    // ---- split input activations (4 tensors) ----
    {
        SplitBatch sb = {};
        const float* srcs[4] = { x_q_a, x_q_b, x_kv_a, x_kv_b };
        for (int i = 0; i < 4; i++) { sb.src[i] = srcs[i]; sb.hi[i] = xhi(i); sb.lo[i] = xlo(i); }
        split_kernel<<<dim3((unsigned)(XSZ / 4 / 256), 4), 256>>>(sb, (int)(XSZ / 4));
    }

    const dim3 gg(EG / 64, MG / 64);

    // q / k / v projections
    qc_gemm_bf16_kernel<<<gg, 256, GSMEM>>>(
        xhi(0), xlo(0), xhi(1), xlo(1), whi(0), wlo(0), whi(1), wlo(1),
        q_ba, q_bb, layer_theta, qa, qb);
    qc_gemm_bf16_kernel<<<gg, 256, GSMEM>>>(
        xhi(2), xlo(2), xhi(3), xlo(3), whi(2), wlo(2), whi(3), wlo(3),
        k_ba, k_bb, layer_theta, ka, kb);
    qc_gemm_bf16_kernel<<<gg, 256, GSMEM>>>(
        xhi(2), xlo(2), xhi(3), xlo(3), whi(4), wlo(4), whi(5), wlo(5),
        v_ba, v_bb, layer_theta, va, vb);

    // RoPE on qa,qb,ka,kb (in place)
    rope_kernel<<<(4 * MG * (EG / 2)) / 256, 256>>>();

    // pre-split K (post-rope, j2h folded) and V (transposed) to bf16 hi/lo
    prep_k_kernel<<<(MG * EG / 4) / 256, 256>>>(thetas_head);
    prep_v_kernel<<<(MG * EG / 4) / 256, 256>>>();

    // tensor-core flash attention -> writes pre-split bf16 hi/lo (g_xH/L[4,5])
    attn_mma_kernel<<<dim3(SG / 128, HG, 2), 256>>>(thetas_head);

    // output projection straight into d_out (out_a then out_b)
    qc_gemm_bf16_kernel<<<gg, 256, GSMEM>>>(
        xhi(4), xlo(4), xhi(5), xlo(5), whi(6), wlo(6), whi(7), wlo(7),
        o_ba, o_bb, layer_theta, outA, outB);
}

// round 14
// speedup vs baseline: 1.2702x; 1.0059x over previous
#include <cuda_runtime.h>
#include <cuda_bf16.h>
#include <math.h>

// Problem constants
#define EG 1024      // embed dim
#define MG 2048      // B*S rows
#define SG 1024      // seq len
#define HG 16        // heads
#define DH 64        // head dim

// ---------------- scratch (device globals: no runtime allocation allowed) ----
__device__ float g_qa[MG * EG];
__device__ float g_qb[MG * EG];
__device__ float g_ka[MG * EG];
__device__ float g_kb[MG * EG];
__device__ float g_va[MG * EG];
__device__ float g_vb[MG * EG];

// pre-split bf16 hi/lo buffers
// weights: 0 q_wa, 1 q_wb, 2 k_wa, 3 k_wb, 4 v_wa, 5 v_wb, 6 o_wa, 7 o_wb
__device__ __nv_bfloat16 g_wH[8][EG * EG];
__device__ __nv_bfloat16 g_wL[8][EG * EG];
// activations: 0 x_q_a, 1 x_q_b, 2 x_kv_a, 3 x_kv_b, 4 oa, 5 ob
__device__ __nv_bfloat16 g_xH[6][MG * EG];
__device__ __nv_bfloat16 g_xL[6][MG * EG];

// attention pre-split buffers (post-rope K, j2h folded; V transposed [b,h,d,s])
__device__ __nv_bfloat16 g_kaH[MG * EG], g_kaL[MG * EG];
__device__ __nv_bfloat16 g_kbH[MG * EG], g_kbL[MG * EG];
__device__ __nv_bfloat16 g_kjH[MG * EG], g_kjL[MG * EG];
__device__ __nv_bfloat16 g_vaTH[MG * EG], g_vaTL[MG * EG];
__device__ __nv_bfloat16 g_vbTH[MG * EG], g_vbTL[MG * EG];

// ---------------------------------------------------------------------------
// helpers
// ---------------------------------------------------------------------------
__device__ __forceinline__ void mma_bf16(float* c, const unsigned* a, const unsigned* b)
{
    asm volatile(
        "mma.sync.aligned.m16n8k16.row.col.f32.bf16.bf16.f32 "
        "{%0,%1,%2,%3}, {%4,%5,%6,%7}, {%8,%9}, {%0,%1,%2,%3};"
        : "+f"(c[0]), "+f"(c[1]), "+f"(c[2]), "+f"(c[3])
        : "r"(a[0]), "r"(a[1]), "r"(a[2]), "r"(a[3]),
          "r"(b[0]), "r"(b[1]));
}

__device__ __forceinline__ void ldsm_x4(unsigned* r, const __nv_bfloat16* p)
{
    unsigned addr = (unsigned)__cvta_generic_to_shared(p);
    asm volatile("ldmatrix.sync.aligned.m8n8.x4.shared.b16 {%0,%1,%2,%3}, [%4];"
                 : "=r"(r[0]), "=r"(r[1]), "=r"(r[2]), "=r"(r[3]) : "r"(addr));
}

__device__ __forceinline__ unsigned pack_hi2(float x, float y)
{
    __nv_bfloat162 h(__float2bfloat16(x), __float2bfloat16(y));
    return *reinterpret_cast<unsigned*>(&h);
}
__device__ __forceinline__ unsigned pack_lo2(float x, float y)
{
    float hx = __bfloat162float(__float2bfloat16(x));
    float hy = __bfloat162float(__float2bfloat16(y));
    __nv_bfloat162 l(__float2bfloat16(x - hx), __float2bfloat16(y - hy));
    return *reinterpret_cast<unsigned*>(&l);
}

__device__ __forceinline__ void cp_async16(unsigned daddr, const void* src)
{
    asm volatile("cp.async.cg.shared.global [%0], [%1], 16;" :: "r"(daddr), "l"(src));
}
__device__ __forceinline__ void cp_commit()
{
    asm volatile("cp.async.commit_group;");
}
template<int N>
__device__ __forceinline__ void cp_wait()
{
    asm volatile("cp.async.wait_group %0;" :: "n"(N));
}

// smem tile strides (bf16 halfword units). BK=32 + pad 8 -> conflict-free frags.
#define TSTR 40
#define TILE_HF (64 * TSTR)

// ---------------------------------------------------------------------------
// Batched fp32 -> bf16 hi/lo split. blockIdx.y selects the tensor.
// ---------------------------------------------------------------------------
struct SplitBatch {
    const float* src[8];
    __nv_bfloat16* hi[8];
    __nv_bfloat16* lo[8];
};

__global__ __launch_bounds__(256) void split_kernel(SplitBatch sb, int nvec)
{
    const int t = blockIdx.x * 256 + threadIdx.x;
    if (t >= nvec) return;
    const int w = blockIdx.y;
    const float4 v = reinterpret_cast<const float4*>(sb.src[w])[t];

    unsigned h0 = pack_hi2(v.x, v.y);
    unsigned h1 = pack_hi2(v.z, v.w);
    unsigned l0 = pack_lo2(v.x, v.y);
    unsigned l1 = pack_lo2(v.z, v.w);

    reinterpret_cast<uint2*>(sb.hi[w])[t] = make_uint2(h0, h1);
    reinterpret_cast<uint2*>(sb.lo[w])[t] = make_uint2(l0, l1);
}

// ---------------------------------------------------------------------------
// Fused quaternion-complex dense on tensor cores (R12-validated, 158us).
//   outA = Xa.Wa^T + j2 * Xb.Wb^T + ba ;  outB = Xa.Wb^T + Xb.Wa^T + bb
// 64x64 CTA tile, BK=32, cp.async double-buffered, ldmatrix frags,
// __launch_bounds__(256,2) to guarantee 2 CTAs/SM.
// ---------------------------------------------------------------------------
__global__ __launch_bounds__(256, 2) void qc_gemm_bf16_kernel(
    const __nv_bfloat16* __restrict__ xaH, const __nv_bfloat16* __restrict__ xaL,
    const __nv_bfloat16* __restrict__ xbH, const __nv_bfloat16* __restrict__ xbL,
    const __nv_bfloat16* __restrict__ waH, const __nv_bfloat16* __restrict__ waL,
    const __nv_bfloat16* __restrict__ wbH, const __nv_bfloat16* __restrict__ wbL,
    const float* __restrict__ ba, const float* __restrict__ bb,
    const float* __restrict__ theta_ptr,
    float* __restrict__ outA, float* __restrict__ outB)
{
    extern __shared__ __nv_bfloat16 sbuf[];

    const int tid = threadIdx.x;
    const int lane = tid & 31;
    const int wid = tid >> 5;
    const int warp_m = wid >> 1;
    const int warp_n = wid & 1;
    const int g = lane >> 2;
    const int t = lane & 3;

    const int m0 = blockIdx.y * 64;
    const int n0 = blockIdx.x * 64;

    const float j2 = sinf(2.0f * theta_ptr[0]) - 1.0f;

    const int aoff = (warp_m * 16 + (lane & 15)) * TSTR + ((lane >> 4) << 3);
    const int boff = ((lane & 7) + ((lane & 16) >> 1)) * TSTR + (((lane >> 3) & 1) << 3);

    const int losel = tid >> 7;           // 0 hi, 1 lo
    const int tt    = tid & 127;
    const int lr0   = tt >> 2;            // rows 0..31 (chunk j=0)
    const int lc0   = (tt & 3) << 3;      // cols 0,8,16,24 (elements)

    const __nv_bfloat16* sxa = (losel ? xaL : xaH) + (size_t)(m0 + lr0) * EG + lc0;
    const __nv_bfloat16* sxb = (losel ? xbL : xbH) + (size_t)(m0 + lr0) * EG + lc0;
    const __nv_bfloat16* swa = (losel ? waL : waH) + (size_t)(n0 + lr0) * EG + lc0;
    const __nv_bfloat16* swb = (losel ? wbL : wbH) + (size_t)(n0 + lr0) * EG + lc0;
    const size_t GROW = (size_t)32 * EG;

    const int doff0 = lr0 * TSTR + lc0;
    const int doff1 = doff0 + 32 * TSTR;
    unsigned dxa[2][2], dxb[2][2], dwa[2][2], dwb[2][2];
    #pragma unroll
    for (int st = 0; st < 2; st++) {
        __nv_bfloat16* base = sbuf + st * 8 * TILE_HF;
        __nv_bfloat16* bxa = base + (0 + losel) * TILE_HF;
        __nv_bfloat16* bxb = base + (2 + losel) * TILE_HF;
        __nv_bfloat16* bwa = base + (4 + losel) * TILE_HF;
        __nv_bfloat16* bwb = base + (6 + losel) * TILE_HF;
        dxa[st][0] = (unsigned)__cvta_generic_to_shared(bxa + doff0);
        dxa[st][1] = (unsigned)__cvta_generic_to_shared(bxa + doff1);
        dxb[st][0] = (unsigned)__cvta_generic_to_shared(bxb + doff0);
        dxb[st][1] = (unsigned)__cvta_generic_to_shared(bxb + doff1);
        dwa[st][0] = (unsigned)__cvta_generic_to_shared(bwa + doff0);
        dwa[st][1] = (unsigned)__cvta_generic_to_shared(bwa + doff1);
        dwb[st][0] = (unsigned)__cvta_generic_to_shared(bwb + doff0);
        dwb[st][1] = (unsigned)__cvta_generic_to_shared(bwb + doff1);
    }

    float accA1[4][4] = {};
    float accA2[4][4] = {};
    float accB [4][4] = {};

    cp_async16(dxa[0][0], sxa);          cp_async16(dxa[0][1], sxa + GROW);
    cp_async16(dxb[0][0], sxb);          cp_async16(dxb[0][1], sxb + GROW);
    cp_async16(dwa[0][0], swa);          cp_async16(dwa[0][1], swa + GROW);
    cp_async16(dwb[0][0], swb);          cp_async16(dwb[0][1], swb + GROW);
    cp_commit();

    const int NIT = EG / 32;
    for (int it = 0; it < NIT; it++) {
        const int cur = it & 1;
        if (it + 1 < NIT) {
            const int nk = (it + 1) * 32;
            const int ns = 1 - cur;
            cp_async16(dxa[ns][0], sxa + nk);   cp_async16(dxa[ns][1], sxa + nk + GROW);
            cp_async16(dxb[ns][0], sxb + nk);   cp_async16(dxb[ns][1], sxb + nk + GROW);
            cp_async16(dwa[ns][0], swa + nk);   cp_async16(dwa[ns][1], swa + nk + GROW);
            cp_async16(dwb[ns][0], swb + nk);   cp_async16(dwb[ns][1], swb + nk + GROW);
            cp_commit();
            cp_wait<1>();
        } else {
            cp_wait<0>();
        }
        __syncthreads();

        const __nv_bfloat16* cb = sbuf + cur * 8 * TILE_HF;
        const __nv_bfloat16* sXaH = cb + 0 * TILE_HF;
        const __nv_bfloat16* sXaL = cb + 1 * TILE_HF;
        const __nv_bfloat16* sXbH = cb + 2 * TILE_HF;
        const __nv_bfloat16* sXbL = cb + 3 * TILE_HF;
        const __nv_bfloat16* sWaH = cb + 4 * TILE_HF;
        const __nv_bfloat16* sWaL = cb + 5 * TILE_HF;
        const __nv_bfloat16* sWbH = cb + 6 * TILE_HF;
        const __nv_bfloat16* sWbL = cb + 7 * TILE_HF;

        #pragma unroll
        for (int ks = 0; ks < 2; ks++) {
            const int sk = ks * 16;
            unsigned aXaH[4], aXaL[4], aXbH[4], aXbL[4];
            ldsm_x4(aXaH, sXaH + aoff + sk);
            ldsm_x4(aXaL, sXaL + aoff + sk);
            ldsm_x4(aXbH, sXbH + aoff + sk);
            ldsm_x4(aXbL, sXbL + aoff + sk);

            #pragma unroll
            for (int fp = 0; fp < 2; fp++) {
                const int bo = (warp_n * 32 + fp * 16) * TSTR + boff + sk;
                unsigned bWaH[4], bWaL[4], bWbH[4], bWbL[4];
                ldsm_x4(bWaH, sWaH + bo);
                ldsm_x4(bWaL, sWaL + bo);
                ldsm_x4(bWbH, sWbH + bo);
                ldsm_x4(bWbL, sWbL + bo);

                const int f0 = fp * 2, f1 = fp * 2 + 1;
                mma_bf16(accA1[f0], aXaH, bWaH + 0);  mma_bf16(accA1[f1], aXaH, bWaH + 2);
                mma_bf16(accA2[f0], aXbH, bWbH + 0);  mma_bf16(accA2[f1], aXbH, bWbH + 2);
                mma_bf16(accB [f0], aXaH, bWbH + 0);  mma_bf16(accB [f1], aXaH, bWbH + 2);
                mma_bf16(accA1[f0], aXaH, bWaL + 0);  mma_bf16(accA1[f1], aXaH, bWaL + 2);
                mma_bf16(accA2[f0], aXbH, bWbL + 0);  mma_bf16(accA2[f1], aXbH, bWbL + 2);
                mma_bf16(accB [f0], aXbH, bWaH + 0);  mma_bf16(accB [f1], aXbH, bWaH + 2);
                mma_bf16(accA1[f0], aXaL, bWaH + 0);  mma_bf16(accA1[f1], aXaL, bWaH + 2);
                mma_bf16(accA2[f0], aXbL, bWbH + 0);  mma_bf16(accA2[f1], aXbL, bWbH + 2);
                mma_bf16(accB [f0], aXaH, bWbL + 0);  mma_bf16(accB [f1], aXaH, bWbL + 2);
                mma_bf16(accB [f0], aXbH, bWaL + 0);  mma_bf16(accB [f1], aXbH, bWaL + 2);
                mma_bf16(accB [f0], aXaL, bWbH + 0);  mma_bf16(accB [f1], aXaL, bWbH + 2);
                mma_bf16(accB [f0], aXbL, bWaH + 0);  mma_bf16(accB [f1], aXbL, bWaH + 2);
            }
        }
        __syncthreads();
    }

    #pragma unroll
    for (int f = 0; f < 4; f++) {
        const int n = n0 + warp_n * 32 + f * 8 + 2 * t;
        const int r0 = m0 + warp_m * 16 + g;
        const int r1 = r0 + 8;
        const float ba0 = ba[n], ba1 = ba[n + 1];
        const float bb0 = bb[n], bb1 = bb[n + 1];

        float2 oa0 = { accA1[f][0] + j2 * accA2[f][0] + ba0,
                       accA1[f][1] + j2 * accA2[f][1] + ba1 };
        float2 oa1 = { accA1[f][2] + j2 * accA2[f][2] + ba0,
                       accA1[f][3] + j2 * accA2[f][3] + ba1 };
        float2 ob0 = { accB[f][0] + bb0, accB[f][1] + bb1 };
        float2 ob1 = { accB[f][2] + bb0, accB[f][3] + bb1 };

        *(float2*)&outA[r0 * EG + n] = oa0;
        *(float2*)&outA[r1 * EG + n] = oa1;
        *(float2*)&outB[r0 * EG + n] = ob0;
        *(float2*)&outB[r1 * EG + n] = ob1;
    }
}

// ---------------------------------------------------------------------------
// RoPE applied in place to g_qa, g_qb, g_ka, g_kb (fp32 throughout).
// ---------------------------------------------------------------------------
__global__ __launch_bounds__(256) void rope_kernel()
{
    const int PAIRS = MG * (EG / 2);
    int tt = blockIdx.x * blockDim.x + threadIdx.x;
    if (tt >= 4 * PAIRS) return;

    const int w = tt / PAIRS;
    const int p = tt % PAIRS;
    float* X = (w == 0) ? g_qa : (w == 1) ? g_qb : (w == 2) ? g_ka : g_kb;

    const int row = p >> 9;
    const int pp  = p & 511;
    const int h   = pp >> 5;
    const int i   = pp & 31;
    const int s   = row & (SG - 1);

    const float freq = exp2f(-(float)i * (13.287712379549449f / 32.0f));
    float sn, cs;
    sincosf((float)s * freq, &sn, &cs);

    const int base = row * EG + h * DH + i;
    const float x1 = X[base];
    const float x2 = X[base + 32];
    X[base]      = x1 * cs - x2 * sn;
    X[base + 32] = x2 * cs + x1 * sn;
}

// ---------------------------------------------------------------------------
// prep_k: post-rope K -> bf16 hi/lo (ka, kb, kj = j2h(h)*kb), same layout.
// ---------------------------------------------------------------------------
__global__ __launch_bounds__(256) void prep_k_kernel(const float* __restrict__ thetas_head)
{
    const int t = blockIdx.x * 256 + threadIdx.x;
    const int row = t >> 8;
    const int c4  = (t & 255) << 2;
    const int h   = c4 >> 6;
    const float j2h = sinf(2.0f * thetas_head[h]) - 1.0f;

    const size_t off = (size_t)row * EG + c4;
    float4 ka = *(const float4*)&g_ka[off];
    float4 kb = *(const float4*)&g_kb[off];
    float4 kj = { j2h * kb.x, j2h * kb.y, j2h * kb.z, j2h * kb.w };

    *(uint2*)&g_kaH[off] = make_uint2(pack_hi2(ka.x, ka.y), pack_hi2(ka.z, ka.w));
    *(uint2*)&g_kaL[off] = make_uint2(pack_lo2(ka.x, ka.y), pack_lo2(ka.z, ka.w));
    *(uint2*)&g_kbH[off] = make_uint2(pack_hi2(kb.x, kb.y), pack_hi2(kb.z, kb.w));
    *(uint2*)&g_kbL[off] = make_uint2(pack_lo2(kb.x, kb.y), pack_lo2(kb.z, kb.w));
    *(uint2*)&g_kjH[off] = make_uint2(pack_hi2(kj.x, kj.y), pack_hi2(kj.z, kj.w));
    *(uint2*)&g_kjL[off] = make_uint2(pack_lo2(kj.x, kj.y), pack_lo2(kj.z, kj.w));
}

// ---------------------------------------------------------------------------
// prep_v: V -> bf16 hi/lo TRANSPOSED to [b,h,d,s] (s contiguous).
// ---------------------------------------------------------------------------
__global__ __launch_bounds__(256) void prep_v_kernel()
{
    const int t = blockIdx.x * 256 + threadIdx.x;
    const int bhd = t >> 8;
    const int s4  = (t & 255) << 2;
    const int b   = bhd >> 10;
    const int hd  = bhd & 1023;

    const size_t ib = ((size_t)b * SG + s4) * EG + hd;
    float a0 = g_va[ib], a1 = g_va[ib + EG], a2 = g_va[ib + 2 * EG], a3 = g_va[ib + 3 * EG];
    float b0 = g_vb[ib], b1 = g_vb[ib + EG], b2 = g_vb[ib + 2 * EG], b3 = g_vb[ib + 3 * EG];

    const size_t ob = (size_t)bhd * SG + s4;
    *(uint2*)&g_vaTH[ob] = make_uint2(pack_hi2(a0, a1), pack_hi2(a2, a3));
    *(uint2*)&g_vaTL[ob] = make_uint2(pack_lo2(a0, a1), pack_lo2(a2, a3));
    *(uint2*)&g_vbTH[ob] = make_uint2(pack_hi2(b0, b1), pack_hi2(b2, b3));
    *(uint2*)&g_vbTL[ob] = make_uint2(pack_lo2(b0, b1), pack_lo2(b2, b3));
}

// ---------------------------------------------------------------------------
// Tensor-core flash attention. Producers copy pre-split data (R12);
// fragment loads via ldmatrix (R7-validated lane mapping);
// heavy-first CTA order (reversed blockIdx.x) for causal balance.
// ---------------------------------------------------------------------------
#define KSTR 72
#define VSTR 40

__global__ __launch_bounds__(256) void attn_mma_kernel(const float* __restrict__ thetas_head)
{
    __shared__ __nv_bfloat16 sKaH[32 * KSTR], sKaL[32 * KSTR];
    __shared__ __nv_bfloat16 sKbH[32 * KSTR], sKbL[32 * KSTR];
    __shared__ __nv_bfloat16 sKjH[32 * KSTR], sKjL[32 * KSTR];
    __shared__ __nv_bfloat16 sVaH[64 * VSTR], sVaL[64 * VSTR];
    __shared__ __nv_bfloat16 sVbH[64 * VSTR], sVbL[64 * VSTR];

    const int b   = blockIdx.z;
    const int h   = blockIdx.y;
    const int r0  = ((int)gridDim.x - 1 - (int)blockIdx.x) * 128;   // heavy tiles first
    const int tid = threadIdx.x;
    const int lane = tid & 31;
    const int wid  = tid >> 5;
    const int g = lane >> 2;
    const int t = lane & 3;

    // ldmatrix B-style per-lane offsets for K (stride KSTR) and V (stride VSTR)
    const int koff = ((lane & 7) + ((lane & 16) >> 1)) * KSTR + (((lane >> 3) & 1) << 3);
    const int voff = ((lane & 7) + ((lane & 16) >> 1)) * VSTR + (((lane >> 3) & 1) << 3);

    unsigned qaH[4][4], qaL[4][4], qbH[4][4], qbL[4][4];
    {
        const int row0 = r0 + wid * 16 + g;
        const int base0 = (b * SG + row0) * EG + h * DH;
        const int base1 = base0 + 8 * EG;
        #pragma unroll
        for (int ks = 0; ks < 4; ks++) {
            const int col = ks * 16 + 2 * t;
            float2 a0 = *(const float2*)&g_qa[base0 + col];
            float2 a1 = *(const float2*)&g_qa[base1 + col];
            float2 a2 = *(const float2*)&g_qa[base0 + col + 8];
            float2 a3 = *(const float2*)&g_qa[base1 + col + 8];
            qaH[ks][0] = pack_hi2(a0.x, a0.y); qaL[ks][0] = pack_lo2(a0.x, a0.y);
            qaH[ks][1] = pack_hi2(a1.x, a1.y); qaL[ks][1] = pack_lo2(a1.x, a1.y);
            qaH[ks][2] = pack_hi2(a2.x, a2.y); qaL[ks][2] = pack_lo2(a2.x, a2.y);
            qaH[ks][3] = pack_hi2(a3.x, a3.y); qaL[ks][3] = pack_lo2(a3.x, a3.y);
            float2 b0 = *(const float2*)&g_qb[base0 + col];
            float2 b1 = *(const float2*)&g_qb[base1 + col];
            float2 b2 = *(const float2*)&g_qb[base0 + col + 8];
            float2 b3 = *(const float2*)&g_qb[base1 + col + 8];
            qbH[ks][0] = pack_hi2(b0.x, b0.y); qbL[ks][0] = pack_lo2(b0.x, b0.y);
            qbH[ks][1] = pack_hi2(b1.x, b1.y); qbL[ks][1] = pack_lo2(b1.x, b1.y);
            qbH[ks][2] = pack_hi2(b2.x, b2.y); qbL[ks][2] = pack_lo2(b2.x, b2.y);
            qbH[ks][3] = pack_hi2(b3.x, b3.y); qbL[ks][3] = pack_lo2(b3.x, b3.y);
        }
    }

    float oa[8][4] = {};
    float ob[8][4] = {};
    float mrow0 = -1e30f, mrow1 = -1e30f;
    float lrow0 = 0.0f,   lrow1 = 0.0f;

    const int ntiles = (r0 >> 5) + 4;
    for (int tile = 0; tile < ntiles; tile++) {
        const int k0 = tile * 32;

        __syncthreads();

        // ---- K producer: pure uint2 copies from pre-split globals ----
        #pragma unroll
        for (int it = 0; it < 2; it++) {
            const int idx = tid + it * 256;
            const int n  = idx >> 4;
            const int d4 = (idx & 15) << 2;
            const size_t ga = (size_t)(b * SG + k0 + n) * EG + h * DH + d4;
            const int si = n * KSTR + d4;
            *(uint2*)&sKaH[si] = *(const uint2*)&g_kaH[ga];
            *(uint2*)&sKaL[si] = *(const uint2*)&g_kaL[ga];
            *(uint2*)&sKbH[si] = *(const uint2*)&g_kbH[ga];
            *(uint2*)&sKbL[si] = *(const uint2*)&g_kbL[ga];
            *(uint2*)&sKjH[si] = *(const uint2*)&g_kjH[ga];
            *(uint2*)&sKjL[si] = *(const uint2*)&g_kjL[ga];
        }
        // ---- V producer: copies from pre-transposed [b,h,d,s] globals ----
        #pragma unroll
        for (int it = 0; it < 2; it++) {
            const int idx = tid + it * 256;
            const int d  = idx >> 3;
            const int s4 = (idx & 7) << 2;
            const size_t ga = ((size_t)(b * HG + h) * DH + d) * SG + k0 + s4;
            const int si = d * VSTR + s4;
            *(uint2*)&sVaH[si] = *(const uint2*)&g_vaTH[ga];
            *(uint2*)&sVaL[si] = *(const uint2*)&g_vaTL[ga];
            *(uint2*)&sVbH[si] = *(const uint2*)&g_vbTH[ga];
            *(uint2*)&sVbL[si] = *(const uint2*)&g_vbTL[ga];
        }
        __syncthreads();

        const int wrow = r0 + wid * 16;
        if (k0 > wrow + 15) continue;

        float sa[4][4] = {};
        float sb[4][4] = {};
        #pragma unroll
        for (int ks = 0; ks < 4; ks++) {
            const int sk = ks * 16;
            #pragma unroll
            for (int pb = 0; pb < 2; pb++) {
                const int ko = pb * 16 * KSTR + koff + sk;
                unsigned kaH[4], kaL[4], kbH[4], kbL[4], kjH[4], kjL[4];
                ldsm_x4(kaH, sKaH + ko);
                ldsm_x4(kaL, sKaL + ko);
                ldsm_x4(kbH, sKbH + ko);
                ldsm_x4(kbL, sKbL + ko);
                ldsm_x4(kjH, sKjH + ko);
                ldsm_x4(kjL, sKjL + ko);

                #pragma unroll
                for (int half = 0; half < 2; half++) {
                    const int nf = pb * 2 + half;
                    const int o = half * 2;
                    mma_bf16(sa[nf], qaH[ks], kaH + o);
                    mma_bf16(sb[nf], qaH[ks], kbH + o);
                    mma_bf16(sa[nf], qaH[ks], kaL + o);
                    mma_bf16(sb[nf], qaH[ks], kbL + o);
                    mma_bf16(sa[nf], qaL[ks], kaH + o);
                    mma_bf16(sb[nf], qaL[ks], kbH + o);
                    mma_bf16(sa[nf], qbH[ks], kjH + o);
                    mma_bf16(sb[nf], qbH[ks], kaH + o);
                    mma_bf16(sa[nf], qbH[ks], kjL + o);
                    mma_bf16(sb[nf], qbH[ks], kaL + o);
                    mma_bf16(sa[nf], qbL[ks], kjH + o);
                    mma_bf16(sb[nf], qbL[ks], kaH + o);
                }
            }
        }

        const bool full = (k0 + 31 <= wrow);
        float mt0 = -1e30f, mt1 = -1e30f;
        #pragma unroll
        for (int nf = 0; nf < 4; nf++) {
            #pragma unroll
            for (int c = 0; c < 4; c++) {
                float v = sqrtf(sa[nf][c] * sa[nf][c] + sb[nf][c] * sb[nf][c] + 1e-8f) * 0.125f;
                if (!full) {
                    const int col = k0 + nf * 8 + 2 * t + (c & 1);
                    const int row = wrow + g + ((c & 2) ? 8 : 0);
                    if (col > row) v = -1e9f;
                }
                sa[nf][c] = v;
                if (c & 2) mt1 = fmaxf(mt1, v); else mt0 = fmaxf(mt0, v);
            }
        }
        mt0 = fmaxf(mt0, __shfl_xor_sync(0xffffffffu, mt0, 1));
        mt0 = fmaxf(mt0, __shfl_xor_sync(0xffffffffu, mt0, 2));
        mt1 = fmaxf(mt1, __shfl_xor_sync(0xffffffffu, mt1, 1));
        mt1 = fmaxf(mt1, __shfl_xor_sync(0xffffffffu, mt1, 2));

        const float mn0 = fmaxf(mrow0, mt0);
        const float mn1 = fmaxf(mrow1, mt1);

        float ps0 = 0.0f, ps1 = 0.0f;
        #pragma unroll
        for (int nf = 0; nf < 4; nf++) {
            #pragma unroll
            for (int c = 0; c < 4; c++) {
                const float p = __expf(sa[nf][c] - ((c & 2) ? mn1 : mn0));
                sa[nf][c] = p;
                if (c & 2) ps1 += p; else ps0 += p;
            }
        }
        ps0 += __shfl_xor_sync(0xffffffffu, ps0, 1);
        ps0 += __shfl_xor_sync(0xffffffffu, ps0, 2);
        ps1 += __shfl_xor_sync(0xffffffffu, ps1, 1);
        ps1 += __shfl_xor_sync(0xffffffffu, ps1, 2);

        const float sc0 = __expf(mrow0 - mn0);
        const float sc1 = __expf(mrow1 - mn1);
        lrow0 = lrow0 * sc0 + ps0;  mrow0 = mn0;
        lrow1 = lrow1 * sc1 + ps1;  mrow1 = mn1;
        #pragma unroll
        for (int nf = 0; nf < 8; nf++) {
            oa[nf][0] *= sc0; oa[nf][1] *= sc0; oa[nf][2] *= sc1; oa[nf][3] *= sc1;
            ob[nf][0] *= sc0; ob[nf][1] *= sc0; ob[nf][2] *= sc1; ob[nf][3] *= sc1;
        }

        unsigned pH[2][4], pL[2][4];
        #pragma unroll
        for (int kc = 0; kc < 2; kc++) {
            const int f = 2 * kc;
            pH[kc][0] = pack_hi2(sa[f][0],     sa[f][1]);
            pL[kc][0] = pack_lo2(sa[f][0],     sa[f][1]);
            pH[kc][1] = pack_hi2(sa[f][2],     sa[f][3]);
            pL[kc][1] = pack_lo2(sa[f][2],     sa[f][3]);
            pH[kc][2] = pack_hi2(sa[f + 1][0], sa[f + 1][1]);
            pL[kc][2] = pack_lo2(sa[f + 1][0], sa[f + 1][1]);
            pH[kc][3] = pack_hi2(sa[f + 1][2], sa[f + 1][3]);
            pL[kc][3] = pack_lo2(sa[f + 1][2], sa[f + 1][3]);
        }

        #pragma unroll
        for (int pv = 0; pv < 4; pv++) {
            #pragma unroll
            for (int kc = 0; kc < 2; kc++) {
                const int vo = pv * 16 * VSTR + voff + kc * 16;
                unsigned vaH[4], vaL[4], vbH[4], vbL[4];
                ldsm_x4(vaH, sVaH + vo);
                ldsm_x4(vaL, sVaL + vo);
                ldsm_x4(vbH, sVbH + vo);
                ldsm_x4(vbL, sVbL + vo);

                #pragma unroll
                for (int half = 0; half < 2; half++) {
                    const int nf = pv * 2 + half;
                    const int o = half * 2;
                    mma_bf16(oa[nf], pH[kc], vaH + o);
                    mma_bf16(ob[nf], pH[kc], vbH + o);
                    mma_bf16(oa[nf], pL[kc], vaH + o);
                    mma_bf16(ob[nf], pL[kc], vbH + o);
                    mma_bf16(oa[nf], pH[kc], vaL + o);
                    mma_bf16(ob[nf], pH[kc], vbL + o);
                }
            }
        }
    }

    // epilogue: write bf16 hi/lo directly (identical split of the fp32 value)
    const float inv0 = 1.0f / lrow0;
    const float inv1 = 1.0f / lrow1;
    const int row0 = r0 + wid * 16 + g;
    const int base0 = (b * SG + row0) * EG + h * DH;
    const int base1 = base0 + 8 * EG;
    __nv_bfloat16* xh4 = g_xH[4];  __nv_bfloat16* xl4 = g_xL[4];
    __nv_bfloat16* xh5 = g_xH[5];  __nv_bfloat16* xl5 = g_xL[5];
    #pragma unroll
    for (int nf = 0; nf < 8; nf++) {
        const int d = nf * 8 + 2 * t;
        float a00 = oa[nf][0] * inv0, a01 = oa[nf][1] * inv0;
        float a10 = oa[nf][2] * inv1, a11 = oa[nf][3] * inv1;
        float b00 = ob[nf][0] * inv0, b01 = ob[nf][1] * inv0;
        float b10 = ob[nf][2] * inv1, b11 = ob[nf][3] * inv1;
        *(unsigned*)&xh4[base0 + d] = pack_hi2(a00, a01);
        *(unsigned*)&xl4[base0 + d] = pack_lo2(a00, a01);
        *(unsigned*)&xh4[base1 + d] = pack_hi2(a10, a11);
        *(unsigned*)&xl4[base1 + d] = pack_lo2(a10, a11);
        *(unsigned*)&xh5[base0 + d] = pack_hi2(b00, b01);
        *(unsigned*)&xl5[base0 + d] = pack_lo2(b00, b01);
        *(unsigned*)&xh5[base1 + d] = pack_hi2(b10, b11);
        *(unsigned*)&xl5[base1 + d] = pack_lo2(b10, b11);
    }
    (void)thetas_head;
}

// ---------------------------------------------------------------------------
extern "C" void kernel_launch(void* const* d_in, const int* in_sizes, int n_in,
                              void* d_out, int out_size)
{
    const float* x_q_a  = (const float*)d_in[0];
    const float* x_q_b  = (const float*)d_in[1];
    const float* x_kv_a = (const float*)d_in[2];
    const float* x_kv_b = (const float*)d_in[3];
    // d_in[4] = mask -- causal, encoded in the attention kernel
    const float* layer_theta = (const float*)d_in[5];
    const float* thetas_head = (const float*)d_in[6];
    const float* q_wa = (const float*)d_in[7];
    const float* q_wb = (const float*)d_in[8];
    const float* q_ba = (const float*)d_in[9];
    const float* q_bb = (const float*)d_in[10];
    const float* k_wa = (const float*)d_in[11];
    const float* k_wb = (const float*)d_in[12];
    const float* k_ba = (const float*)d_in[13];
    const float* k_bb = (const float*)d_in[14];
    const float* v_wa = (const float*)d_in[15];
    const float* v_wb = (const float*)d_in[16];
    const float* v_ba = (const float*)d_in[17];
    const float* v_bb = (const float*)d_in[18];
    const float* o_wa = (const float*)d_in[19];
    const float* o_wb = (const float*)d_in[20];
    const float* o_ba = (const float*)d_in[21];
    const float* o_bb = (const float*)d_in[22];

    float *qa, *qb, *ka, *kb, *va, *vb;
    cudaGetSymbolAddress((void**)&qa, g_qa);
    cudaGetSymbolAddress((void**)&qb, g_qb);
    cudaGetSymbolAddress((void**)&ka, g_ka);
    cudaGetSymbolAddress((void**)&kb, g_kb);
    cudaGetSymbolAddress((void**)&va, g_va);
    cudaGetSymbolAddress((void**)&vb, g_vb);

    __nv_bfloat16 *wH, *wL, *xH, *xL;
    cudaGetSymbolAddress((void**)&wH, g_wH);
    cudaGetSymbolAddress((void**)&wL, g_wL);
    cudaGetSymbolAddress((void**)&xH, g_xH);
    cudaGetSymbolAddress((void**)&xL, g_xL);
    const size_t WSZ = (size_t)EG * EG;
    const size_t XSZ = (size_t)MG * EG;
    auto whi = [&](int i) { return wH + i * WSZ; };
    auto wlo = [&](int i) { return wL + i * WSZ; };
    auto xhi = [&](int i) { return xH + i * XSZ; };
    auto xlo = [&](int i) { return xL + i * XSZ; };

    float* outA = (float*)d_out;
    float* outB = (float*)d_out + (size_t)MG * EG;

    const int GSMEM = 2 * 8 * TILE_HF * (int)sizeof(__nv_bfloat16);  // 81920
    cudaFuncSetAttribute(qc_gemm_bf16_kernel,
                         cudaFuncAttributeMaxDynamicSharedMemorySize, GSMEM);

    // ---- split weights (8 matrices) ----
    {
        SplitBatch sb = {};
        const float* srcs[8] = { q_wa, q_wb, k_wa, k_wb, v_wa, v_wb, o_wa, o_wb };
        for (int i = 0; i < 8; i++) { sb.src[i] = srcs[i]; sb.hi[i] = whi(i); sb.lo[i] = wlo(i); }
        split_kernel<<<dim3((unsigned)(WSZ / 4 / 256), 8), 256>>>(sb, (int)(WSZ / 4));
    }
    // ---- split input activations (4 tensors) ----
    {
        SplitBatch sb = {};
        const float* srcs[4] = { x_q_a, x_q_b, x_kv_a, x_kv_b };
        for (int i = 0; i < 4; i++) { sb.src[i] = srcs[i]; sb.hi[i] = xhi(i); sb.lo[i] = xlo(i); }
        split_kernel<<<dim3((unsigned)(XSZ / 4 / 256), 4), 256>>>(sb, (int)(XSZ / 4));
    }

    const dim3 gg(EG / 64, MG / 64);

    // q / k / v projections
    qc_gemm_bf16_kernel<<<gg, 256, GSMEM>>>(
        xhi(0), xlo(0), xhi(1), xlo(1), whi(0), wlo(0), whi(1), wlo(1),
        q_ba, q_bb, layer_theta, qa, qb);
    qc_gemm_bf16_kernel<<<gg, 256, GSMEM>>>(
        xhi(2), xlo(2), xhi(3), xlo(3), whi(2), wlo(2), whi(3), wlo(3),
        k_ba, k_bb, layer_theta, ka, kb);
    qc_gemm_bf16_kernel<<<gg, 256, GSMEM>>>(
        xhi(2), xlo(2), xhi(3), xlo(3), whi(4), wlo(4), whi(5), wlo(5),
        v_ba, v_bb, layer_theta, va, vb);

    // RoPE on qa,qb,ka,kb (in place)
    rope_kernel<<<(4 * MG * (EG / 2)) / 256, 256>>>();

    // pre-split K (post-rope, j2h folded) and V (transposed) to bf16 hi/lo
    prep_k_kernel<<<(MG * EG / 4) / 256, 256>>>(thetas_head);
    prep_v_kernel<<<(MG * EG / 4) / 256, 256>>>();

    // tensor-core flash attention -> writes pre-split bf16 hi/lo (g_xH/L[4,5])
    attn_mma_kernel<<<dim3(SG / 128, HG, 2), 256>>>(thetas_head);

    // output projection straight into d_out (out_a then out_b)
    qc_gemm_bf16_kernel<<<gg, 256, GSMEM>>>(
        xhi(4), xlo(4), xhi(5), xlo(5), whi(6), wlo(6), whi(7), wlo(7),
        o_ba, o_bb, layer_theta, outA, outB);
}

// round 15
// speedup vs baseline: 1.3846x; 1.0901x over previous
#include <cuda_runtime.h>
#include <cuda_bf16.h>
#include <math.h>

// Problem constants
#define EG 1024      // embed dim
#define MG 2048      // B*S rows
#define SG 1024      // seq len
#define HG 16        // heads
#define DH 64        // head dim

// ---------------- scratch (device globals: no runtime allocation allowed) ----
__device__ float g_qa[MG * EG];
__device__ float g_qb[MG * EG];
__device__ float g_ka[MG * EG];
__device__ float g_kb[MG * EG];
__device__ float g_va[MG * EG];
__device__ float g_vb[MG * EG];

// pre-split bf16 hi/lo buffers
// weights: 0 q_wa, 1 q_wb, 2 k_wa, 3 k_wb, 4 v_wa, 5 v_wb, 6 o_wa, 7 o_wb
__device__ __nv_bfloat16 g_wH[8][EG * EG];
__device__ __nv_bfloat16 g_wL[8][EG * EG];
// activations: 0 x_q_a, 1 x_q_b, 2 x_kv_a, 3 x_kv_b, 4 oa, 5 ob
__device__ __nv_bfloat16 g_xH[6][MG * EG];
__device__ __nv_bfloat16 g_xL[6][MG * EG];

// attention pre-split buffers (post-rope K, j2h folded; V transposed [b,h,d,s])
__device__ __nv_bfloat16 g_kaH[MG * EG], g_kaL[MG * EG];
__device__ __nv_bfloat16 g_kbH[MG * EG], g_kbL[MG * EG];
__device__ __nv_bfloat16 g_kjH[MG * EG], g_kjL[MG * EG];
__device__ __nv_bfloat16 g_vaTH[MG * EG], g_vaTL[MG * EG];
__device__ __nv_bfloat16 g_vbTH[MG * EG], g_vbTL[MG * EG];

// ---------------------------------------------------------------------------
// helpers
// ---------------------------------------------------------------------------
__device__ __forceinline__ void mma_bf16(float* c, const unsigned* a, const unsigned* b)
{
    asm volatile(
        "mma.sync.aligned.m16n8k16.row.col.f32.bf16.bf16.f32 "
        "{%0,%1,%2,%3}, {%4,%5,%6,%7}, {%8,%9}, {%0,%1,%2,%3};"
        : "+f"(c[0]), "+f"(c[1]), "+f"(c[2]), "+f"(c[3])
        : "r"(a[0]), "r"(a[1]), "r"(a[2]), "r"(a[3]),
          "r"(b[0]), "r"(b[1]));
}

__device__ __forceinline__ void ldsm_x4(unsigned* r, const __nv_bfloat16* p)
{
    unsigned addr = (unsigned)__cvta_generic_to_shared(p);
    asm volatile("ldmatrix.sync.aligned.m8n8.x4.shared.b16 {%0,%1,%2,%3}, [%4];"
                 : "=r"(r[0]), "=r"(r[1]), "=r"(r[2]), "=r"(r[3]) : "r"(addr));
}

__device__ __forceinline__ unsigned pack_hi2(float x, float y)
{
    __nv_bfloat162 h(__float2bfloat16(x), __float2bfloat16(y));
    return *reinterpret_cast<unsigned*>(&h);
}
__device__ __forceinline__ unsigned pack_lo2(float x, float y)
{
    float hx = __bfloat162float(__float2bfloat16(x));
    float hy = __bfloat162float(__float2bfloat16(y));
    __nv_bfloat162 l(__float2bfloat16(x - hx), __float2bfloat16(y - hy));
    return *reinterpret_cast<unsigned*>(&l);
}

__device__ __forceinline__ void cp_async16(unsigned daddr, const void* src)
{
    asm volatile("cp.async.cg.shared.global [%0], [%1], 16;" :: "r"(daddr), "l"(src));
}
__device__ __forceinline__ void cp_commit()
{
    asm volatile("cp.async.commit_group;");
}
template<int N>
__device__ __forceinline__ void cp_wait()
{
    asm volatile("cp.async.wait_group %0;" :: "n"(N));
}

// smem tile strides (bf16 halfword units). BK=32 + pad 8 -> conflict-free frags.
#define TSTR 40
#define TILE_HF (64 * TSTR)

// ---------------------------------------------------------------------------
// Batched fp32 -> bf16 hi/lo split. blockIdx.y selects the tensor.
// ---------------------------------------------------------------------------
struct SplitBatch {
    const float* src[8];
    __nv_bfloat16* hi[8];
    __nv_bfloat16* lo[8];
};

__global__ __launch_bounds__(256) void split_kernel(SplitBatch sb, int nvec)
{
    const int t = blockIdx.x * 256 + threadIdx.x;
    if (t >= nvec) return;
    const int w = blockIdx.y;
    const float4 v = reinterpret_cast<const float4*>(sb.src[w])[t];

    unsigned h0 = pack_hi2(v.x, v.y);
    unsigned h1 = pack_hi2(v.z, v.w);
    unsigned l0 = pack_lo2(v.x, v.y);
    unsigned l1 = pack_lo2(v.z, v.w);

    reinterpret_cast<uint2*>(sb.hi[w])[t] = make_uint2(h0, h1);
    reinterpret_cast<uint2*>(sb.lo[w])[t] = make_uint2(l0, l1);
}

// ---------------------------------------------------------------------------
// Fused quaternion-complex dense on tensor cores.
//   outA = Xa.Wa^T + j2 * Xb.Wb^T + ba ;  outB = Xa.Wb^T + Xb.Wa^T + bb
// 64x64 CTA tile, BK=32, cp.async double-buffered, ldmatrix frags,
// __launch_bounds__(256,2). Early barrier: placed right after the LAST
// ldmatrix of each iteration (all smem reads done) so the final 24-MMA
// block overlaps with the barrier and the next stage refill.
// ---------------------------------------------------------------------------
__global__ __launch_bounds__(256, 2) void qc_gemm_bf16_kernel(
    const __nv_bfloat16* __restrict__ xaH, const __nv_bfloat16* __restrict__ xaL,
    const __nv_bfloat16* __restrict__ xbH, const __nv_bfloat16* __restrict__ xbL,
    const __nv_bfloat16* __restrict__ waH, const __nv_bfloat16* __restrict__ waL,
    const __nv_bfloat16* __restrict__ wbH, const __nv_bfloat16* __restrict__ wbL,
    const float* __restrict__ ba, const float* __restrict__ bb,
    const float* __restrict__ theta_ptr,
    float* __restrict__ outA, float* __restrict__ outB)
{
    extern __shared__ __nv_bfloat16 sbuf[];

    const int tid = threadIdx.x;
    const int lane = tid & 31;
    const int wid = tid >> 5;
    const int warp_m = wid >> 1;
    const int warp_n = wid & 1;
    const int g = lane >> 2;
    const int t = lane & 3;

    const int m0 = blockIdx.y * 64;
    const int n0 = blockIdx.x * 64;

    const float j2 = sinf(2.0f * theta_ptr[0]) - 1.0f;

    const int aoff = (warp_m * 16 + (lane & 15)) * TSTR + ((lane >> 4) << 3);
    const int boff = ((lane & 7) + ((lane & 16) >> 1)) * TSTR + (((lane >> 3) & 1) << 3);

    const int losel = tid >> 7;           // 0 hi, 1 lo
    const int tt    = tid & 127;
    const int lr0   = tt >> 2;            // rows 0..31 (chunk j=0)
    const int lc0   = (tt & 3) << 3;      // cols 0,8,16,24 (elements)

    const __nv_bfloat16* sxa = (losel ? xaL : xaH) + (size_t)(m0 + lr0) * EG + lc0;
    const __nv_bfloat16* sxb = (losel ? xbL : xbH) + (size_t)(m0 + lr0) * EG + lc0;
    const __nv_bfloat16* swa = (losel ? waL : waH) + (size_t)(n0 + lr0) * EG + lc0;
    const __nv_bfloat16* swb = (losel ? wbL : wbH) + (size_t)(n0 + lr0) * EG + lc0;
    const size_t GROW = (size_t)32 * EG;

    const int doff0 = lr0 * TSTR + lc0;
    const int doff1 = doff0 + 32 * TSTR;
    unsigned dxa[2][2], dxb[2][2], dwa[2][2], dwb[2][2];
    #pragma unroll
    for (int st = 0; st < 2; st++) {
        __nv_bfloat16* base = sbuf + st * 8 * TILE_HF;
        __nv_bfloat16* bxa = base + (0 + losel) * TILE_HF;
        __nv_bfloat16* bxb = base + (2 + losel) * TILE_HF;
        __nv_bfloat16* bwa = base + (4 + losel) * TILE_HF;
        __nv_bfloat16* bwb = base + (6 + losel) * TILE_HF;
        dxa[st][0] = (unsigned)__cvta_generic_to_shared(bxa + doff0);
        dxa[st][1] = (unsigned)__cvta_generic_to_shared(bxa + doff1);
        dxb[st][0] = (unsigned)__cvta_generic_to_shared(bxb + doff0);
        dxb[st][1] = (unsigned)__cvta_generic_to_shared(bxb + doff1);
        dwa[st][0] = (unsigned)__cvta_generic_to_shared(bwa + doff0);
        dwa[st][1] = (unsigned)__cvta_generic_to_shared(bwa + doff1);
        dwb[st][0] = (unsigned)__cvta_generic_to_shared(bwb + doff0);
        dwb[st][1] = (unsigned)__cvta_generic_to_shared(bwb + doff1);
    }

    float accA1[4][4] = {};
    float accA2[4][4] = {};
    float accB [4][4] = {};

    cp_async16(dxa[0][0], sxa);          cp_async16(dxa[0][1], sxa + GROW);
    cp_async16(dxb[0][0], sxb);          cp_async16(dxb[0][1], sxb + GROW);
    cp_async16(dwa[0][0], swa);          cp_async16(dwa[0][1], swa + GROW);
    cp_async16(dwb[0][0], swb);          cp_async16(dwb[0][1], swb + GROW);
    cp_commit();

#define QC_MMA_BLOCK(f0, f1) \
    mma_bf16(accA1[f0], aXaH, bWaH + 0);  mma_bf16(accA1[f1], aXaH, bWaH + 2); \
    mma_bf16(accA2[f0], aXbH, bWbH + 0);  mma_bf16(accA2[f1], aXbH, bWbH + 2); \
    mma_bf16(accB [f0], aXaH, bWbH + 0);  mma_bf16(accB [f1], aXaH, bWbH + 2); \
    mma_bf16(accA1[f0], aXaH, bWaL + 0);  mma_bf16(accA1[f1], aXaH, bWaL + 2); \
    mma_bf16(accA2[f0], aXbH, bWbL + 0);  mma_bf16(accA2[f1], aXbH, bWbL + 2); \
    mma_bf16(accB [f0], aXbH, bWaH + 0);  mma_bf16(accB [f1], aXbH, bWaH + 2); \
    mma_bf16(accA1[f0], aXaL, bWaH + 0);  mma_bf16(accA1[f1], aXaL, bWaH + 2); \
    mma_bf16(accA2[f0], aXbL, bWbH + 0);  mma_bf16(accA2[f1], aXbL, bWbH + 2); \
    mma_bf16(accB [f0], aXaH, bWbL + 0);  mma_bf16(accB [f1], aXaH, bWbL + 2); \
    mma_bf16(accB [f0], aXbH, bWaL + 0);  mma_bf16(accB [f1], aXbH, bWaL + 2); \
    mma_bf16(accB [f0], aXaL, bWbH + 0);  mma_bf16(accB [f1], aXaL, bWbH + 2); \
    mma_bf16(accB [f0], aXbL, bWaH + 0);  mma_bf16(accB [f1], aXbL, bWaH + 2)

#define QC_LD_A(sk) \
    ldsm_x4(aXaH, sXaH + aoff + (sk)); ldsm_x4(aXaL, sXaL + aoff + (sk)); \
    ldsm_x4(aXbH, sXbH + aoff + (sk)); ldsm_x4(aXbL, sXbL + aoff + (sk))

#define QC_LD_B(bo) \
    ldsm_x4(bWaH, sWaH + (bo)); ldsm_x4(bWaL, sWaL + (bo)); \
    ldsm_x4(bWbH, sWbH + (bo)); ldsm_x4(bWbL, sWbL + (bo))

    const int NIT = EG / 32;
    for (int it = 0; it < NIT; it++) {
        const int cur = it & 1;
        if (it + 1 < NIT) {
            const int nk = (it + 1) * 32;
            const int ns = 1 - cur;
            cp_async16(dxa[ns][0], sxa + nk);   cp_async16(dxa[ns][1], sxa + nk + GROW);
            cp_async16(dxb[ns][0], sxb + nk);   cp_async16(dxb[ns][1], sxb + nk + GROW);
            cp_async16(dwa[ns][0], swa + nk);   cp_async16(dwa[ns][1], swa + nk + GROW);
            cp_async16(dwb[ns][0], swb + nk);   cp_async16(dwb[ns][1], swb + nk + GROW);
            cp_commit();
            cp_wait<1>();
        } else {
            cp_wait<0>();
        }
        __syncthreads();

        const __nv_bfloat16* cb = sbuf + cur * 8 * TILE_HF;
        const __nv_bfloat16* sXaH = cb + 0 * TILE_HF;
        const __nv_bfloat16* sXaL = cb + 1 * TILE_HF;
        const __nv_bfloat16* sXbH = cb + 2 * TILE_HF;
        const __nv_bfloat16* sXbL = cb + 3 * TILE_HF;
        const __nv_bfloat16* sWaH = cb + 4 * TILE_HF;
        const __nv_bfloat16* sWaL = cb + 5 * TILE_HF;
        const __nv_bfloat16* sWbH = cb + 6 * TILE_HF;
        const __nv_bfloat16* sWbL = cb + 7 * TILE_HF;

        unsigned aXaH[4], aXaL[4], aXbH[4], aXbL[4];
        unsigned bWaH[4], bWaL[4], bWbH[4], bWbL[4];
        const int bo0 = (warp_n * 32) * TSTR + boff;
        const int bo1 = (warp_n * 32 + 16) * TSTR + boff;

        // ks = 0
        QC_LD_A(0);
        QC_LD_B(bo0);
        QC_MMA_BLOCK(0, 1);
        QC_LD_B(bo1);
        QC_MMA_BLOCK(2, 3);
        // ks = 1
        QC_LD_A(16);
        QC_LD_B(bo0 + 16);
        QC_MMA_BLOCK(0, 1);
        QC_LD_B(bo1 + 16);
        __syncthreads();   // all smem reads for this stage complete; refill may proceed
        QC_MMA_BLOCK(2, 3);
    }

    #pragma unroll
    for (int f = 0; f < 4; f++) {
        const int n = n0 + warp_n * 32 + f * 8 + 2 * t;
        const int r0 = m0 + warp_m * 16 + g;
        const int r1 = r0 + 8;
        const float ba0 = ba[n], ba1 = ba[n + 1];
        const float bb0 = bb[n], bb1 = bb[n + 1];

        float2 oa0 = { accA1[f][0] + j2 * accA2[f][0] + ba0,
                       accA1[f][1] + j2 * accA2[f][1] + ba1 };
        float2 oa1 = { accA1[f][2] + j2 * accA2[f][2] + ba0,
                       accA1[f][3] + j2 * accA2[f][3] + ba1 };
        float2 ob0 = { accB[f][0] + bb0, accB[f][1] + bb1 };
        float2 ob1 = { accB[f][2] + bb0, accB[f][3] + bb1 };

        *(float2*)&outA[r0 * EG + n] = oa0;
        *(float2*)&outA[r1 * EG + n] = oa1;
        *(float2*)&outB[r0 * EG + n] = ob0;
        *(float2*)&outB[r1 * EG + n] = ob1;
    }
}

// ---------------------------------------------------------------------------
// RoPE applied in place to g_qa, g_qb, g_ka, g_kb (fp32 throughout).
// ---------------------------------------------------------------------------
__global__ __launch_bounds__(256) void rope_kernel()
{
    const int PAIRS = MG * (EG / 2);
    int tt = blockIdx.x * blockDim.x + threadIdx.x;
    if (tt >= 4 * PAIRS) return;

    const int w = tt / PAIRS;
    const int p = tt % PAIRS;
    float* X = (w == 0) ? g_qa : (w == 1) ? g_qb : (w == 2) ? g_ka : g_kb;

    const int row = p >> 9;
    const int pp  = p & 511;
    const int h   = pp >> 5;
    const int i   = pp & 31;
    const int s   = row & (SG - 1);

    const float freq = exp2f(-(float)i * (13.287712379549449f / 32.0f));
    float sn, cs;
    sincosf((float)s * freq, &sn, &cs);

    const int base = row * EG + h * DH + i;
    const float x1 = X[base];
    const float x2 = X[base + 32];
    X[base]      = x1 * cs - x2 * sn;
    X[base + 32] = x2 * cs + x1 * sn;
}

// ---------------------------------------------------------------------------
// prep_k: post-rope K -> bf16 hi/lo (ka, kb, kj = j2h(h)*kb), same layout.
// ---------------------------------------------------------------------------
__global__ __launch_bounds__(256) void prep_k_kernel(const float* __restrict__ thetas_head)
{
    const int t = blockIdx.x * 256 + threadIdx.x;
    const int row = t >> 8;
    const int c4  = (t & 255) << 2;
    const int h   = c4 >> 6;
    const float j2h = sinf(2.0f * thetas_head[h]) - 1.0f;

    const size_t off = (size_t)row * EG + c4;
    float4 ka = *(const float4*)&g_ka[off];
    float4 kb = *(const float4*)&g_kb[off];
    float4 kj = { j2h * kb.x, j2h * kb.y, j2h * kb.z, j2h * kb.w };

    *(uint2*)&g_kaH[off] = make_uint2(pack_hi2(ka.x, ka.y), pack_hi2(ka.z, ka.w));
    *(uint2*)&g_kaL[off] = make_uint2(pack_lo2(ka.x, ka.y), pack_lo2(ka.z, ka.w));
    *(uint2*)&g_kbH[off] = make_uint2(pack_hi2(kb.x, kb.y), pack_hi2(kb.z, kb.w));
    *(uint2*)&g_kbL[off] = make_uint2(pack_lo2(kb.x, kb.y), pack_lo2(kb.z, kb.w));
    *(uint2*)&g_kjH[off] = make_uint2(pack_hi2(kj.x, kj.y), pack_hi2(kj.z, kj.w));
    *(uint2*)&g_kjL[off] = make_uint2(pack_lo2(kj.x, kj.y), pack_lo2(kj.z, kj.w));
}

// ---------------------------------------------------------------------------
// prep_v: V -> bf16 hi/lo TRANSPOSED to [b,h,d,s] (s contiguous).
// ---------------------------------------------------------------------------
__global__ __launch_bounds__(256) void prep_v_kernel()
{
    const int t = blockIdx.x * 256 + threadIdx.x;
    const int bhd = t >> 8;
    const int s4  = (t & 255) << 2;
    const int b   = bhd >> 10;
    const int hd  = bhd & 1023;

    const size_t ib = ((size_t)b * SG + s4) * EG + hd;
    float a0 = g_va[ib], a1 = g_va[ib + EG], a2 = g_va[ib + 2 * EG], a3 = g_va[ib + 3 * EG];
    float b0 = g_vb[ib], b1 = g_vb[ib + EG], b2 = g_vb[ib + 2 * EG], b3 = g_vb[ib + 3 * EG];

    const size_t ob = (size_t)bhd * SG + s4;
    *(uint2*)&g_vaTH[ob] = make_uint2(pack_hi2(a0, a1), pack_hi2(a2, a3));
    *(uint2*)&g_vaTL[ob] = make_uint2(pack_lo2(a0, a1), pack_lo2(a2, a3));
    *(uint2*)&g_vbTH[ob] = make_uint2(pack_hi2(b0, b1), pack_hi2(b2, b3));
    *(uint2*)&g_vbTL[ob] = make_uint2(pack_lo2(b0, b1), pack_lo2(b2, b3));
}

// ---------------------------------------------------------------------------
// Tensor-core flash attention (R14-validated).
// ---------------------------------------------------------------------------
#define KSTR 72
#define VSTR 40

__global__ __launch_bounds__(256) void attn_mma_kernel(const float* __restrict__ thetas_head)
{
    __shared__ __nv_bfloat16 sKaH[32 * KSTR], sKaL[32 * KSTR];
    __shared__ __nv_bfloat16 sKbH[32 * KSTR], sKbL[32 * KSTR];
    __shared__ __nv_bfloat16 sKjH[32 * KSTR], sKjL[32 * KSTR];
    __shared__ __nv_bfloat16 sVaH[64 * VSTR], sVaL[64 * VSTR];
    __shared__ __nv_bfloat16 sVbH[64 * VSTR], sVbL[64 * VSTR];

    const int b   = blockIdx.z;
    const int h   = blockIdx.y;
    const int r0  = ((int)gridDim.x - 1 - (int)blockIdx.x) * 128;   // heavy tiles first
    const int tid = threadIdx.x;
    const int lane = tid & 31;
    const int wid  = tid >> 5;
    const int g = lane >> 2;
    const int t = lane & 3;

    const int koff = ((lane & 7) + ((lane & 16) >> 1)) * KSTR + (((lane >> 3) & 1) << 3);
    const int voff = ((lane & 7) + ((lane & 16) >> 1)) * VSTR + (((lane >> 3) & 1) << 3);

    unsigned qaH[4][4], qaL[4][4], qbH[4][4], qbL[4][4];
    {
        const int row0 = r0 + wid * 16 + g;
        const int base0 = (b * SG + row0) * EG + h * DH;
        const int base1 = base0 + 8 * EG;
        #pragma unroll
        for (int ks = 0; ks < 4; ks++) {
            const int col = ks * 16 + 2 * t;
            float2 a0 = *(const float2*)&g_qa[base0 + col];
            float2 a1 = *(const float2*)&g_qa[base1 + col];
            float2 a2 = *(const float2*)&g_qa[base0 + col + 8];
            float2 a3 = *(const float2*)&g_qa[base1 + col + 8];
            qaH[ks][0] = pack_hi2(a0.x, a0.y); qaL[ks][0] = pack_lo2(a0.x, a0.y);
            qaH[ks][1] = pack_hi2(a1.x, a1.y); qaL[ks][1] = pack_lo2(a1.x, a1.y);
            qaH[ks][2] = pack_hi2(a2.x, a2.y); qaL[ks][2] = pack_lo2(a2.x, a2.y);
            qaH[ks][3] = pack_hi2(a3.x, a3.y); qaL[ks][3] = pack_lo2(a3.x, a3.y);
            float2 b0 = *(const float2*)&g_qb[base0 + col];
            float2 b1 = *(const float2*)&g_qb[base1 + col];
            float2 b2 = *(const float2*)&g_qb[base0 + col + 8];
            float2 b3 = *(const float2*)&g_qb[base1 + col + 8];
            qbH[ks][0] = pack_hi2(b0.x, b0.y); qbL[ks][0] = pack_lo2(b0.x, b0.y);
            qbH[ks][1] = pack_hi2(b1.x, b1.y); qbL[ks][1] = pack_lo2(b1.x, b1.y);
            qbH[ks][2] = pack_hi2(b2.x, b2.y); qbL[ks][2] = pack_lo2(b2.x, b2.y);
            qbH[ks][3] = pack_hi2(b3.x, b3.y); qbL[ks][3] = pack_lo2(b3.x, b3.y);
        }
    }

    float oa[8][4] = {};
    float ob[8][4] = {};
    float mrow0 = -1e30f, mrow1 = -1e30f;
    float lrow0 = 0.0f,   lrow1 = 0.0f;

    const int ntiles = (r0 >> 5) + 4;
    for (int tile = 0; tile < ntiles; tile++) {
        const int k0 = tile * 32;

        __syncthreads();

        #pragma unroll
        for (int it = 0; it < 2; it++) {
            const int idx = tid + it * 256;
            const int n  = idx >> 4;
            const int d4 = (idx & 15) << 2;
            const size_t ga = (size_t)(b * SG + k0 + n) * EG + h * DH + d4;
            const int si = n * KSTR + d4;
            *(uint2*)&sKaH[si] = *(const uint2*)&g_kaH[ga];
            *(uint2*)&sKaL[si] = *(const uint2*)&g_kaL[ga];
            *(uint2*)&sKbH[si] = *(const uint2*)&g_kbH[ga];
            *(uint2*)&sKbL[si] = *(const uint2*)&g_kbL[ga];
            *(uint2*)&sKjH[si] = *(const uint2*)&g_kjH[ga];
            *(uint2*)&sKjL[si] = *(const uint2*)&g_kjL[ga];
        }
        #pragma unroll
        for (int it = 0; it < 2; it++) {
            const int idx = tid + it * 256;
            const int d  = idx >> 3;
            const int s4 = (idx & 7) << 2;
            const size_t ga = ((size_t)(b * HG + h) * DH + d) * SG + k0 + s4;
            const int si = d * VSTR + s4;
            *(uint2*)&sVaH[si] = *(const uint2*)&g_vaTH[ga];
            *(uint2*)&sVaL[si] = *(const uint2*)&g_vaTL[ga];
            *(uint2*)&sVbH[si] = *(const uint2*)&g_vbTH[ga];
            *(uint2*)&sVbL[si] = *(const uint2*)&g_vbTL[ga];
        }
        __syncthreads();

        const int wrow = r0 + wid * 16;
        if (k0 > wrow + 15) continue;

        float sa[4][4] = {};
        float sb[4][4] = {};
        #pragma unroll
        for (int ks = 0; ks < 4; ks++) {
            const int sk = ks * 16;
            #pragma unroll
            for (int pb = 0; pb < 2; pb++) {
                const int ko = pb * 16 * KSTR + koff + sk;
                unsigned kaH[4], kaL[4], kbH[4], kbL[4], kjH[4], kjL[4];
                ldsm_x4(kaH, sKaH + ko);
                ldsm_x4(kaL, sKaL + ko);
                ldsm_x4(kbH, sKbH + ko);
                ldsm_x4(kbL, sKbL + ko);
                ldsm_x4(kjH, sKjH + ko);
                ldsm_x4(kjL, sKjL + ko);

                #pragma unroll
                for (int half = 0; half < 2; half++) {
                    const int nf = pb * 2 + half;
                    const int o = half * 2;
                    mma_bf16(sa[nf], qaH[ks], kaH + o);
                    mma_bf16(sb[nf], qaH[ks], kbH + o);
                    mma_bf16(sa[nf], qaH[ks], kaL + o);
                    mma_bf16(sb[nf], qaH[ks], kbL + o);
                    mma_bf16(sa[nf], qaL[ks], kaH + o);
                    mma_bf16(sb[nf], qaL[ks], kbH + o);
                    mma_bf16(sa[nf], qbH[ks], kjH + o);
                    mma_bf16(sb[nf], qbH[ks], kaH + o);
                    mma_bf16(sa[nf], qbH[ks], kjL + o);
                    mma_bf16(sb[nf], qbH[ks], kaL + o);
                    mma_bf16(sa[nf], qbL[ks], kjH + o);
                    mma_bf16(sb[nf], qbL[ks], kaH + o);
                }
            }
        }

        const bool full = (k0 + 31 <= wrow);
        float mt0 = -1e30f, mt1 = -1e30f;
        #pragma unroll
        for (int nf = 0; nf < 4; nf++) {
            #pragma unroll
            for (int c = 0; c < 4; c++) {
                float v = sqrtf(sa[nf][c] * sa[nf][c] + sb[nf][c] * sb[nf][c] + 1e-8f) * 0.125f;
                if (!full) {
                    const int col = k0 + nf * 8 + 2 * t + (c & 1);
                    const int row = wrow + g + ((c & 2) ? 8 : 0);
                    if (col > row) v = -1e9f;
                }
                sa[nf][c] = v;
                if (c & 2) mt1 = fmaxf(mt1, v); else mt0 = fmaxf(mt0, v);
            }
        }
        mt0 = fmaxf(mt0, __shfl_xor_sync(0xffffffffu, mt0, 1));
        mt0 = fmaxf(mt0, __shfl_xor_sync(0xffffffffu, mt0, 2));
        mt1 = fmaxf(mt1, __shfl_xor_sync(0xffffffffu, mt1, 1));
        mt1 = fmaxf(mt1, __shfl_xor_sync(0xffffffffu, mt1, 2));

        const float mn0 = fmaxf(mrow0, mt0);
        const float mn1 = fmaxf(mrow1, mt1);

        float ps0 = 0.0f, ps1 = 0.0f;
        #pragma unroll
        for (int nf = 0; nf < 4; nf++) {
            #pragma unroll
            for (int c = 0; c < 4; c++) {
                const float p = __expf(sa[nf][c] - ((c & 2) ? mn1 : mn0));
                sa[nf][c] = p;
                if (c & 2) ps1 += p; else ps0 += p;
            }
        }
        ps0 += __shfl_xor_sync(0xffffffffu, ps0, 1);
        ps0 += __shfl_xor_sync(0xffffffffu, ps0, 2);
        ps1 += __shfl_xor_sync(0xffffffffu, ps1, 1);
        ps1 += __shfl_xor_sync(0xffffffffu, ps1, 2);

        const float sc0 = __expf(mrow0 - mn0);
        const float sc1 = __expf(mrow1 - mn1);
        lrow0 = lrow0 * sc0 + ps0;  mrow0 = mn0;
        lrow1 = lrow1 * sc1 + ps1;  mrow1 = mn1;
        #pragma unroll
        for (int nf = 0; nf < 8; nf++) {
            oa[nf][0] *= sc0; oa[nf][1] *= sc0; oa[nf][2] *= sc1; oa[nf][3] *= sc1;
            ob[nf][0] *= sc0; ob[nf][1] *= sc0; ob[nf][2] *= sc1; ob[nf][3] *= sc1;
        }

        unsigned pH[2][4], pL[2][4];
        #pragma unroll
        for (int kc = 0; kc < 2; kc++) {
            const int f = 2 * kc;
            pH[kc][0] = pack_hi2(sa[f][0],     sa[f][1]);
            pL[kc][0] = pack_lo2(sa[f][0],     sa[f][1]);
            pH[kc][1] = pack_hi2(sa[f][2],     sa[f][3]);
            pL[kc][1] = pack_lo2(sa[f][2],     sa[f][3]);
            pH[kc][2] = pack_hi2(sa[f + 1][0], sa[f + 1][1]);
            pL[kc][2] = pack_lo2(sa[f + 1][0], sa[f + 1][1]);
            pH[kc][3] = pack_hi2(sa[f + 1][2], sa[f + 1][3]);
            pL[kc][3] = pack_lo2(sa[f + 1][2], sa[f + 1][3]);
        }

        #pragma unroll
        for (int pv = 0; pv < 4; pv++) {
            #pragma unroll
            for (int kc = 0; kc < 2; kc++) {
                const int vo = pv * 16 * VSTR + voff + kc * 16;
                unsigned vaH[4], vaL[4], vbH[4], vbL[4];
                ldsm_x4(vaH, sVaH + vo);
                ldsm_x4(vaL, sVaL + vo);
                ldsm_x4(vbH, sVbH + vo);
                ldsm_x4(vbL, sVbL + vo);

                #pragma unroll
                for (int half = 0; half < 2; half++) {
                    const int nf = pv * 2 + half;
                    const int o = half * 2;
                    mma_bf16(oa[nf], pH[kc], vaH + o);
                    mma_bf16(ob[nf], pH[kc], vbH + o);
                    mma_bf16(oa[nf], pL[kc], vaH + o);
                    mma_bf16(ob[nf], pL[kc], vbH + o);
                    mma_bf16(oa[nf], pH[kc], vaL + o);
                    mma_bf16(ob[nf], pH[kc], vbL + o);
                }
            }
        }
    }

    // epilogue: write bf16 hi/lo directly (identical split of the fp32 value)
    const float inv0 = 1.0f / lrow0;
    const float inv1 = 1.0f / lrow1;
    const int row0 = r0 + wid * 16 + g;
    const int base0 = (b * SG + row0) * EG + h * DH;
    const int base1 = base0 + 8 * EG;
    __nv_bfloat16* xh4 = g_xH[4];  __nv_bfloat16* xl4 = g_xL[4];
    __nv_bfloat16* xh5 = g_xH[5];  __nv_bfloat16* xl5 = g_xL[5];
    #pragma unroll
    for (int nf = 0; nf < 8; nf++) {
        const int d = nf * 8 + 2 * t;
        float a00 = oa[nf][0] * inv0, a01 = oa[nf][1] * inv0;
        float a10 = oa[nf][2] * inv1, a11 = oa[nf][3] * inv1;
        float b00 = ob[nf][0] * inv0, b01 = ob[nf][1] * inv0;
        float b10 = ob[nf][2] * inv1, b11 = ob[nf][3] * inv1;
        *(unsigned*)&xh4[base0 + d] = pack_hi2(a00, a01);
        *(unsigned*)&xl4[base0 + d] = pack_lo2(a00, a01);
        *(unsigned*)&xh4[base1 + d] = pack_hi2(a10, a11);
        *(unsigned*)&xl4[base1 + d] = pack_lo2(a10, a11);
        *(unsigned*)&xh5[base0 + d] = pack_hi2(b00, b01);
        *(unsigned*)&xl5[base0 + d] = pack_lo2(b00, b01);
        *(unsigned*)&xh5[base1 + d] = pack_hi2(b10, b11);
        *(unsigned*)&xl5[base1 + d] = pack_lo2(b10, b11);
    }
    (void)thetas_head;
}

// ---------------------------------------------------------------------------
extern "C" void kernel_launch(void* const* d_in, const int* in_sizes, int n_in,
                              void* d_out, int out_size)
{
    const float* x_q_a  = (const float*)d_in[0];
    const float* x_q_b  = (const float*)d_in[1];
    const float* x_kv_a = (const float*)d_in[2];
    const float* x_kv_b = (const float*)d_in[3];
    // d_in[4] = mask -- causal, encoded in the attention kernel
    const float* layer_theta = (const float*)d_in[5];
    const float* thetas_head = (const float*)d_in[6];
    const float* q_wa = (const float*)d_in[7];
    const float* q_wb = (const float*)d_in[8];
    const float* q_ba = (const float*)d_in[9];
    const float* q_bb = (const float*)d_in[10];
    const float* k_wa = (const float*)d_in[11];
    const float* k_wb = (const float*)d_in[12];
    const float* k_ba = (const float*)d_in[13];
    const float* k_bb = (const float*)d_in[14];
    const float* v_wa = (const float*)d_in[15];
    const float* v_wb = (const float*)d_in[16];
    const float* v_ba = (const float*)d_in[17];
    const float* v_bb = (const float*)d_in[18];
    const float* o_wa = (const float*)d_in[19];
    const float* o_wb = (const float*)d_in[20];
    const float* o_ba = (const float*)d_in[21];
    const float* o_bb = (const float*)d_in[22];

    float *qa, *qb, *ka, *kb, *va, *vb;
    cudaGetSymbolAddress((void**)&qa, g_qa);
    cudaGetSymbolAddress((void**)&qb, g_qb);
    cudaGetSymbolAddress((void**)&ka, g_ka);
    cudaGetSymbolAddress((void**)&kb, g_kb);
    cudaGetSymbolAddress((void**)&va, g_va);
    cudaGetSymbolAddress((void**)&vb, g_vb);

    __nv_bfloat16 *wH, *wL, *xH, *xL;
    cudaGetSymbolAddress((void**)&wH, g_wH);
    cudaGetSymbolAddress((void**)&wL, g_wL);
    cudaGetSymbolAddress((void**)&xH, g_xH);
    cudaGetSymbolAddress((void**)&xL, g_xL);
    const size_t WSZ = (size_t)EG * EG;
    const size_t XSZ = (size_t)MG * EG;
    auto whi = [&](int i) { return wH + i * WSZ; };
    auto wlo = [&](int i) { return wL + i * WSZ; };
    auto xhi = [&](int i) { return xH + i * XSZ; };
    auto xlo = [&](int i) { return xL + i * XSZ; };

    float* outA = (float*)d_out;
    float* outB = (float*)d_out + (size_t)MG * EG;

    const int GSMEM = 2 * 8 * TILE_HF * (int)sizeof(__nv_bfloat16);  // 81920
    cudaFuncSetAttribute(qc_gemm_bf16_kernel,
                         cudaFuncAttributeMaxDynamicSharedMemorySize, GSMEM);

    // ---- streams/events for graph-capturable fork/join (created once) ----
    static cudaStream_t s1 = nullptr, s2 = nullptr;
    static cudaEvent_t ev0 = nullptr, ev_w = nullptr, ev_x = nullptr,
                       ev_k = nullptr, ev_pv = nullptr;
    if (s1 == nullptr) {
        cudaStreamCreateWithFlags(&s1, cudaStreamNonBlocking);
        cudaStreamCreateWithFlags(&s2, cudaStreamNonBlocking);
        cudaEventCreateWithFlags(&ev0,  cudaEventDisableTiming);
        cudaEventCreateWithFlags(&ev_w, cudaEventDisableTiming);
        cudaEventCreateWithFlags(&ev_x, cudaEventDisableTiming);
        cudaEventCreateWithFlags(&ev_k, cudaEventDisableTiming);
        cudaEventCreateWithFlags(&ev_pv, cudaEventDisableTiming);
    }

    // fork
    cudaEventRecord(ev0, 0);
    cudaStreamWaitEvent(s1, ev0, 0);
    cudaStreamWaitEvent(s2, ev0, 0);

    // ---- split weights (s0) || split activations (s1) ----
    {
        SplitBatch sb = {};
        const float* srcs[8] = { q_wa, q_wb, k_wa, k_wb, v_wa, v_wb, o_wa, o_wb };
        for (int i = 0; i < 8; i++) { sb.src[i] = srcs[i]; sb.hi[i] = whi(i); sb.lo[i] = wlo(i); }
        split_kernel<<<dim3((unsigned)(WSZ / 4 / 256), 8), 256, 0, 0>>>(sb, (int)(WSZ / 4));
    }
    cudaEventRecord(ev_w, 0);
    {
        SplitBatch sb = {};
        const float* srcs[4] = { x_q_a, x_q_b, x_kv_a, x_kv_b };
        for (int i = 0; i < 4; i++) { sb.src[i] = srcs[i]; sb.hi[i] = xhi(i); sb.lo[i] = xlo(i); }
        split_kernel<<<dim3((unsigned)(XSZ / 4 / 256), 4), 256, 0, s1>>>(sb, (int)(XSZ / 4));
    }
    cudaEventRecord(ev_x, s1);

    const dim3 gg(EG / 64, MG / 64);

    // q on s0 (needs weights [s0-ordered] + acts [ev_x])
    cudaStreamWaitEvent(0, ev_x, 0);
    qc_gemm_bf16_kernel<<<gg, 256, GSMEM, 0>>>(
        xhi(0), xlo(0), xhi(1), xlo(1), whi(0), wlo(0), whi(1), wlo(1),
        q_ba, q_bb, layer_theta, qa, qb);
    // k on s1 (needs acts [s1-ordered] + weights [ev_w])
    cudaStreamWaitEvent(s1, ev_w, 0);
    qc_gemm_bf16_kernel<<<gg, 256, GSMEM, s1>>>(
        xhi(2), xlo(2), xhi(3), xlo(3), whi(2), wlo(2), whi(3), wlo(3),
        k_ba, k_bb, layer_theta, ka, kb);
    cudaEventRecord(ev_k, s1);
    // v on s2 (needs both)
    cudaStreamWaitEvent(s2, ev_w, 0);
    cudaStreamWaitEvent(s2, ev_x, 0);
    qc_gemm_bf16_kernel<<<gg, 256, GSMEM, s2>>>(
        xhi(2), xlo(2), xhi(3), xlo(3), whi(4), wlo(4), whi(5), wlo(5),
        v_ba, v_bb, layer_theta, va, vb);
    prep_v_kernel<<<(MG * EG / 4) / 256, 256, 0, s2>>>();
    cudaEventRecord(ev_pv, s2);

    // rope (q [s0-ordered] + k [ev_k]) then prep_k, on s0 -- overlaps v/prep_v
    cudaStreamWaitEvent(0, ev_k, 0);
    rope_kernel<<<(4 * MG * (EG / 2)) / 256, 256, 0, 0>>>();
    prep_k_kernel<<<(MG * EG / 4) / 256, 256, 0, 0>>>(thetas_head);

    // attention joins s2 via ev_pv
    cudaStreamWaitEvent(0, ev_pv, 0);
    attn_mma_kernel<<<dim3(SG / 128, HG, 2), 256, 0, 0>>>(thetas_head);

    // output projection straight into d_out (out_a then out_b)
    qc_gemm_bf16_kernel<<<gg, 256, GSMEM, 0>>>(
        xhi(4), xlo(4), xhi(5), xlo(5), whi(6), wlo(6), whi(7), wlo(7),
        o_ba, o_bb, layer_theta, outA, outB);
}

// round 16
// speedup vs baseline: 1.4254x; 1.0294x over previous
#include <cuda_runtime.h>
#include <cuda_bf16.h>
#include <math.h>

// Problem constants
#define EG 1024      // embed dim
#define MG 2048      // B*S rows
#define SG 1024      // seq len
#define HG 16        // heads
#define DH 64        // head dim

// ---------------- scratch (device globals: no runtime allocation allowed) ----
__device__ float g_qa[MG * EG];
__device__ float g_qb[MG * EG];
__device__ float g_ka[MG * EG];
__device__ float g_kb[MG * EG];
__device__ float g_va[MG * EG];
__device__ float g_vb[MG * EG];

// pre-split bf16 hi/lo buffers
// weights: 0 q_wa, 1 q_wb, 2 k_wa, 3 k_wb, 4 v_wa, 5 v_wb, 6 o_wa, 7 o_wb
__device__ __nv_bfloat16 g_wH[8][EG * EG];
__device__ __nv_bfloat16 g_wL[8][EG * EG];
// activations: 0 x_q_a, 1 x_q_b, 2 x_kv_a, 3 x_kv_b, 4 oa, 5 ob
__device__ __nv_bfloat16 g_xH[6][MG * EG];
__device__ __nv_bfloat16 g_xL[6][MG * EG];

// attention pre-split buffers (post-rope K, j2h folded; V transposed [b,h,d,s])
__device__ __nv_bfloat16 g_kaH[MG * EG], g_kaL[MG * EG];
__device__ __nv_bfloat16 g_kbH[MG * EG], g_kbL[MG * EG];
__device__ __nv_bfloat16 g_kjH[MG * EG], g_kjL[MG * EG];
__device__ __nv_bfloat16 g_vaTH[MG * EG], g_vaTL[MG * EG];
__device__ __nv_bfloat16 g_vbTH[MG * EG], g_vbTL[MG * EG];

// split-K attention partials: [half][b][h][row] (+ [d] for acc)
__device__ float g_pm[2 * 2 * HG * SG];
__device__ float g_pl[2 * 2 * HG * SG];
__device__ float g_poa[(size_t)2 * 2 * HG * SG * DH];
__device__ float g_pob[(size_t)2 * 2 * HG * SG * DH];

// ---------------------------------------------------------------------------
// helpers
// ---------------------------------------------------------------------------
__device__ __forceinline__ void mma_bf16(float* c, const unsigned* a, const unsigned* b)
{
    asm volatile(
        "mma.sync.aligned.m16n8k16.row.col.f32.bf16.bf16.f32 "
        "{%0,%1,%2,%3}, {%4,%5,%6,%7}, {%8,%9}, {%0,%1,%2,%3};"
        : "+f"(c[0]), "+f"(c[1]), "+f"(c[2]), "+f"(c[3])
        : "r"(a[0]), "r"(a[1]), "r"(a[2]), "r"(a[3]),
          "r"(b[0]), "r"(b[1]));
}

__device__ __forceinline__ void ldsm_x4(unsigned* r, const __nv_bfloat16* p)
{
    unsigned addr = (unsigned)__cvta_generic_to_shared(p);
    asm volatile("ldmatrix.sync.aligned.m8n8.x4.shared.b16 {%0,%1,%2,%3}, [%4];"
                 : "=r"(r[0]), "=r"(r[1]), "=r"(r[2]), "=r"(r[3]) : "r"(addr));
}

__device__ __forceinline__ unsigned pack_hi2(float x, float y)
{
    __nv_bfloat162 h(__float2bfloat16(x), __float2bfloat16(y));
    return *reinterpret_cast<unsigned*>(&h);
}
__device__ __forceinline__ unsigned pack_lo2(float x, float y)
{
    float hx = __bfloat162float(__float2bfloat16(x));
    float hy = __bfloat162float(__float2bfloat16(y));
    __nv_bfloat162 l(__float2bfloat16(x - hx), __float2bfloat16(y - hy));
    return *reinterpret_cast<unsigned*>(&l);
}

__device__ __forceinline__ void cp_async16(unsigned daddr, const void* src)
{
    asm volatile("cp.async.cg.shared.global [%0], [%1], 16;" :: "r"(daddr), "l"(src));
}
__device__ __forceinline__ void cp_commit()
{
    asm volatile("cp.async.commit_group;");
}
template<int N>
__device__ __forceinline__ void cp_wait()
{
    asm volatile("cp.async.wait_group %0;" :: "n"(N));
}

// smem tile strides (bf16 halfword units). BK=32 + pad 8 -> conflict-free frags.
#define TSTR 40
#define TILE_HF (64 * TSTR)

// ---------------------------------------------------------------------------
// Batched fp32 -> bf16 hi/lo split. blockIdx.y selects the tensor.
// ---------------------------------------------------------------------------
struct SplitBatch {
    const float* src[8];
    __nv_bfloat16* hi[8];
    __nv_bfloat16* lo[8];
};

__global__ __launch_bounds__(256) void split_kernel(SplitBatch sb, int nvec)
{
    const int t = blockIdx.x * 256 + threadIdx.x;
    if (t >= nvec) return;
    const int w = blockIdx.y;
    const float4 v = reinterpret_cast<const float4*>(sb.src[w])[t];

    unsigned h0 = pack_hi2(v.x, v.y);
    unsigned h1 = pack_hi2(v.z, v.w);
    unsigned l0 = pack_lo2(v.x, v.y);
    unsigned l1 = pack_lo2(v.z, v.w);

    reinterpret_cast<uint2*>(sb.hi[w])[t] = make_uint2(h0, h1);
    reinterpret_cast<uint2*>(sb.lo[w])[t] = make_uint2(l0, l1);
}

// ---------------------------------------------------------------------------
// Fused quaternion-complex dense on tensor cores (R15-validated, 158us).
// ---------------------------------------------------------------------------
__global__ __launch_bounds__(256, 2) void qc_gemm_bf16_kernel(
    const __nv_bfloat16* __restrict__ xaH, const __nv_bfloat16* __restrict__ xaL,
    const __nv_bfloat16* __restrict__ xbH, const __nv_bfloat16* __restrict__ xbL,
    const __nv_bfloat16* __restrict__ waH, const __nv_bfloat16* __restrict__ waL,
    const __nv_bfloat16* __restrict__ wbH, const __nv_bfloat16* __restrict__ wbL,
    const float* __restrict__ ba, const float* __restrict__ bb,
    const float* __restrict__ theta_ptr,
    float* __restrict__ outA, float* __restrict__ outB)
{
    extern __shared__ __nv_bfloat16 sbuf[];

    const int tid = threadIdx.x;
    const int lane = tid & 31;
    const int wid = tid >> 5;
    const int warp_m = wid >> 1;
    const int warp_n = wid & 1;
    const int g = lane >> 2;
    const int t = lane & 3;

    const int m0 = blockIdx.y * 64;
    const int n0 = blockIdx.x * 64;

    const float j2 = sinf(2.0f * theta_ptr[0]) - 1.0f;

    const int aoff = (warp_m * 16 + (lane & 15)) * TSTR + ((lane >> 4) << 3);
    const int boff = ((lane & 7) + ((lane & 16) >> 1)) * TSTR + (((lane >> 3) & 1) << 3);

    const int losel = tid >> 7;           // 0 hi, 1 lo
    const int tt    = tid & 127;
    const int lr0   = tt >> 2;            // rows 0..31 (chunk j=0)
    const int lc0   = (tt & 3) << 3;      // cols 0,8,16,24 (elements)

    const __nv_bfloat16* sxa = (losel ? xaL : xaH) + (size_t)(m0 + lr0) * EG + lc0;
    const __nv_bfloat16* sxb = (losel ? xbL : xbH) + (size_t)(m0 + lr0) * EG + lc0;
    const __nv_bfloat16* swa = (losel ? waL : waH) + (size_t)(n0 + lr0) * EG + lc0;
    const __nv_bfloat16* swb = (losel ? wbL : wbH) + (size_t)(n0 + lr0) * EG + lc0;
    const size_t GROW = (size_t)32 * EG;

    const int doff0 = lr0 * TSTR + lc0;
    const int doff1 = doff0 + 32 * TSTR;
    unsigned dxa[2][2], dxb[2][2], dwa[2][2], dwb[2][2];
    #pragma unroll
    for (int st = 0; st < 2; st++) {
        __nv_bfloat16* base = sbuf + st * 8 * TILE_HF;
        __nv_bfloat16* bxa = base + (0 + losel) * TILE_HF;
        __nv_bfloat16* bxb = base + (2 + losel) * TILE_HF;
        __nv_bfloat16* bwa = base + (4 + losel) * TILE_HF;
        __nv_bfloat16* bwb = base + (6 + losel) * TILE_HF;
        dxa[st][0] = (unsigned)__cvta_generic_to_shared(bxa + doff0);
        dxa[st][1] = (unsigned)__cvta_generic_to_shared(bxa + doff1);
        dxb[st][0] = (unsigned)__cvta_generic_to_shared(bxb + doff0);
        dxb[st][1] = (unsigned)__cvta_generic_to_shared(bxb + doff1);
        dwa[st][0] = (unsigned)__cvta_generic_to_shared(bwa + doff0);
        dwa[st][1] = (unsigned)__cvta_generic_to_shared(bwa + doff1);
        dwb[st][0] = (unsigned)__cvta_generic_to_shared(bwb + doff0);
        dwb[st][1] = (unsigned)__cvta_generic_to_shared(bwb + doff1);
    }

    float accA1[4][4] = {};
    float accA2[4][4] = {};
    float accB [4][4] = {};

    cp_async16(dxa[0][0], sxa);          cp_async16(dxa[0][1], sxa + GROW);
    cp_async16(dxb[0][0], sxb);          cp_async16(dxb[0][1], sxb + GROW);
    cp_async16(dwa[0][0], swa);          cp_async16(dwa[0][1], swa + GROW);
    cp_async16(dwb[0][0], swb);          cp_async16(dwb[0][1], swb + GROW);
    cp_commit();

#define QC_MMA_BLOCK(f0, f1) \
    mma_bf16(accA1[f0], aXaH, bWaH + 0);  mma_bf16(accA1[f1], aXaH, bWaH + 2); \
    mma_bf16(accA2[f0], aXbH, bWbH + 0);  mma_bf16(accA2[f1], aXbH, bWbH + 2); \
    mma_bf16(accB [f0], aXaH, bWbH + 0);  mma_bf16(accB [f1], aXaH, bWbH + 2); \
    mma_bf16(accA1[f0], aXaH, bWaL + 0);  mma_bf16(accA1[f1], aXaH, bWaL + 2); \
    mma_bf16(accA2[f0], aXbH, bWbL + 0);  mma_bf16(accA2[f1], aXbH, bWbL + 2); \
    mma_bf16(accB [f0], aXbH, bWaH + 0);  mma_bf16(accB [f1], aXbH, bWaH + 2); \
    mma_bf16(accA1[f0], aXaL, bWaH + 0);  mma_bf16(accA1[f1], aXaL, bWaH + 2); \
    mma_bf16(accA2[f0], aXbL, bWbH + 0);  mma_bf16(accA2[f1], aXbL, bWbH + 2); \
    mma_bf16(accB [f0], aXaH, bWbL + 0);  mma_bf16(accB [f1], aXaH, bWbL + 2); \
    mma_bf16(accB [f0], aXbH, bWaL + 0);  mma_bf16(accB [f1], aXbH, bWaL + 2); \
    mma_bf16(accB [f0], aXaL, bWbH + 0);  mma_bf16(accB [f1], aXaL, bWbH + 2); \
    mma_bf16(accB [f0], aXbL, bWaH + 0);  mma_bf16(accB [f1], aXbL, bWaH + 2)

#define QC_LD_A(sk) \
    ldsm_x4(aXaH, sXaH + aoff + (sk)); ldsm_x4(aXaL, sXaL + aoff + (sk)); \
    ldsm_x4(aXbH, sXbH + aoff + (sk)); ldsm_x4(aXbL, sXbL + aoff + (sk))

#define QC_LD_B(bo) \
    ldsm_x4(bWaH, sWaH + (bo)); ldsm_x4(bWaL, sWaL + (bo)); \
    ldsm_x4(bWbH, sWbH + (bo)); ldsm_x4(bWbL, sWbL + (bo))

    const int NIT = EG / 32;
    for (int it = 0; it < NIT; it++) {
        const int cur = it & 1;
        if (it + 1 < NIT) {
            const int nk = (it + 1) * 32;
            const int ns = 1 - cur;
            cp_async16(dxa[ns][0], sxa + nk);   cp_async16(dxa[ns][1], sxa + nk + GROW);
            cp_async16(dxb[ns][0], sxb + nk);   cp_async16(dxb[ns][1], sxb + nk + GROW);
            cp_async16(dwa[ns][0], swa + nk);   cp_async16(dwa[ns][1], swa + nk + GROW);
            cp_async16(dwb[ns][0], swb + nk);   cp_async16(dwb[ns][1], swb + nk + GROW);
            cp_commit();
            cp_wait<1>();
        } else {
            cp_wait<0>();
        }
        __syncthreads();

        const __nv_bfloat16* cb = sbuf + cur * 8 * TILE_HF;
        const __nv_bfloat16* sXaH = cb + 0 * TILE_HF;
        const __nv_bfloat16* sXaL = cb + 1 * TILE_HF;
        const __nv_bfloat16* sXbH = cb + 2 * TILE_HF;
        const __nv_bfloat16* sXbL = cb + 3 * TILE_HF;
        const __nv_bfloat16* sWaH = cb + 4 * TILE_HF;
        const __nv_bfloat16* sWaL = cb + 5 * TILE_HF;
        const __nv_bfloat16* sWbH = cb + 6 * TILE_HF;
        const __nv_bfloat16* sWbL = cb + 7 * TILE_HF;

        unsigned aXaH[4], aXaL[4], aXbH[4], aXbL[4];
        unsigned bWaH[4], bWaL[4], bWbH[4], bWbL[4];
        const int bo0 = (warp_n * 32) * TSTR + boff;
        const int bo1 = (warp_n * 32 + 16) * TSTR + boff;

        QC_LD_A(0);
        QC_LD_B(bo0);
        QC_MMA_BLOCK(0, 1);
        QC_LD_B(bo1);
        QC_MMA_BLOCK(2, 3);
        QC_LD_A(16);
        QC_LD_B(bo0 + 16);
        QC_MMA_BLOCK(0, 1);
        QC_LD_B(bo1 + 16);
        __syncthreads();   // all smem reads complete; refill may proceed
        QC_MMA_BLOCK(2, 3);
    }

    #pragma unroll
    for (int f = 0; f < 4; f++) {
        const int n = n0 + warp_n * 32 + f * 8 + 2 * t;
        const int r0 = m0 + warp_m * 16 + g;
        const int r1 = r0 + 8;
        const float ba0 = ba[n], ba1 = ba[n + 1];
        const float bb0 = bb[n], bb1 = bb[n + 1];

        float2 oa0 = { accA1[f][0] + j2 * accA2[f][0] + ba0,
                       accA1[f][1] + j2 * accA2[f][1] + ba1 };
        float2 oa1 = { accA1[f][2] + j2 * accA2[f][2] + ba0,
                       accA1[f][3] + j2 * accA2[f][3] + ba1 };
        float2 ob0 = { accB[f][0] + bb0, accB[f][1] + bb1 };
        float2 ob1 = { accB[f][2] + bb0, accB[f][3] + bb1 };

        *(float2*)&outA[r0 * EG + n] = oa0;
        *(float2*)&outA[r1 * EG + n] = oa1;
        *(float2*)&outB[r0 * EG + n] = ob0;
        *(float2*)&outB[r1 * EG + n] = ob1;
    }
}

// ---------------------------------------------------------------------------
// RoPE applied in place to g_qa, g_qb, g_ka, g_kb (fp32 throughout).
// ---------------------------------------------------------------------------
__global__ __launch_bounds__(256) void rope_kernel()
{
    const int PAIRS = MG * (EG / 2);
    int tt = blockIdx.x * blockDim.x + threadIdx.x;
    if (tt >= 4 * PAIRS) return;

    const int w = tt / PAIRS;
    const int p = tt % PAIRS;
    float* X = (w == 0) ? g_qa : (w == 1) ? g_qb : (w == 2) ? g_ka : g_kb;

    const int row = p >> 9;
    const int pp  = p & 511;
    const int h   = pp >> 5;
    const int i   = pp & 31;
    const int s   = row & (SG - 1);

    const float freq = exp2f(-(float)i * (13.287712379549449f / 32.0f));
    float sn, cs;
    sincosf((float)s * freq, &sn, &cs);

    const int base = row * EG + h * DH + i;
    const float x1 = X[base];
    const float x2 = X[base + 32];
    X[base]      = x1 * cs - x2 * sn;
    X[base + 32] = x2 * cs + x1 * sn;
}

// ---------------------------------------------------------------------------
// prep_k: post-rope K -> bf16 hi/lo (ka, kb, kj = j2h(h)*kb), same layout.
// ---------------------------------------------------------------------------
__global__ __launch_bounds__(256) void prep_k_kernel(const float* __restrict__ thetas_head)
{
    const int t = blockIdx.x * 256 + threadIdx.x;
    const int row = t >> 8;
    const int c4  = (t & 255) << 2;
    const int h   = c4 >> 6;
    const float j2h = sinf(2.0f * thetas_head[h]) - 1.0f;

    const size_t off = (size_t)row * EG + c4;
    float4 ka = *(const float4*)&g_ka[off];
    float4 kb = *(const float4*)&g_kb[off];
    float4 kj = { j2h * kb.x, j2h * kb.y, j2h * kb.z, j2h * kb.w };

    *(uint2*)&g_kaH[off] = make_uint2(pack_hi2(ka.x, ka.y), pack_hi2(ka.z, ka.w));
    *(uint2*)&g_kaL[off] = make_uint2(pack_lo2(ka.x, ka.y), pack_lo2(ka.z, ka.w));
    *(uint2*)&g_kbH[off] = make_uint2(pack_hi2(kb.x, kb.y), pack_hi2(kb.z, kb.w));
    *(uint2*)&g_kbL[off] = make_uint2(pack_lo2(kb.x, kb.y), pack_lo2(kb.z, kb.w));
    *(uint2*)&g_kjH[off] = make_uint2(pack_hi2(kj.x, kj.y), pack_hi2(kj.z, kj.w));
    *(uint2*)&g_kjL[off] = make_uint2(pack_lo2(kj.x, kj.y), pack_lo2(kj.z, kj.w));
}

// ---------------------------------------------------------------------------
// prep_v: V -> bf16 hi/lo TRANSPOSED to [b,h,d,s] (s contiguous).
// ---------------------------------------------------------------------------
__global__ __launch_bounds__(256) void prep_v_kernel()
{
    const int t = blockIdx.x * 256 + threadIdx.x;
    const int bhd = t >> 8;
    const int s4  = (t & 255) << 2;
    const int b   = bhd >> 10;
    const int hd  = bhd & 1023;

    const size_t ib = ((size_t)b * SG + s4) * EG + hd;
    float a0 = g_va[ib], a1 = g_va[ib + EG], a2 = g_va[ib + 2 * EG], a3 = g_va[ib + 3 * EG];
    float b0 = g_vb[ib], b1 = g_vb[ib + EG], b2 = g_vb[ib + 2 * EG], b3 = g_vb[ib + 3 * EG];

    const size_t ob = (size_t)bhd * SG + s4;
    *(uint2*)&g_vaTH[ob] = make_uint2(pack_hi2(a0, a1), pack_hi2(a2, a3));
    *(uint2*)&g_vaTL[ob] = make_uint2(pack_lo2(a0, a1), pack_lo2(a2, a3));
    *(uint2*)&g_vbTH[ob] = make_uint2(pack_hi2(b0, b1), pack_hi2(b2, b3));
    *(uint2*)&g_vbTL[ob] = make_uint2(pack_lo2(b0, b1), pack_lo2(b2, b3));
}

// ---------------------------------------------------------------------------
// Split-K tensor-core flash attention. Grid (16, H, B):
//   x -> (j = 7 - x/2 [heavy first], half = x&1)
//   q-block j covers rows [128j, 128j+128); k-tiles [0, 4j+4) split evenly:
//   half0 = [0, 2j+2), half1 = [2j+2, 4j+4).
// Writes UNNORMALIZED partials (m, l, acc) to g_pm/g_pl/g_poa/g_pob.
// Masked scores use -INF (safe when a row's first tile is fully masked).
// ---------------------------------------------------------------------------
#define KSTR 72
#define VSTR 40

__global__ __launch_bounds__(256) void attn_mma_kernel()
{
    __shared__ __nv_bfloat16 sKaH[32 * KSTR], sKaL[32 * KSTR];
    __shared__ __nv_bfloat16 sKbH[32 * KSTR], sKbL[32 * KSTR];
    __shared__ __nv_bfloat16 sKjH[32 * KSTR], sKjL[32 * KSTR];
    __shared__ __nv_bfloat16 sVaH[64 * VSTR], sVaL[64 * VSTR];
    __shared__ __nv_bfloat16 sVbH[64 * VSTR], sVbL[64 * VSTR];

    const int b    = blockIdx.z;
    const int h    = blockIdx.y;
    const int jq   = 7 - ((int)blockIdx.x >> 1);   // heavy blocks first
    const int half = blockIdx.x & 1;
    const int r0   = jq * 128;
    const int tb   = half ? (2 * jq + 2) : 0;
    const int te   = half ? (4 * jq + 4) : (2 * jq + 2);

    const int tid = threadIdx.x;
    const int lane = tid & 31;
    const int wid  = tid >> 5;
    const int g = lane >> 2;
    const int t = lane & 3;

    const float NEGINF = -__int_as_float(0x7f800000);

    const int koff = ((lane & 7) + ((lane & 16) >> 1)) * KSTR + (((lane >> 3) & 1) << 3);
    const int voff = ((lane & 7) + ((lane & 16) >> 1)) * VSTR + (((lane >> 3) & 1) << 3);

    unsigned qaH[4][4], qaL[4][4], qbH[4][4], qbL[4][4];
    {
        const int row0 = r0 + wid * 16 + g;
        const int base0 = (b * SG + row0) * EG + h * DH;
        const int base1 = base0 + 8 * EG;
        #pragma unroll
        for (int ks = 0; ks < 4; ks++) {
            const int col = ks * 16 + 2 * t;
            float2 a0 = *(const float2*)&g_qa[base0 + col];
            float2 a1 = *(const float2*)&g_qa[base1 + col];
            float2 a2 = *(const float2*)&g_qa[base0 + col + 8];
            float2 a3 = *(const float2*)&g_qa[base1 + col + 8];
            qaH[ks][0] = pack_hi2(a0.x, a0.y); qaL[ks][0] = pack_lo2(a0.x, a0.y);
            qaH[ks][1] = pack_hi2(a1.x, a1.y); qaL[ks][1] = pack_lo2(a1.x, a1.y);
            qaH[ks][2] = pack_hi2(a2.x, a2.y); qaL[ks][2] = pack_lo2(a2.x, a2.y);
            qaH[ks][3] = pack_hi2(a3.x, a3.y); qaL[ks][3] = pack_lo2(a3.x, a3.y);
            float2 b0 = *(const float2*)&g_qb[base0 + col];
            float2 b1 = *(const float2*)&g_qb[base1 + col];
            float2 b2 = *(const float2*)&g_qb[base0 + col + 8];
            float2 b3 = *(const float2*)&g_qb[base1 + col + 8];
            qbH[ks][0] = pack_hi2(b0.x, b0.y); qbL[ks][0] = pack_lo2(b0.x, b0.y);
            qbH[ks][1] = pack_hi2(b1.x, b1.y); qbL[ks][1] = pack_lo2(b1.x, b1.y);
            qbH[ks][2] = pack_hi2(b2.x, b2.y); qbL[ks][2] = pack_lo2(b2.x, b2.y);
            qbH[ks][3] = pack_hi2(b3.x, b3.y); qbL[ks][3] = pack_lo2(b3.x, b3.y);
        }
    }

    float oa[8][4] = {};
    float ob[8][4] = {};
    float mrow0 = -1e30f, mrow1 = -1e30f;
    float lrow0 = 0.0f,   lrow1 = 0.0f;

    for (int tile = tb; tile < te; tile++) {
        const int k0 = tile * 32;

        __syncthreads();

        #pragma unroll
        for (int it = 0; it < 2; it++) {
            const int idx = tid + it * 256;
            const int n  = idx >> 4;
            const int d4 = (idx & 15) << 2;
            const size_t ga = (size_t)(b * SG + k0 + n) * EG + h * DH + d4;
            const int si = n * KSTR + d4;
            *(uint2*)&sKaH[si] = *(const uint2*)&g_kaH[ga];
            *(uint2*)&sKaL[si] = *(const uint2*)&g_kaL[ga];
            *(uint2*)&sKbH[si] = *(const uint2*)&g_kbH[ga];
            *(uint2*)&sKbL[si] = *(const uint2*)&g_kbL[ga];
            *(uint2*)&sKjH[si] = *(const uint2*)&g_kjH[ga];
            *(uint2*)&sKjL[si] = *(const uint2*)&g_kjL[ga];
        }
        #pragma unroll
        for (int it = 0; it < 2; it++) {
            const int idx = tid + it * 256;
            const int d  = idx >> 3;
            const int s4 = (idx & 7) << 2;
            const size_t ga = ((size_t)(b * HG + h) * DH + d) * SG + k0 + s4;
            const int si = d * VSTR + s4;
            *(uint2*)&sVaH[si] = *(const uint2*)&g_vaTH[ga];
            *(uint2*)&sVaL[si] = *(const uint2*)&g_vaTL[ga];
            *(uint2*)&sVbH[si] = *(const uint2*)&g_vbTH[ga];
            *(uint2*)&sVbL[si] = *(const uint2*)&g_vbTL[ga];
        }
        __syncthreads();

        const int wrow = r0 + wid * 16;
        if (k0 > wrow + 15) continue;

        float sa[4][4] = {};
        float sb[4][4] = {};
        #pragma unroll
        for (int ks = 0; ks < 4; ks++) {
            const int sk = ks * 16;
            #pragma unroll
            for (int pb = 0; pb < 2; pb++) {
                const int ko = pb * 16 * KSTR + koff + sk;
                unsigned kaH[4], kaL[4], kbH[4], kbL[4], kjH[4], kjL[4];
                ldsm_x4(kaH, sKaH + ko);
                ldsm_x4(kaL, sKaL + ko);
                ldsm_x4(kbH, sKbH + ko);
                ldsm_x4(kbL, sKbL + ko);
                ldsm_x4(kjH, sKjH + ko);
                ldsm_x4(kjL, sKjL + ko);

                #pragma unroll
                for (int hh = 0; hh < 2; hh++) {
                    const int nf = pb * 2 + hh;
                    const int o = hh * 2;
                    mma_bf16(sa[nf], qaH[ks], kaH + o);
                    mma_bf16(sb[nf], qaH[ks], kbH + o);
                    mma_bf16(sa[nf], qaH[ks], kaL + o);
                    mma_bf16(sb[nf], qaH[ks], kbL + o);
                    mma_bf16(sa[nf], qaL[ks], kaH + o);
                    mma_bf16(sb[nf], qaL[ks], kbH + o);
                    mma_bf16(sa[nf], qbH[ks], kjH + o);
                    mma_bf16(sb[nf], qbH[ks], kaH + o);
                    mma_bf16(sa[nf], qbH[ks], kjL + o);
                    mma_bf16(sb[nf], qbH[ks], kaL + o);
                    mma_bf16(sa[nf], qbL[ks], kjH + o);
                    mma_bf16(sb[nf], qbL[ks], kaH + o);
                }
            }
        }

        const bool full = (k0 + 31 <= wrow);
        float mt0 = NEGINF, mt1 = NEGINF;
        #pragma unroll
        for (int nf = 0; nf < 4; nf++) {
            #pragma unroll
            for (int c = 0; c < 4; c++) {
                float v = sqrtf(sa[nf][c] * sa[nf][c] + sb[nf][c] * sb[nf][c] + 1e-8f) * 0.125f;
                if (!full) {
                    const int col = k0 + nf * 8 + 2 * t + (c & 1);
                    const int row = wrow + g + ((c & 2) ? 8 : 0);
                    if (col > row) v = NEGINF;
                }
                sa[nf][c] = v;
                if (c & 2) mt1 = fmaxf(mt1, v); else mt0 = fmaxf(mt0, v);
            }
        }
        mt0 = fmaxf(mt0, __shfl_xor_sync(0xffffffffu, mt0, 1));
        mt0 = fmaxf(mt0, __shfl_xor_sync(0xffffffffu, mt0, 2));
        mt1 = fmaxf(mt1, __shfl_xor_sync(0xffffffffu, mt1, 1));
        mt1 = fmaxf(mt1, __shfl_xor_sync(0xffffffffu, mt1, 2));

        const float mn0 = fmaxf(mrow0, mt0);
        const float mn1 = fmaxf(mrow1, mt1);

        float ps0 = 0.0f, ps1 = 0.0f;
        #pragma unroll
        for (int nf = 0; nf < 4; nf++) {
            #pragma unroll
            for (int c = 0; c < 4; c++) {
                const float p = __expf(sa[nf][c] - ((c & 2) ? mn1 : mn0));
                sa[nf][c] = p;
                if (c & 2) ps1 += p; else ps0 += p;
            }
        }
        ps0 += __shfl_xor_sync(0xffffffffu, ps0, 1);
        ps0 += __shfl_xor_sync(0xffffffffu, ps0, 2);
        ps1 += __shfl_xor_sync(0xffffffffu, ps1, 1);
        ps1 += __shfl_xor_sync(0xffffffffu, ps1, 2);

        const float sc0 = __expf(mrow0 - mn0);
        const float sc1 = __expf(mrow1 - mn1);
        lrow0 = lrow0 * sc0 + ps0;  mrow0 = mn0;
        lrow1 = lrow1 * sc1 + ps1;  mrow1 = mn1;
        #pragma unroll
        for (int nf = 0; nf < 8; nf++) {
            oa[nf][0] *= sc0; oa[nf][1] *= sc0; oa[nf][2] *= sc1; oa[nf][3] *= sc1;
            ob[nf][0] *= sc0; ob[nf][1] *= sc0; ob[nf][2] *= sc1; ob[nf][3] *= sc1;
        }

        unsigned pH[2][4], pL[2][4];
        #pragma unroll
        for (int kc = 0; kc < 2; kc++) {
            const int f = 2 * kc;
            pH[kc][0] = pack_hi2(sa[f][0],     sa[f][1]);
            pL[kc][0] = pack_lo2(sa[f][0],     sa[f][1]);
            pH[kc][1] = pack_hi2(sa[f][2],     sa[f][3]);
            pL[kc][1] = pack_lo2(sa[f][2],     sa[f][3]);
            pH[kc][2] = pack_hi2(sa[f + 1][0], sa[f + 1][1]);
            pL[kc][2] = pack_lo2(sa[f + 1][0], sa[f + 1][1]);
            pH[kc][3] = pack_hi2(sa[f + 1][2], sa[f + 1][3]);
            pL[kc][3] = pack_lo2(sa[f + 1][2], sa[f + 1][3]);
        }

        #pragma unroll
        for (int pv = 0; pv < 4; pv++) {
            #pragma unroll
            for (int kc = 0; kc < 2; kc++) {
                const int vo = pv * 16 * VSTR + voff + kc * 16;
                unsigned vaH[4], vaL[4], vbH[4], vbL[4];
                ldsm_x4(vaH, sVaH + vo);
                ldsm_x4(vaL, sVaL + vo);
                ldsm_x4(vbH, sVbH + vo);
                ldsm_x4(vbL, sVbL + vo);

                #pragma unroll
                for (int hh = 0; hh < 2; hh++) {
                    const int nf = pv * 2 + hh;
                    const int o = hh * 2;
                    mma_bf16(oa[nf], pH[kc], vaH + o);
                    mma_bf16(ob[nf], pH[kc], vbH + o);
                    mma_bf16(oa[nf], pL[kc], vaH + o);
                    mma_bf16(ob[nf], pL[kc], vbH + o);
                    mma_bf16(oa[nf], pH[kc], vaL + o);
                    mma_bf16(ob[nf], pH[kc], vbL + o);
                }
            }
        }
    }

    // epilogue: write UNNORMALIZED partials + (m, l) to scratch
    const int mlb = ((half * 2 + b) * HG + h) * SG;
    const int row0 = r0 + wid * 16 + g;
    if (t == 0) {
        g_pm[mlb + row0]     = mrow0;  g_pl[mlb + row0]     = lrow0;
        g_pm[mlb + row0 + 8] = mrow1;  g_pl[mlb + row0 + 8] = lrow1;
    }
    float* pa0 = g_poa + (size_t)(mlb + row0) * DH;
    float* pa1 = g_poa + (size_t)(mlb + row0 + 8) * DH;
    float* pb0 = g_pob + (size_t)(mlb + row0) * DH;
    float* pb1 = g_pob + (size_t)(mlb + row0 + 8) * DH;
    #pragma unroll
    for (int nf = 0; nf < 8; nf++) {
        const int d = nf * 8 + 2 * t;
        *(float2*)&pa0[d] = make_float2(oa[nf][0], oa[nf][1]);
        *(float2*)&pa1[d] = make_float2(oa[nf][2], oa[nf][3]);
        *(float2*)&pb0[d] = make_float2(ob[nf][0], ob[nf][1]);
        *(float2*)&pb1[d] = make_float2(ob[nf][2], ob[nf][3]);
    }
}

// ---------------------------------------------------------------------------
// Combine the two k-halves (exact fp32 flash merge), write pre-split bf16.
// Grid (8, H, B), 256 threads: 2 threads per row, 32 dims each.
// ---------------------------------------------------------------------------
__global__ __launch_bounds__(256) void attn_combine_kernel()
{
    const int jq = blockIdx.x;
    const int h  = blockIdx.y;
    const int b  = blockIdx.z;
    const int tid = threadIdx.x;
    const int row = jq * 128 + (tid >> 1);
    const int d0  = (tid & 1) * 32;

    const int mb1 = ((0 * 2 + b) * HG + h) * SG + row;
    const int mb2 = ((1 * 2 + b) * HG + h) * SG + row;
    const float m1 = g_pm[mb1], l1 = g_pl[mb1];
    const float m2 = g_pm[mb2], l2 = g_pl[mb2];
    const float ms = fmaxf(m1, m2);
    const float w1 = __expf(m1 - ms);
    const float w2 = __expf(m2 - ms);
    const float linv = 1.0f / (l1 * w1 + l2 * w2);
    const float c1 = w1 * linv, c2 = w2 * linv;

    const float* pa1 = g_poa + (size_t)mb1 * DH + d0;
    const float* pa2 = g_poa + (size_t)mb2 * DH + d0;
    const float* pb1 = g_pob + (size_t)mb1 * DH + d0;
    const float* pb2 = g_pob + (size_t)mb2 * DH + d0;

    __nv_bfloat16* xh4 = g_xH[4];  __nv_bfloat16* xl4 = g_xL[4];
    __nv_bfloat16* xh5 = g_xH[5];  __nv_bfloat16* xl5 = g_xL[5];
    const size_t obase = (size_t)(b * SG + row) * EG + h * DH + d0;

    #pragma unroll
    for (int d = 0; d < 32; d += 4) {
        float4 a1 = *(const float4*)&pa1[d];
        float4 a2 = *(const float4*)&pa2[d];
        float ax = a1.x * c1 + a2.x * c2;
        float ay = a1.y * c1 + a2.y * c2;
        float az = a1.z * c1 + a2.z * c2;
        float aw = a1.w * c1 + a2.w * c2;
        *(uint2*)&xh4[obase + d] = make_uint2(pack_hi2(ax, ay), pack_hi2(az, aw));
        *(uint2*)&xl4[obase + d] = make_uint2(pack_lo2(ax, ay), pack_lo2(az, aw));

        float4 b1 = *(const float4*)&pb1[d];
        float4 b2 = *(const float4*)&pb2[d];
        float bx = b1.x * c1 + b2.x * c2;
        float by = b1.y * c1 + b2.y * c2;
        float bz = b1.z * c1 + b2.z * c2;
        float bw = b1.w * c1 + b2.w * c2;
        *(uint2*)&xh5[obase + d] = make_uint2(pack_hi2(bx, by), pack_hi2(bz, bw));
        *(uint2*)&xl5[obase + d] = make_uint2(pack_lo2(bx, by), pack_lo2(bz, bw));
    }
}

// ---------------------------------------------------------------------------
extern "C" void kernel_launch(void* const* d_in, const int* in_sizes, int n_in,
                              void* d_out, int out_size)
{
    const float* x_q_a  = (const float*)d_in[0];
    const float* x_q_b  = (const float*)d_in[1];
    const float* x_kv_a = (const float*)d_in[2];
    const float* x_kv_b = (const float*)d_in[3];
    // d_in[4] = mask -- causal, encoded in the attention kernel
    const float* layer_theta = (const float*)d_in[5];
    const float* thetas_head = (const float*)d_in[6];
    const float* q_wa = (const float*)d_in[7];
    const float* q_wb = (const float*)d_in[8];
    const float* q_ba = (const float*)d_in[9];
    const float* q_bb = (const float*)d_in[10];
    const float* k_wa = (const float*)d_in[11];
    const float* k_wb = (const float*)d_in[12];
    const float* k_ba = (const float*)d_in[13];
    const float* k_bb = (const float*)d_in[14];
    const float* v_wa = (const float*)d_in[15];
    const float* v_wb = (const float*)d_in[16];
    const float* v_ba = (const float*)d_in[17];
    const float* v_bb = (const float*)d_in[18];
    const float* o_wa = (const float*)d_in[19];
    const float* o_wb = (const float*)d_in[20];
    const float* o_ba = (const float*)d_in[21];
    const float* o_bb = (const float*)d_in[22];

    float *qa, *qb, *ka, *kb, *va, *vb;
    cudaGetSymbolAddress((void**)&qa, g_qa);
    cudaGetSymbolAddress((void**)&qb, g_qb);
    cudaGetSymbolAddress((void**)&ka, g_ka);
    cudaGetSymbolAddress((void**)&kb, g_kb);
    cudaGetSymbolAddress((void**)&va, g_va);
    cudaGetSymbolAddress((void**)&vb, g_vb);

    __nv_bfloat16 *wH, *wL, *xH, *xL;
    cudaGetSymbolAddress((void**)&wH, g_wH);
    cudaGetSymbolAddress((void**)&wL, g_wL);
    cudaGetSymbolAddress((void**)&xH, g_xH);
    cudaGetSymbolAddress((void**)&xL, g_xL);
    const size_t WSZ = (size_t)EG * EG;
    const size_t XSZ = (size_t)MG * EG;
    auto whi = [&](int i) { return wH + i * WSZ; };
    auto wlo = [&](int i) { return wL + i * WSZ; };
    auto xhi = [&](int i) { return xH + i * XSZ; };
    auto xlo = [&](int i) { return xL + i * XSZ; };

    float* outA = (float*)d_out;
    float* outB = (float*)d_out + (size_t)MG * EG;

    const int GSMEM = 2 * 8 * TILE_HF * (int)sizeof(__nv_bfloat16);  // 81920
    cudaFuncSetAttribute(qc_gemm_bf16_kernel,
                         cudaFuncAttributeMaxDynamicSharedMemorySize, GSMEM);

    // ---- streams/events for graph-capturable fork/join (created once) ----
    static cudaStream_t s1 = nullptr, s2 = nullptr;
    static cudaEvent_t ev0 = nullptr, ev_w = nullptr, ev_x = nullptr,
                       ev_k = nullptr, ev_pv = nullptr;
    if (s1 == nullptr) {
        cudaStreamCreateWithFlags(&s1, cudaStreamNonBlocking);
        cudaStreamCreateWithFlags(&s2, cudaStreamNonBlocking);
        cudaEventCreateWithFlags(&ev0,  cudaEventDisableTiming);
        cudaEventCreateWithFlags(&ev_w, cudaEventDisableTiming);
        cudaEventCreateWithFlags(&ev_x, cudaEventDisableTiming);
        cudaEventCreateWithFlags(&ev_k, cudaEventDisableTiming);
        cudaEventCreateWithFlags(&ev_pv, cudaEventDisableTiming);
    }

    // fork
    cudaEventRecord(ev0, 0);
    cudaStreamWaitEvent(s1, ev0, 0);
    cudaStreamWaitEvent(s2, ev0, 0);

    // ---- split weights (s0) || split activations (s1) ----
    {
        SplitBatch sb = {};
        const float* srcs[8] = { q_wa, q_wb, k_wa, k_wb, v_wa, v_wb, o_wa, o_wb };
        for (int i = 0; i < 8; i++) { sb.src[i] = srcs[i]; sb.hi[i] = whi(i); sb.lo[i] = wlo(i); }
        split_kernel<<<dim3((unsigned)(WSZ / 4 / 256), 8), 256, 0, 0>>>(sb, (int)(WSZ / 4));
    }
    cudaEventRecord(ev_w, 0);
    {
        SplitBatch sb = {};
        const float* srcs[4] = { x_q_a, x_q_b, x_kv_a, x_kv_b };
        for (int i = 0; i < 4; i++) { sb.src[i] = srcs[i]; sb.hi[i] = xhi(i); sb.lo[i] = xlo(i); }
        split_kernel<<<dim3((unsigned)(XSZ / 4 / 256), 4), 256, 0, s1>>>(sb, (int)(XSZ / 4));
    }
    cudaEventRecord(ev_x, s1);

    const dim3 gg(EG / 64, MG / 64);

    // q on s0 (needs weights [s0-ordered] + acts [ev_x])
    cudaStreamWaitEvent(0, ev_x, 0);
    qc_gemm_bf16_kernel<<<gg, 256, GSMEM, 0>>>(
        xhi(0), xlo(0), xhi(1), xlo(1), whi(0), wlo(0), whi(1), wlo(1),
        q_ba, q_bb, layer_theta, qa, qb);
    // k on s1 (needs acts [s1-ordered] + weights [ev_w])
    cudaStreamWaitEvent(s1, ev_w, 0);
    qc_gemm_bf16_kernel<<<gg, 256, GSMEM, s1>>>(
        xhi(2), xlo(2), xhi(3), xlo(3), whi(2), wlo(2), whi(3), wlo(3),
        k_ba, k_bb, layer_theta, ka, kb);
    cudaEventRecord(ev_k, s1);
    // v on s2 (needs both)
    cudaStreamWaitEvent(s2, ev_w, 0);
    cudaStreamWaitEvent(s2, ev_x, 0);
    qc_gemm_bf16_kernel<<<gg, 256, GSMEM, s2>>>(
        xhi(2), xlo(2), xhi(3), xlo(3), whi(4), wlo(4), whi(5), wlo(5),
        v_ba, v_bb, layer_theta, va, vb);
    prep_v_kernel<<<(MG * EG / 4) / 256, 256, 0, s2>>>();
    cudaEventRecord(ev_pv, s2);

    // rope (q [s0-ordered] + k [ev_k]) then prep_k, on s0 -- overlaps v/prep_v
    cudaStreamWaitEvent(0, ev_k, 0);
    rope_kernel<<<(4 * MG * (EG / 2)) / 256, 256, 0, 0>>>();
    prep_k_kernel<<<(MG * EG / 4) / 256, 256, 0, 0>>>(thetas_head);

    // attention joins s2 via ev_pv; split-K (512 balanced CTAs) + combine
    cudaStreamWaitEvent(0, ev_pv, 0);
    attn_mma_kernel<<<dim3(16, HG, 2), 256, 0, 0>>>();
    attn_combine_kernel<<<dim3(SG / 128, HG, 2), 256, 0, 0>>>();

    // output projection straight into d_out (out_a then out_b)
    qc_gemm_bf16_kernel<<<gg, 256, GSMEM, 0>>>(
        xhi(4), xlo(4), xhi(5), xlo(5), whi(6), wlo(6), whi(7), wlo(7),
        o_ba, o_bb, layer_theta, outA, outB);
}

// round 17
// speedup vs baseline: 1.4676x; 1.0296x over previous
#include <cuda_runtime.h>
#include <cuda_bf16.h>
#include <math.h>

// Problem constants
#define EG 1024      // embed dim
#define MG 2048      // B*S rows
#define SG 1024      // seq len
#define HG 16        // heads
#define DH 64        // head dim

// ---------------- scratch (device globals: no runtime allocation allowed) ----
__device__ float g_qa[MG * EG];
__device__ float g_qb[MG * EG];
__device__ float g_ka[MG * EG];
__device__ float g_kb[MG * EG];
__device__ float g_va[MG * EG];
__device__ float g_vb[MG * EG];

// pre-split bf16 hi/lo buffers
// weights: 0 q_wa, 1 q_wb, 2 k_wa, 3 k_wb, 4 v_wa, 5 v_wb, 6 o_wa, 7 o_wb
__device__ __nv_bfloat16 g_wH[8][EG * EG];
__device__ __nv_bfloat16 g_wL[8][EG * EG];
// activations: 0 x_q_a, 1 x_q_b, 2 x_kv_a, 3 x_kv_b, 4 oa, 5 ob
__device__ __nv_bfloat16 g_xH[6][MG * EG];
__device__ __nv_bfloat16 g_xL[6][MG * EG];

// attention pre-split buffers (post-rope K, j2h folded; V transposed [b,h,d,s])
__device__ __nv_bfloat16 g_kaH[MG * EG], g_kaL[MG * EG];
__device__ __nv_bfloat16 g_kbH[MG * EG], g_kbL[MG * EG];
__device__ __nv_bfloat16 g_kjH[MG * EG], g_kjL[MG * EG];
__device__ __nv_bfloat16 g_vaTH[MG * EG], g_vaTL[MG * EG];
__device__ __nv_bfloat16 g_vbTH[MG * EG], g_vbTL[MG * EG];

// split-K attention partials: [half][b][h][row] (+ [d] for acc)
__device__ float g_pm[2 * 2 * HG * SG];
__device__ float g_pl[2 * 2 * HG * SG];
__device__ float g_poa[(size_t)2 * 2 * HG * SG * DH];
__device__ float g_pob[(size_t)2 * 2 * HG * SG * DH];

// ---------------------------------------------------------------------------
// helpers
// ---------------------------------------------------------------------------
__device__ __forceinline__ void mma_bf16(float* c, const unsigned* a, const unsigned* b)
{
    asm volatile(
        "mma.sync.aligned.m16n8k16.row.col.f32.bf16.bf16.f32 "
        "{%0,%1,%2,%3}, {%4,%5,%6,%7}, {%8,%9}, {%0,%1,%2,%3};"
        : "+f"(c[0]), "+f"(c[1]), "+f"(c[2]), "+f"(c[3])
        : "r"(a[0]), "r"(a[1]), "r"(a[2]), "r"(a[3]),
          "r"(b[0]), "r"(b[1]));
}

__device__ __forceinline__ void ldsm_x4(unsigned* r, const __nv_bfloat16* p)
{
    unsigned addr = (unsigned)__cvta_generic_to_shared(p);
    asm volatile("ldmatrix.sync.aligned.m8n8.x4.shared.b16 {%0,%1,%2,%3}, [%4];"
                 : "=r"(r[0]), "=r"(r[1]), "=r"(r[2]), "=r"(r[3]) : "r"(addr));
}

__device__ __forceinline__ unsigned pack_hi2(float x, float y)
{
    __nv_bfloat162 h(__float2bfloat16(x), __float2bfloat16(y));
    return *reinterpret_cast<unsigned*>(&h);
}
__device__ __forceinline__ unsigned pack_lo2(float x, float y)
{
    float hx = __bfloat162float(__float2bfloat16(x));
    float hy = __bfloat162float(__float2bfloat16(y));
    __nv_bfloat162 l(__float2bfloat16(x - hx), __float2bfloat16(y - hy));
    return *reinterpret_cast<unsigned*>(&l);
}

__device__ __forceinline__ void cp_async16(unsigned daddr, const void* src)
{
    asm volatile("cp.async.cg.shared.global [%0], [%1], 16;" :: "r"(daddr), "l"(src));
}
__device__ __forceinline__ void cp_commit()
{
    asm volatile("cp.async.commit_group;");
}
template<int N>
__device__ __forceinline__ void cp_wait()
{
    asm volatile("cp.async.wait_group %0;" :: "n"(N));
}

// smem tile strides (bf16 halfword units). BK=32 + pad 8 -> conflict-free frags.
#define TSTR 40
#define TILE_HF (64 * TSTR)

// ---------------------------------------------------------------------------
// Batched fp32 -> bf16 hi/lo split. blockIdx.y selects the tensor.
// ---------------------------------------------------------------------------
struct SplitBatch {
    const float* src[8];
    __nv_bfloat16* hi[8];
    __nv_bfloat16* lo[8];
};

__global__ __launch_bounds__(256) void split_kernel(SplitBatch sb, int nvec)
{
    const int t = blockIdx.x * 256 + threadIdx.x;
    if (t >= nvec) return;
    const int w = blockIdx.y;
    const float4 v = reinterpret_cast<const float4*>(sb.src[w])[t];

    unsigned h0 = pack_hi2(v.x, v.y);
    unsigned h1 = pack_hi2(v.z, v.w);
    unsigned l0 = pack_lo2(v.x, v.y);
    unsigned l1 = pack_lo2(v.z, v.w);

    reinterpret_cast<uint2*>(sb.hi[w])[t] = make_uint2(h0, h1);
    reinterpret_cast<uint2*>(sb.lo[w])[t] = make_uint2(l0, l1);
}

// ---------------------------------------------------------------------------
// Fused quaternion-complex dense on tensor cores.
//   outA = Xa.Wa^T + j2 * Xb.Wb^T + ba ;  outB = Xa.Wb^T + Xb.Wa^T + bb
// 64x64 CTA tile, BK=32, cp.async double-buffered, ldmatrix frags,
// __launch_bounds__(256,2). SINGLE barrier per k-iteration:
//   cp_wait<0>; __syncthreads(); issue refill(other stage); compute(cur).
// The one barrier proves prev-iteration reads are done (safe to refill) and
// makes the drained cp.async data visible. MMA lines interleaved A1,B,A2,B,...
// so every accumulator has >=4-instruction RAW spacing.
// ---------------------------------------------------------------------------
__global__ __launch_bounds__(256, 2) void qc_gemm_bf16_kernel(
    const __nv_bfloat16* __restrict__ xaH, const __nv_bfloat16* __restrict__ xaL,
    const __nv_bfloat16* __restrict__ xbH, const __nv_bfloat16* __restrict__ xbL,
    const __nv_bfloat16* __restrict__ waH, const __nv_bfloat16* __restrict__ waL,
    const __nv_bfloat16* __restrict__ wbH, const __nv_bfloat16* __restrict__ wbL,
    const float* __restrict__ ba, const float* __restrict__ bb,
    const float* __restrict__ theta_ptr,
    float* __restrict__ outA, float* __restrict__ outB)
{
    extern __shared__ __nv_bfloat16 sbuf[];

    const int tid = threadIdx.x;
    const int lane = tid & 31;
    const int wid = tid >> 5;
    const int warp_m = wid >> 1;
    const int warp_n = wid & 1;
    const int g = lane >> 2;
    const int t = lane & 3;

    const int m0 = blockIdx.y * 64;
    const int n0 = blockIdx.x * 64;

    const float j2 = sinf(2.0f * theta_ptr[0]) - 1.0f;

    const int aoff = (warp_m * 16 + (lane & 15)) * TSTR + ((lane >> 4) << 3);
    const int boff = ((lane & 7) + ((lane & 16) >> 1)) * TSTR + (((lane >> 3) & 1) << 3);

    const int losel = tid >> 7;           // 0 hi, 1 lo
    const int tt    = tid & 127;
    const int lr0   = tt >> 2;            // rows 0..31 (chunk j=0)
    const int lc0   = (tt & 3) << 3;      // cols 0,8,16,24 (elements)

    const __nv_bfloat16* sxa = (losel ? xaL : xaH) + (size_t)(m0 + lr0) * EG + lc0;
    const __nv_bfloat16* sxb = (losel ? xbL : xbH) + (size_t)(m0 + lr0) * EG + lc0;
    const __nv_bfloat16* swa = (losel ? waL : waH) + (size_t)(n0 + lr0) * EG + lc0;
    const __nv_bfloat16* swb = (losel ? wbL : wbH) + (size_t)(n0 + lr0) * EG + lc0;
    const size_t GROW = (size_t)32 * EG;

    const int doff0 = lr0 * TSTR + lc0;
    const int doff1 = doff0 + 32 * TSTR;
    unsigned dxa[2][2], dxb[2][2], dwa[2][2], dwb[2][2];
    #pragma unroll
    for (int st = 0; st < 2; st++) {
        __nv_bfloat16* base = sbuf + st * 8 * TILE_HF;
        __nv_bfloat16* bxa = base + (0 + losel) * TILE_HF;
        __nv_bfloat16* bxb = base + (2 + losel) * TILE_HF;
        __nv_bfloat16* bwa = base + (4 + losel) * TILE_HF;
        __nv_bfloat16* bwb = base + (6 + losel) * TILE_HF;
        dxa[st][0] = (unsigned)__cvta_generic_to_shared(bxa + doff0);
        dxa[st][1] = (unsigned)__cvta_generic_to_shared(bxa + doff1);
        dxb[st][0] = (unsigned)__cvta_generic_to_shared(bxb + doff0);
        dxb[st][1] = (unsigned)__cvta_generic_to_shared(bxb + doff1);
        dwa[st][0] = (unsigned)__cvta_generic_to_shared(bwa + doff0);
        dwa[st][1] = (unsigned)__cvta_generic_to_shared(bwa + doff1);
        dwb[st][0] = (unsigned)__cvta_generic_to_shared(bwb + doff0);
        dwb[st][1] = (unsigned)__cvta_generic_to_shared(bwb + doff1);
    }

    float accA1[4][4] = {};
    float accA2[4][4] = {};
    float accB [4][4] = {};

    // prologue: stage 0, k0 = 0
    cp_async16(dxa[0][0], sxa);          cp_async16(dxa[0][1], sxa + GROW);
    cp_async16(dxb[0][0], sxb);          cp_async16(dxb[0][1], sxb + GROW);
    cp_async16(dwa[0][0], swa);          cp_async16(dwa[0][1], swa + GROW);
    cp_async16(dwb[0][0], swb);          cp_async16(dwb[0][1], swb + GROW);
    cp_commit();

// interleaved A1,B,A2,B,... : every accumulator >=4-instruction RAW spacing
#define QC_MMA_BLOCK(f0, f1) \
    mma_bf16(accA1[f0], aXaH, bWaH + 0);  mma_bf16(accA1[f1], aXaH, bWaH + 2); \
    mma_bf16(accB [f0], aXaH, bWbH + 0);  mma_bf16(accB [f1], aXaH, bWbH + 2); \
    mma_bf16(accA2[f0], aXbH, bWbH + 0);  mma_bf16(accA2[f1], aXbH, bWbH + 2); \
    mma_bf16(accB [f0], aXaH, bWbL + 0);  mma_bf16(accB [f1], aXaH, bWbL + 2); \
    mma_bf16(accA1[f0], aXaH, bWaL + 0);  mma_bf16(accA1[f1], aXaH, bWaL + 2); \
    mma_bf16(accB [f0], aXaL, bWbH + 0);  mma_bf16(accB [f1], aXaL, bWbH + 2); \
    mma_bf16(accA2[f0], aXbH, bWbL + 0);  mma_bf16(accA2[f1], aXbH, bWbL + 2); \
    mma_bf16(accB [f0], aXbH, bWaH + 0);  mma_bf16(accB [f1], aXbH, bWaH + 2); \
    mma_bf16(accA1[f0], aXaL, bWaH + 0);  mma_bf16(accA1[f1], aXaL, bWaH + 2); \
    mma_bf16(accB [f0], aXbH, bWaL + 0);  mma_bf16(accB [f1], aXbH, bWaL + 2); \
    mma_bf16(accA2[f0], aXbL, bWbH + 0);  mma_bf16(accA2[f1], aXbL, bWbH + 2); \
    mma_bf16(accB [f0], aXbL, bWaH + 0);  mma_bf16(accB [f1], aXbL, bWaH + 2)

#define QC_LD_A(sk) \
    ldsm_x4(aXaH, sXaH + aoff + (sk)); ldsm_x4(aXaL, sXaL + aoff + (sk)); \
    ldsm_x4(aXbH, sXbH + aoff + (sk)); ldsm_x4(aXbL, sXbL + aoff + (sk))

#define QC_LD_B(bo) \
    ldsm_x4(bWaH, sWaH + (bo)); ldsm_x4(bWaL, sWaL + (bo)); \
    ldsm_x4(bWbH, sWbH + (bo)); ldsm_x4(bWbL, sWbL + (bo))

    const int NIT = EG / 32;
    for (int it = 0; it < NIT; it++) {
        const int cur = it & 1;

        cp_wait<0>();        // drain the single pending refill (stage cur)
        __syncthreads();     // prev-iter reads done + refilled data visible

        if (it + 1 < NIT) {  // refill the other stage (its readers are done)
            const int nk = (it + 1) * 32;
            const int ns = 1 - cur;
            cp_async16(dxa[ns][0], sxa + nk);   cp_async16(dxa[ns][1], sxa + nk + GROW);
            cp_async16(dxb[ns][0], sxb + nk);   cp_async16(dxb[ns][1], sxb + nk + GROW);
            cp_async16(dwa[ns][0], swa + nk);   cp_async16(dwa[ns][1], swa + nk + GROW);
            cp_async16(dwb[ns][0], swb + nk);   cp_async16(dwb[ns][1], swb + nk + GROW);
            cp_commit();
        }

        const __nv_bfloat16* cb = sbuf + cur * 8 * TILE_HF;
        const __nv_bfloat16* sXaH = cb + 0 * TILE_HF;
        const __nv_bfloat16* sXaL = cb + 1 * TILE_HF;
        const __nv_bfloat16* sXbH = cb + 2 * TILE_HF;
        const __nv_bfloat16* sXbL = cb + 3 * TILE_HF;
        const __nv_bfloat16* sWaH = cb + 4 * TILE_HF;
        const __nv_bfloat16* sWaL = cb + 5 * TILE_HF;
        const __nv_bfloat16* sWbH = cb + 6 * TILE_HF;
        const __nv_bfloat16* sWbL = cb + 7 * TILE_HF;

        unsigned aXaH[4], aXaL[4], aXbH[4], aXbL[4];
        unsigned bWaH[4], bWaL[4], bWbH[4], bWbL[4];
        const int bo0 = (warp_n * 32) * TSTR + boff;
        const int bo1 = (warp_n * 32 + 16) * TSTR + boff;

        QC_LD_A(0);
        QC_LD_B(bo0);
        QC_MMA_BLOCK(0, 1);
        QC_LD_B(bo1);
        QC_MMA_BLOCK(2, 3);
        QC_LD_A(16);
        QC_LD_B(bo0 + 16);
        QC_MMA_BLOCK(0, 1);
        QC_LD_B(bo1 + 16);
        QC_MMA_BLOCK(2, 3);
    }

    #pragma unroll
    for (int f = 0; f < 4; f++) {
        const int n = n0 + warp_n * 32 + f * 8 + 2 * t;
        const int r0 = m0 + warp_m * 16 + g;
        const int r1 = r0 + 8;
        const float ba0 = ba[n], ba1 = ba[n + 1];
        const float bb0 = bb[n], bb1 = bb[n + 1];

        float2 oa0 = { accA1[f][0] + j2 * accA2[f][0] + ba0,
                       accA1[f][1] + j2 * accA2[f][1] + ba1 };
        float2 oa1 = { accA1[f][2] + j2 * accA2[f][2] + ba0,
                       accA1[f][3] + j2 * accA2[f][3] + ba1 };
        float2 ob0 = { accB[f][0] + bb0, accB[f][1] + bb1 };
        float2 ob1 = { accB[f][2] + bb0, accB[f][3] + bb1 };

        *(float2*)&outA[r0 * EG + n] = oa0;
        *(float2*)&outA[r1 * EG + n] = oa1;
        *(float2*)&outB[r0 * EG + n] = ob0;
        *(float2*)&outB[r1 * EG + n] = ob1;
    }
}

// ---------------------------------------------------------------------------
// RoPE applied in place to g_qa, g_qb, g_ka, g_kb (fp32 throughout).
// ---------------------------------------------------------------------------
__global__ __launch_bounds__(256) void rope_kernel()
{
    const int PAIRS = MG * (EG / 2);
    int tt = blockIdx.x * blockDim.x + threadIdx.x;
    if (tt >= 4 * PAIRS) return;

    const int w = tt / PAIRS;
    const int p = tt % PAIRS;
    float* X = (w == 0) ? g_qa : (w == 1) ? g_qb : (w == 2) ? g_ka : g_kb;

    const int row = p >> 9;
    const int pp  = p & 511;
    const int h   = pp >> 5;
    const int i   = pp & 31;
    const int s   = row & (SG - 1);

    const float freq = exp2f(-(float)i * (13.287712379549449f / 32.0f));
    float sn, cs;
    sincosf((float)s * freq, &sn, &cs);

    const int base = row * EG + h * DH + i;
    const float x1 = X[base];
    const float x2 = X[base + 32];
    X[base]      = x1 * cs - x2 * sn;
    X[base + 32] = x2 * cs + x1 * sn;
}

// ---------------------------------------------------------------------------
// prep_k: post-rope K -> bf16 hi/lo (ka, kb, kj = j2h(h)*kb), same layout.
// ---------------------------------------------------------------------------
__global__ __launch_bounds__(256) void prep_k_kernel(const float* __restrict__ thetas_head)
{
    const int t = blockIdx.x * 256 + threadIdx.x;
    const int row = t >> 8;
    const int c4  = (t & 255) << 2;
    const int h   = c4 >> 6;
    const float j2h = sinf(2.0f * thetas_head[h]) - 1.0f;

    const size_t off = (size_t)row * EG + c4;
    float4 ka = *(const float4*)&g_ka[off];
    float4 kb = *(const float4*)&g_kb[off];
    float4 kj = { j2h * kb.x, j2h * kb.y, j2h * kb.z, j2h * kb.w };

    *(uint2*)&g_kaH[off] = make_uint2(pack_hi2(ka.x, ka.y), pack_hi2(ka.z, ka.w));
    *(uint2*)&g_kaL[off] = make_uint2(pack_lo2(ka.x, ka.y), pack_lo2(ka.z, ka.w));
    *(uint2*)&g_kbH[off] = make_uint2(pack_hi2(kb.x, kb.y), pack_hi2(kb.z, kb.w));
    *(uint2*)&g_kbL[off] = make_uint2(pack_lo2(kb.x, kb.y), pack_lo2(kb.z, kb.w));
    *(uint2*)&g_kjH[off] = make_uint2(pack_hi2(kj.x, kj.y), pack_hi2(kj.z, kj.w));
    *(uint2*)&g_kjL[off] = make_uint2(pack_lo2(kj.x, kj.y), pack_lo2(kj.z, kj.w));
}

// ---------------------------------------------------------------------------
// prep_v: V -> bf16 hi/lo TRANSPOSED to [b,h,d,s] (s contiguous).
// ---------------------------------------------------------------------------
__global__ __launch_bounds__(256) void prep_v_kernel()
{
    const int t = blockIdx.x * 256 + threadIdx.x;
    const int bhd = t >> 8;
    const int s4  = (t & 255) << 2;
    const int b   = bhd >> 10;
    const int hd  = bhd & 1023;

    const size_t ib = ((size_t)b * SG + s4) * EG + hd;
    float a0 = g_va[ib], a1 = g_va[ib + EG], a2 = g_va[ib + 2 * EG], a3 = g_va[ib + 3 * EG];
    float b0 = g_vb[ib], b1 = g_vb[ib + EG], b2 = g_vb[ib + 2 * EG], b3 = g_vb[ib + 3 * EG];

    const size_t ob = (size_t)bhd * SG + s4;
    *(uint2*)&g_vaTH[ob] = make_uint2(pack_hi2(a0, a1), pack_hi2(a2, a3));
    *(uint2*)&g_vaTL[ob] = make_uint2(pack_lo2(a0, a1), pack_lo2(a2, a3));
    *(uint2*)&g_vbTH[ob] = make_uint2(pack_hi2(b0, b1), pack_hi2(b2, b3));
    *(uint2*)&g_vbTL[ob] = make_uint2(pack_lo2(b0, b1), pack_lo2(b2, b3));
}

// ---------------------------------------------------------------------------
// Split-K tensor-core flash attention (R16-validated). Grid (16, H, B).
// ---------------------------------------------------------------------------
#define KSTR 72
#define VSTR 40

__global__ __launch_bounds__(256) void attn_mma_kernel()
{
    __shared__ __nv_bfloat16 sKaH[32 * KSTR], sKaL[32 * KSTR];
    __shared__ __nv_bfloat16 sKbH[32 * KSTR], sKbL[32 * KSTR];
    __shared__ __nv_bfloat16 sKjH[32 * KSTR], sKjL[32 * KSTR];
    __shared__ __nv_bfloat16 sVaH[64 * VSTR], sVaL[64 * VSTR];
    __shared__ __nv_bfloat16 sVbH[64 * VSTR], sVbL[64 * VSTR];

    const int b    = blockIdx.z;
    const int h    = blockIdx.y;
    const int jq   = 7 - ((int)blockIdx.x >> 1);   // heavy blocks first
    const int half = blockIdx.x & 1;
    const int r0   = jq * 128;
    const int tb   = half ? (2 * jq + 2) : 0;
    const int te   = half ? (4 * jq + 4) : (2 * jq + 2);

    const int tid = threadIdx.x;
    const int lane = tid & 31;
    const int wid  = tid >> 5;
    const int g = lane >> 2;
    const int t = lane & 3;

    const float NEGINF = -__int_as_float(0x7f800000);

    const int koff = ((lane & 7) + ((lane & 16) >> 1)) * KSTR + (((lane >> 3) & 1) << 3);
    const int voff = ((lane & 7) + ((lane & 16) >> 1)) * VSTR + (((lane >> 3) & 1) << 3);

    unsigned qaH[4][4], qaL[4][4], qbH[4][4], qbL[4][4];
    {
        const int row0 = r0 + wid * 16 + g;
        const int base0 = (b * SG + row0) * EG + h * DH;
        const int base1 = base0 + 8 * EG;
        #pragma unroll
        for (int ks = 0; ks < 4; ks++) {
            const int col = ks * 16 + 2 * t;
            float2 a0 = *(const float2*)&g_qa[base0 + col];
            float2 a1 = *(const float2*)&g_qa[base1 + col];
            float2 a2 = *(const float2*)&g_qa[base0 + col + 8];
            float2 a3 = *(const float2*)&g_qa[base1 + col + 8];
            qaH[ks][0] = pack_hi2(a0.x, a0.y); qaL[ks][0] = pack_lo2(a0.x, a0.y);
            qaH[ks][1] = pack_hi2(a1.x, a1.y); qaL[ks][1] = pack_lo2(a1.x, a1.y);
            qaH[ks][2] = pack_hi2(a2.x, a2.y); qaL[ks][2] = pack_lo2(a2.x, a2.y);
            qaH[ks][3] = pack_hi2(a3.x, a3.y); qaL[ks][3] = pack_lo2(a3.x, a3.y);
            float2 b0 = *(const float2*)&g_qb[base0 + col];
            float2 b1 = *(const float2*)&g_qb[base1 + col];
            float2 b2 = *(const float2*)&g_qb[base0 + col + 8];
            float2 b3 = *(const float2*)&g_qb[base1 + col + 8];
            qbH[ks][0] = pack_hi2(b0.x, b0.y); qbL[ks][0] = pack_lo2(b0.x, b0.y);
            qbH[ks][1] = pack_hi2(b1.x, b1.y); qbL[ks][1] = pack_lo2(b1.x, b1.y);
            qbH[ks][2] = pack_hi2(b2.x, b2.y); qbL[ks][2] = pack_lo2(b2.x, b2.y);
            qbH[ks][3] = pack_hi2(b3.x, b3.y); qbL[ks][3] = pack_lo2(b3.x, b3.y);
        }
    }

    float oa[8][4] = {};
    float ob[8][4] = {};
    float mrow0 = -1e30f, mrow1 = -1e30f;
    float lrow0 = 0.0f,   lrow1 = 0.0f;

    for (int tile = tb; tile < te; tile++) {
        const int k0 = tile * 32;

        __syncthreads();

        #pragma unroll
        for (int it = 0; it < 2; it++) {
            const int idx = tid + it * 256;
            const int n  = idx >> 4;
            const int d4 = (idx & 15) << 2;
            const size_t ga = (size_t)(b * SG + k0 + n) * EG + h * DH + d4;
            const int si = n * KSTR + d4;
            *(uint2*)&sKaH[si] = *(const uint2*)&g_kaH[ga];
            *(uint2*)&sKaL[si] = *(const uint2*)&g_kaL[ga];
            *(uint2*)&sKbH[si] = *(const uint2*)&g_kbH[ga];
            *(uint2*)&sKbL[si] = *(const uint2*)&g_kbL[ga];
            *(uint2*)&sKjH[si] = *(const uint2*)&g_kjH[ga];
            *(uint2*)&sKjL[si] = *(const uint2*)&g_kjL[ga];
        }
        #pragma unroll
        for (int it = 0; it < 2; it++) {
            const int idx = tid + it * 256;
            const int d  = idx >> 3;
            const int s4 = (idx & 7) << 2;
            const size_t ga = ((size_t)(b * HG + h) * DH + d) * SG + k0 + s4;
            const int si = d * VSTR + s4;
            *(uint2*)&sVaH[si] = *(const uint2*)&g_vaTH[ga];
            *(uint2*)&sVaL[si] = *(const uint2*)&g_vaTL[ga];
            *(uint2*)&sVbH[si] = *(const uint2*)&g_vbTH[ga];
            *(uint2*)&sVbL[si] = *(const uint2*)&g_vbTL[ga];
        }
        __syncthreads();

        const int wrow = r0 + wid * 16;
        if (k0 > wrow + 15) continue;

        float sa[4][4] = {};
        float sb[4][4] = {};
        #pragma unroll
        for (int ks = 0; ks < 4; ks++) {
            const int sk = ks * 16;
            #pragma unroll
            for (int pb = 0; pb < 2; pb++) {
                const int ko = pb * 16 * KSTR + koff + sk;
                unsigned kaH[4], kaL[4], kbH[4], kbL[4], kjH[4], kjL[4];
                ldsm_x4(kaH, sKaH + ko);
                ldsm_x4(kaL, sKaL + ko);
                ldsm_x4(kbH, sKbH + ko);
                ldsm_x4(kbL, sKbL + ko);
                ldsm_x4(kjH, sKjH + ko);
                ldsm_x4(kjL, sKjL + ko);

                #pragma unroll
                for (int hh = 0; hh < 2; hh++) {
                    const int nf = pb * 2 + hh;
                    const int o = hh * 2;
                    mma_bf16(sa[nf], qaH[ks], kaH + o);
                    mma_bf16(sb[nf], qaH[ks], kbH + o);
                    mma_bf16(sa[nf], qaH[ks], kaL + o);
                    mma_bf16(sb[nf], qaH[ks], kbL + o);
                    mma_bf16(sa[nf], qaL[ks], kaH + o);
                    mma_bf16(sb[nf], qaL[ks], kbH + o);
                    mma_bf16(sa[nf], qbH[ks], kjH + o);
                    mma_bf16(sb[nf], qbH[ks], kaH + o);
                    mma_bf16(sa[nf], qbH[ks], kjL + o);
                    mma_bf16(sb[nf], qbH[ks], kaL + o);
                    mma_bf16(sa[nf], qbL[ks], kjH + o);
                    mma_bf16(sb[nf], qbL[ks], kaH + o);
                }
            }
        }

        const bool full = (k0 + 31 <= wrow);
        float mt0 = NEGINF, mt1 = NEGINF;
        #pragma unroll
        for (int nf = 0; nf < 4; nf++) {
            #pragma unroll
            for (int c = 0; c < 4; c++) {
                float v = sqrtf(sa[nf][c] * sa[nf][c] + sb[nf][c] * sb[nf][c] + 1e-8f) * 0.125f;
                if (!full) {
                    const int col = k0 + nf * 8 + 2 * t + (c & 1);
                    const int row = wrow + g + ((c & 2) ? 8 : 0);
                    if (col > row) v = NEGINF;
                }
                sa[nf][c] = v;
                if (c & 2) mt1 = fmaxf(mt1, v); else mt0 = fmaxf(mt0, v);
            }
        }
        mt0 = fmaxf(mt0, __shfl_xor_sync(0xffffffffu, mt0, 1));
        mt0 = fmaxf(mt0, __shfl_xor_sync(0xffffffffu, mt0, 2));
        mt1 = fmaxf(mt1, __shfl_xor_sync(0xffffffffu, mt1, 1));
        mt1 = fmaxf(mt1, __shfl_xor_sync(0xffffffffu, mt1, 2));

        const float mn0 = fmaxf(mrow0, mt0);
        const float mn1 = fmaxf(mrow1, mt1);

        float ps0 = 0.0f, ps1 = 0.0f;
        #pragma unroll
        for (int nf = 0; nf < 4; nf++) {
            #pragma unroll
            for (int c = 0; c < 4; c++) {
                const float p = __expf(sa[nf][c] - ((c & 2) ? mn1 : mn0));
                sa[nf][c] = p;
                if (c & 2) ps1 += p; else ps0 += p;
            }
        }
        ps0 += __shfl_xor_sync(0xffffffffu, ps0, 1);
        ps0 += __shfl_xor_sync(0xffffffffu, ps0, 2);
        ps1 += __shfl_xor_sync(0xffffffffu, ps1, 1);
        ps1 += __shfl_xor_sync(0xffffffffu, ps1, 2);

        const float sc0 = __expf(mrow0 - mn0);
        const float sc1 = __expf(mrow1 - mn1);
        lrow0 = lrow0 * sc0 + ps0;  mrow0 = mn0;
        lrow1 = lrow1 * sc1 + ps1;  mrow1 = mn1;
        #pragma unroll
        for (int nf = 0; nf < 8; nf++) {
            oa[nf][0] *= sc0; oa[nf][1] *= sc0; oa[nf][2] *= sc1; oa[nf][3] *= sc1;
            ob[nf][0] *= sc0; ob[nf][1] *= sc0; ob[nf][2] *= sc1; ob[nf][3] *= sc1;
        }

        unsigned pH[2][4], pL[2][4];
        #pragma unroll
        for (int kc = 0; kc < 2; kc++) {
            const int f = 2 * kc;
            pH[kc][0] = pack_hi2(sa[f][0],     sa[f][1]);
            pL[kc][0] = pack_lo2(sa[f][0],     sa[f][1]);
            pH[kc][1] = pack_hi2(sa[f][2],     sa[f][3]);
            pL[kc][1] = pack_lo2(sa[f][2],     sa[f][3]);
            pH[kc][2] = pack_hi2(sa[f + 1][0], sa[f + 1][1]);
            pL[kc][2] = pack_lo2(sa[f + 1][0], sa[f + 1][1]);
            pH[kc][3] = pack_hi2(sa[f + 1][2], sa[f + 1][3]);
            pL[kc][3] = pack_lo2(sa[f + 1][2], sa[f + 1][3]);
        }

        #pragma unroll
        for (int pv = 0; pv < 4; pv++) {
            #pragma unroll
            for (int kc = 0; kc < 2; kc++) {
                const int vo = pv * 16 * VSTR + voff + kc * 16;
                unsigned vaH[4], vaL[4], vbH[4], vbL[4];
                ldsm_x4(vaH, sVaH + vo);
                ldsm_x4(vaL, sVaL + vo);
                ldsm_x4(vbH, sVbH + vo);
                ldsm_x4(vbL, sVbL + vo);

                #pragma unroll
                for (int hh = 0; hh < 2; hh++) {
                    const int nf = pv * 2 + hh;
                    const int o = hh * 2;
                    mma_bf16(oa[nf], pH[kc], vaH + o);
                    mma_bf16(ob[nf], pH[kc], vbH + o);
                    mma_bf16(oa[nf], pL[kc], vaH + o);
                    mma_bf16(ob[nf], pL[kc], vbH + o);
                    mma_bf16(oa[nf], pH[kc], vaL + o);
                    mma_bf16(ob[nf], pH[kc], vbL + o);
                }
            }
        }
    }

    // epilogue: write UNNORMALIZED partials + (m, l) to scratch
    const int mlb = ((half * 2 + b) * HG + h) * SG;
    const int row0 = r0 + wid * 16 + g;
    if (t == 0) {
        g_pm[mlb + row0]     = mrow0;  g_pl[mlb + row0]     = lrow0;
        g_pm[mlb + row0 + 8] = mrow1;  g_pl[mlb + row0 + 8] = lrow1;
    }
    float* pa0 = g_poa + (size_t)(mlb + row0) * DH;
    float* pa1 = g_poa + (size_t)(mlb + row0 + 8) * DH;
    float* pb0 = g_pob + (size_t)(mlb + row0) * DH;
    float* pb1 = g_pob + (size_t)(mlb + row0 + 8) * DH;
    #pragma unroll
    for (int nf = 0; nf < 8; nf++) {
        const int d = nf * 8 + 2 * t;
        *(float2*)&pa0[d] = make_float2(oa[nf][0], oa[nf][1]);
        *(float2*)&pa1[d] = make_float2(oa[nf][2], oa[nf][3]);
        *(float2*)&pb0[d] = make_float2(ob[nf][0], ob[nf][1]);
        *(float2*)&pb1[d] = make_float2(ob[nf][2], ob[nf][3]);
    }
}

// ---------------------------------------------------------------------------
// Combine the two k-halves (exact fp32 flash merge), write pre-split bf16.
// ---------------------------------------------------------------------------
__global__ __launch_bounds__(256) void attn_combine_kernel()
{
    const int jq = blockIdx.x;
    const int h  = blockIdx.y;
    const int b  = blockIdx.z;
    const int tid = threadIdx.x;
    const int row = jq * 128 + (tid >> 1);
    const int d0  = (tid & 1) * 32;

    const int mb1 = ((0 * 2 + b) * HG + h) * SG + row;
    const int mb2 = ((1 * 2 + b) * HG + h) * SG + row;
    const float m1 = g_pm[mb1], l1 = g_pl[mb1];
    const float m2 = g_pm[mb2], l2 = g_pl[mb2];
    const float ms = fmaxf(m1, m2);
    const float w1 = __expf(m1 - ms);
    const float w2 = __expf(m2 - ms);
    const float linv = 1.0f / (l1 * w1 + l2 * w2);
    const float c1 = w1 * linv, c2 = w2 * linv;

    const float* pa1 = g_poa + (size_t)mb1 * DH + d0;
    const float* pa2 = g_poa + (size_t)mb2 * DH + d0;
    const float* pb1 = g_pob + (size_t)mb1 * DH + d0;
    const float* pb2 = g_pob + (size_t)mb2 * DH + d0;

    __nv_bfloat16* xh4 = g_xH[4];  __nv_bfloat16* xl4 = g_xL[4];
    __nv_bfloat16* xh5 = g_xH[5];  __nv_bfloat16* xl5 = g_xL[5];
    const size_t obase = (size_t)(b * SG + row) * EG + h * DH + d0;

    #pragma unroll
    for (int d = 0; d < 32; d += 4) {
        float4 a1 = *(const float4*)&pa1[d];
        float4 a2 = *(const float4*)&pa2[d];
        float ax = a1.x * c1 + a2.x * c2;
        float ay = a1.y * c1 + a2.y * c2;
        float az = a1.z * c1 + a2.z * c2;
        float aw = a1.w * c1 + a2.w * c2;
        *(uint2*)&xh4[obase + d] = make_uint2(pack_hi2(ax, ay), pack_hi2(az, aw));
        *(uint2*)&xl4[obase + d] = make_uint2(pack_lo2(ax, ay), pack_lo2(az, aw));

        float4 b1 = *(const float4*)&pb1[d];
        float4 b2 = *(const float4*)&pb2[d];
        float bx = b1.x * c1 + b2.x * c2;
        float by = b1.y * c1 + b2.y * c2;
        float bz = b1.z * c1 + b2.z * c2;
        float bw = b1.w * c1 + b2.w * c2;
        *(uint2*)&xh5[obase + d] = make_uint2(pack_hi2(bx, by), pack_hi2(bz, bw));
        *(uint2*)&xl5[obase + d] = make_uint2(pack_lo2(bx, by), pack_lo2(bz, bw));
    }
}

// ---------------------------------------------------------------------------
extern "C" void kernel_launch(void* const* d_in, const int* in_sizes, int n_in,
                              void* d_out, int out_size)
{
    const float* x_q_a  = (const float*)d_in[0];
    const float* x_q_b  = (const float*)d_in[1];
    const float* x_kv_a = (const float*)d_in[2];
    const float* x_kv_b = (const float*)d_in[3];
    // d_in[4] = mask -- causal, encoded in the attention kernel
    const float* layer_theta = (const float*)d_in[5];
    const float* thetas_head = (const float*)d_in[6];
    const float* q_wa = (const float*)d_in[7];
    const float* q_wb = (const float*)d_in[8];
    const float* q_ba = (const float*)d_in[9];
    const float* q_bb = (const float*)d_in[10];
    const float* k_wa = (const float*)d_in[11];
    const float* k_wb = (const float*)d_in[12];
    const float* k_ba = (const float*)d_in[13];
    const float* k_bb = (const float*)d_in[14];
    const float* v_wa = (const float*)d_in[15];
    const float* v_wb = (const float*)d_in[16];
    const float* v_ba = (const float*)d_in[17];
    const float* v_bb = (const float*)d_in[18];
    const float* o_wa = (const float*)d_in[19];
    const float* o_wb = (const float*)d_in[20];
    const float* o_ba = (const float*)d_in[21];
    const float* o_bb = (const float*)d_in[22];

    float *qa, *qb, *ka, *kb, *va, *vb;
    cudaGetSymbolAddress((void**)&qa, g_qa);
    cudaGetSymbolAddress((void**)&qb, g_qb);
    cudaGetSymbolAddress((void**)&ka, g_ka);
    cudaGetSymbolAddress((void**)&kb, g_kb);
    cudaGetSymbolAddress((void**)&va, g_va);
    cudaGetSymbolAddress((void**)&vb, g_vb);

    __nv_bfloat16 *wH, *wL, *xH, *xL;
    cudaGetSymbolAddress((void**)&wH, g_wH);
    cudaGetSymbolAddress((void**)&wL, g_wL);
    cudaGetSymbolAddress((void**)&xH, g_xH);
    cudaGetSymbolAddress((void**)&xL, g_xL);
    const size_t WSZ = (size_t)EG * EG;
    const size_t XSZ = (size_t)MG * EG;
    auto whi = [&](int i) { return wH + i * WSZ; };
    auto wlo = [&](int i) { return wL + i * WSZ; };
    auto xhi = [&](int i) { return xH + i * XSZ; };
    auto xlo = [&](int i) { return xL + i * XSZ; };

    float* outA = (float*)d_out;
    float* outB = (float*)d_out + (size_t)MG * EG;

    const int GSMEM = 2 * 8 * TILE_HF * (int)sizeof(__nv_bfloat16);  // 81920
    cudaFuncSetAttribute(qc_gemm_bf16_kernel,
                         cudaFuncAttributeMaxDynamicSharedMemorySize, GSMEM);

    // ---- streams/events for graph-capturable fork/join (created once) ----
    static cudaStream_t s1 = nullptr, s2 = nullptr;
    static cudaEvent_t ev0 = nullptr, ev_w = nullptr, ev_x = nullptr,
                       ev_k = nullptr, ev_pv = nullptr;
    if (s1 == nullptr) {
        cudaStreamCreateWithFlags(&s1, cudaStreamNonBlocking);
        cudaStreamCreateWithFlags(&s2, cudaStreamNonBlocking);
        cudaEventCreateWithFlags(&ev0,  cudaEventDisableTiming);
        cudaEventCreateWithFlags(&ev_w, cudaEventDisableTiming);
        cudaEventCreateWithFlags(&ev_x, cudaEventDisableTiming);
        cudaEventCreateWithFlags(&ev_k, cudaEventDisableTiming);
        cudaEventCreateWithFlags(&ev_pv, cudaEventDisableTiming);
    }

    // fork
    cudaEventRecord(ev0, 0);
    cudaStreamWaitEvent(s1, ev0, 0);
    cudaStreamWaitEvent(s2, ev0, 0);

    // ---- split weights (s0) || split activations (s1) ----
    {
        SplitBatch sb = {};
        const float* srcs[8] = { q_wa, q_wb, k_wa, k_wb, v_wa, v_wb, o_wa, o_wb };
        for (int i = 0; i < 8; i++) { sb.src[i] = srcs[i]; sb.hi[i] = whi(i); sb.lo[i] = wlo(i); }
        split_kernel<<<dim3((unsigned)(WSZ / 4 / 256), 8), 256, 0, 0>>>(sb, (int)(WSZ / 4));
    }
    cudaEventRecord(ev_w, 0);
    {
        SplitBatch sb = {};
        const float* srcs[4] = { x_q_a, x_q_b, x_kv_a, x_kv_b };
        for (int i = 0; i < 4; i++) { sb.src[i] = srcs[i]; sb.hi[i] = xhi(i); sb.lo[i] = xlo(i); }
        split_kernel<<<dim3((unsigned)(XSZ / 4 / 256), 4), 256, 0, s1>>>(sb, (int)(XSZ / 4));
    }
    cudaEventRecord(ev_x, s1);

    const dim3 gg(EG / 64, MG / 64);

    // q on s0 (needs weights [s0-ordered] + acts [ev_x])
    cudaStreamWaitEvent(0, ev_x, 0);
    qc_gemm_bf16_kernel<<<gg, 256, GSMEM, 0>>>(
        xhi(0), xlo(0), xhi(1), xlo(1), whi(0), wlo(0), whi(1), wlo(1),
        q_ba, q_bb, layer_theta, qa, qb);
    // k on s1 (needs acts [s1-ordered] + weights [ev_w])
    cudaStreamWaitEvent(s1, ev_w, 0);
    qc_gemm_bf16_kernel<<<gg, 256, GSMEM, s1>>>(
        xhi(2), xlo(2), xhi(3), xlo(3), whi(2), wlo(2), whi(3), wlo(3),
        k_ba, k_bb, layer_theta, ka, kb);
    cudaEventRecord(ev_k, s1);
    // v on s2 (needs both)
    cudaStreamWaitEvent(s2, ev_w, 0);
    cudaStreamWaitEvent(s2, ev_x, 0);
    qc_gemm_bf16_kernel<<<gg, 256, GSMEM, s2>>>(
        xhi(2), xlo(2), xhi(3), xlo(3), whi(4), wlo(4), whi(5), wlo(5),
        v_ba, v_bb, layer_theta, va, vb);
    prep_v_kernel<<<(MG * EG / 4) / 256, 256, 0, s2>>>();
    cudaEventRecord(ev_pv, s2);

    // rope (q [s0-ordered] + k [ev_k]) then prep_k, on s0 -- overlaps v/prep_v
    cudaStreamWaitEvent(0, ev_k, 0);
    rope_kernel<<<(4 * MG * (EG / 2)) / 256, 256, 0, 0>>>();
    prep_k_kernel<<<(MG * EG / 4) / 256, 256, 0, 0>>>(thetas_head);

    // attention joins s2 via ev_pv; split-K (512 balanced CTAs) + combine
    cudaStreamWaitEvent(0, ev_pv, 0);
    attn_mma_kernel<<<dim3(16, HG, 2), 256, 0, 0>>>();
    attn_combine_kernel<<<dim3(SG / 128, HG, 2), 256, 0, 0>>>();

    // output projection straight into d_out (out_a then out_b)
    qc_gemm_bf16_kernel<<<gg, 256, GSMEM, 0>>>(
        xhi(4), xlo(4), xhi(5), xlo(5), whi(6), wlo(6), whi(7), wlo(7),
        o_ba, o_bb, layer_theta, outA, outB);
}